// round 2
// baseline (speedup 1.0000x reference)
#include <cuda_runtime.h>
#include <cuda_bf16.h>
#include <math.h>

// Problem constants
#define BB 4
#define TT 2048
#define EE 1024
#define HH 16
#define DD 64
#define MM (BB*TT)        // 8192
#define FF (4*EE)         // 4096

// ---------------- scratch (device globals; no allocation allowed) -------------
__device__ float g_x [MM*EE];   // x after embed (residual 1 input)
__device__ float g_h [MM*EE];   // LN output (reused for ln1 and ln2)
__device__ float g_q [MM*EE];   // q, layout [B,T,H,D] == [M,E]
__device__ float g_k [MM*EE];
__device__ float g_v [MM*EE];
__device__ float g_o [MM*EE];   // attention output, concat heads [B,T,E]
__device__ float g_x2[MM*EE];   // x + attn_proj (residual 2 input)
__device__ float g_m [MM*FF];   // gelu(fc) activations

// ---------------- embed: x = wte[ids] + wpe ----------------------------------
__global__ __launch_bounds__(256) void embed_kernel(
    const int* __restrict__ ids, const float* __restrict__ wte,
    const float* __restrict__ wpe, float* __restrict__ X)
{
    int i = blockIdx.x * 256 + threadIdx.x;    // float4 index over M*E/4
    int row = i >> 8;                           // 256 float4 per row
    int c   = i & 255;
    int t   = row & (TT - 1);
    int id  = ids[row];
    float4 a = ((const float4*)wte)[(size_t)id * 256 + c];
    float4 p = ((const float4*)wpe)[(size_t)t  * 256 + c];
    a.x += p.x; a.y += p.y; a.z += p.z; a.w += p.w;
    ((float4*)X)[i] = a;
}

// ---------------- layernorm (one block per row, E=1024) -----------------------
__global__ __launch_bounds__(256) void ln_kernel(
    const float* __restrict__ X, const float* __restrict__ G,
    const float* __restrict__ Bt, float* __restrict__ Y)
{
    __shared__ float red[16];
    int row = blockIdx.x, tid = threadIdx.x;
    const float4* x4 = (const float4*)(X + ((size_t)row << 10));
    float4 a = x4[tid];
    float s  = a.x + a.y + a.z + a.w;
    float sq = a.x*a.x + a.y*a.y + a.z*a.z + a.w*a.w;
    #pragma unroll
    for (int o = 16; o; o >>= 1) {
        s  += __shfl_xor_sync(0xffffffffu, s,  o);
        sq += __shfl_xor_sync(0xffffffffu, sq, o);
    }
    if ((tid & 31) == 0) { red[tid >> 5] = s; red[8 + (tid >> 5)] = sq; }
    __syncthreads();
    float ts = 0.f, tq = 0.f;
    #pragma unroll
    for (int i = 0; i < 8; i++) { ts += red[i]; tq += red[8 + i]; }
    float mean = ts * (1.f / 1024.f);
    float var  = tq * (1.f / 1024.f) - mean * mean;
    float inv  = rsqrtf(var + 1e-5f);
    float4 g4 = ((const float4*)G)[tid];
    float4 b4 = ((const float4*)Bt)[tid];
    float4 o;
    o.x = (a.x - mean) * inv * g4.x + b4.x;
    o.y = (a.y - mean) * inv * g4.y + b4.y;
    o.z = (a.z - mean) * inv * g4.z + b4.z;
    o.w = (a.w - mean) * inv * g4.w + b4.w;
    ((float4*)(Y + ((size_t)row << 10)))[tid] = o;
}

// ---------------- tiled SGEMM: C = act(A@W + bias [+ R]) ----------------------
// WL=0: W row-major [K,N].  WL=1: W is (H,E,D): idx = (n/64)*K*64 + k*64 + n%64
template<int WL, bool GELU_, bool RES>
__global__ __launch_bounds__(256) void gemm_kernel(
    const float* __restrict__ A, const float* __restrict__ W,
    const float* __restrict__ bias, const float* __restrict__ Rp,
    float* __restrict__ C, int M, int N, int K)
{
    __shared__ float As[16][128];
    __shared__ float Ws[16][128];
    int tid = threadIdx.x;
    int bn = blockIdx.x * 128, bm = blockIdx.y * 128;
    int tx = tid & 15, ty = tid >> 4;
    float acc[8][8];
    #pragma unroll
    for (int i = 0; i < 8; i++)
        #pragma unroll
        for (int j = 0; j < 8; j++) acc[i][j] = 0.f;

    int arow = tid >> 2;          // 0..63 (two passes: +64)
    int akc  = (tid & 3) << 2;    // k offset 0,4,8,12
    int wcol = (tid & 31) << 2;   // 0..124
    int wrow = tid >> 5;          // 0..7 (two passes: +8)

    for (int k0 = 0; k0 < K; k0 += 16) {
        #pragma unroll
        for (int p = 0; p < 2; p++) {
            int mm = arow + p * 64;
            float4 va = *(const float4*)(A + (size_t)(bm + mm) * K + k0 + akc);
            As[akc + 0][mm] = va.x; As[akc + 1][mm] = va.y;
            As[akc + 2][mm] = va.z; As[akc + 3][mm] = va.w;
        }
        #pragma unroll
        for (int p = 0; p < 2; p++) {
            int kk = wrow + p * 8;
            int n  = bn + wcol;
            const float* wp;
            if (WL == 0) wp = W + (size_t)(k0 + kk) * N + n;
            else         wp = W + ((size_t)(n >> 6)) * (size_t)K * 64
                                + (size_t)(k0 + kk) * 64 + (n & 63);
            *(float4*)&Ws[kk][wcol] = *(const float4*)wp;
        }
        __syncthreads();
        #pragma unroll
        for (int kk = 0; kk < 16; kk++) {
            float4 a0 = *(const float4*)&As[kk][ty << 2];
            float4 a1 = *(const float4*)&As[kk][64 + (ty << 2)];
            float4 b0 = *(const float4*)&Ws[kk][tx << 2];
            float4 b1 = *(const float4*)&Ws[kk][64 + (tx << 2)];
            float av[8] = {a0.x,a0.y,a0.z,a0.w,a1.x,a1.y,a1.z,a1.w};
            float bv[8] = {b0.x,b0.y,b0.z,b0.w,b1.x,b1.y,b1.z,b1.w};
            #pragma unroll
            for (int i = 0; i < 8; i++)
                #pragma unroll
                for (int j = 0; j < 8; j++)
                    acc[i][j] += av[i] * bv[j];
        }
        __syncthreads();
    }
    // epilogue
    #pragma unroll
    for (int i = 0; i < 8; i++) {
        int m = bm + ((i < 4) ? ((ty << 2) + i) : (64 + (ty << 2) + i - 4));
        #pragma unroll
        for (int half = 0; half < 2; half++) {
            int n = bn + half * 64 + (tx << 2);
            float v[4];
            #pragma unroll
            for (int j = 0; j < 4; j++) {
                float x = acc[i][half * 4 + j] + bias[n + j];
                if (GELU_) x = 0.5f * x * (1.f + erff(x * 0.70710678118654752f));
                v[j] = x;
            }
            if (RES) {
                float4 rr = *(const float4*)(Rp + (size_t)m * N + n);
                v[0] += rr.x; v[1] += rr.y; v[2] += rr.z; v[3] += rr.w;
            }
            float4 o; o.x = v[0]; o.y = v[1]; o.z = v[2]; o.w = v[3];
            *(float4*)(C + (size_t)m * N + n) = o;
        }
    }
}

// ---------------- flash attention (causal) ------------------------------------
// grid: (T/64, H, B); block 256.  Each thread: rows r and r+32, d-slice sub*8..+7
#define AST 68   // smem row stride (floats), keeps float4 alignment
__global__ __launch_bounds__(256) void attn_kernel(
    const float* __restrict__ Q, const float* __restrict__ K,
    const float* __restrict__ V, float* __restrict__ O)
{
    extern __shared__ float sm[];
    float* Qs = sm;
    float* Ks = sm + 64 * AST;
    float* Vs = sm + 2 * 64 * AST;
    float* Ps = sm + 3 * 64 * AST;

    int qt = blockIdx.x, h = blockIdx.y, b = blockIdx.z;
    int tid = threadIdx.x;
    int sub = tid & 7;       // d-slice index
    int r   = tid >> 3;      // 0..31 -> rows r and r+32

    const size_t base = ((size_t)(b * TT) << 10) + ((size_t)h << 6);

    // load Q tile [64][64]
    {
        int lr = tid >> 2, lc = (tid & 3) * 16;
        const float4* src = (const float4*)(Q + base + ((size_t)(qt * 64 + lr) << 10) + lc);
        float4* dst = (float4*)(Qs + lr * AST + lc);
        dst[0] = src[0]; dst[1] = src[1]; dst[2] = src[2]; dst[3] = src[3];
    }
    __syncthreads();

    float q0[8], q1[8];
    const float sc_qk = 0.125f;   // 1/sqrt(64)
    #pragma unroll
    for (int i = 0; i < 8; i++) {
        q0[i] = Qs[r * AST + sub * 8 + i] * sc_qk;
        q1[i] = Qs[(r + 32) * AST + sub * 8 + i] * sc_qk;
    }
    float m0 = -INFINITY, m1 = -INFINITY, l0 = 0.f, l1 = 0.f;
    float acc0[8], acc1[8];
    #pragma unroll
    for (int i = 0; i < 8; i++) { acc0[i] = 0.f; acc1[i] = 0.f; }
    int iq0 = qt * 64 + r, iq1 = iq0 + 32;

    for (int kt = 0; kt <= qt; kt++) {
        __syncthreads();   // prior-iteration consumers done before overwrite
        {
            int lr = tid >> 2, lc = (tid & 3) * 16;
            const float4* sk = (const float4*)(K + base + ((size_t)(kt * 64 + lr) << 10) + lc);
            const float4* sv = (const float4*)(V + base + ((size_t)(kt * 64 + lr) << 10) + lc);
            float4* dk = (float4*)(Ks + lr * AST + lc);
            float4* dv = (float4*)(Vs + lr * AST + lc);
            dk[0]=sk[0]; dk[1]=sk[1]; dk[2]=sk[2]; dk[3]=sk[3];
            dv[0]=sv[0]; dv[1]=sv[1]; dv[2]=sv[2]; dv[3]=sv[3];
        }
        __syncthreads();

        float mx0 = -INFINITY, mx1 = -INFINITY;
        bool diag = (kt == qt);
        #pragma unroll 4
        for (int j = 0; j < 64; j++) {
            const float4* kr = (const float4*)(Ks + j * AST + sub * 8);
            float4 ka = kr[0], kb = kr[1];
            float kk[8] = {ka.x,ka.y,ka.z,ka.w,kb.x,kb.y,kb.z,kb.w};
            float s0 = 0.f, s1 = 0.f;
            #pragma unroll
            for (int i = 0; i < 8; i++) { s0 += q0[i]*kk[i]; s1 += q1[i]*kk[i]; }
            #pragma unroll
            for (int o = 1; o < 8; o <<= 1) {
                s0 += __shfl_xor_sync(0xffffffffu, s0, o);
                s1 += __shfl_xor_sync(0xffffffffu, s1, o);
            }
            if (diag) {
                int jg = kt * 64 + j;
                if (jg > iq0) s0 = -INFINITY;
                if (jg > iq1) s1 = -INFINITY;
            }
            mx0 = fmaxf(mx0, s0); mx1 = fmaxf(mx1, s1);
            if (sub == (j & 7)) { Ps[r * AST + j] = s0; Ps[(r + 32) * AST + j] = s1; }
        }
        float nm0 = fmaxf(m0, mx0), nm1 = fmaxf(m1, mx1);
        float scl0 = expf(m0 - nm0), scl1 = expf(m1 - nm1);
        float ls0 = 0.f, ls1 = 0.f;
        #pragma unroll
        for (int jj = 0; jj < 8; jj++) {
            int j = jj * 8 + sub;
            float e0 = expf(Ps[r * AST + j] - nm0);
            float e1 = expf(Ps[(r + 32) * AST + j] - nm1);
            Ps[r * AST + j] = e0; Ps[(r + 32) * AST + j] = e1;
            ls0 += e0; ls1 += e1;
        }
        #pragma unroll
        for (int o = 1; o < 8; o <<= 1) {
            ls0 += __shfl_xor_sync(0xffffffffu, ls0, o);
            ls1 += __shfl_xor_sync(0xffffffffu, ls1, o);
        }
        l0 = l0 * scl0 + ls0; l1 = l1 * scl1 + ls1;
        #pragma unroll
        for (int i = 0; i < 8; i++) { acc0[i] *= scl0; acc1[i] *= scl1; }
        __syncwarp();
        #pragma unroll 4
        for (int j = 0; j < 64; j++) {
            float p0 = Ps[r * AST + j], p1 = Ps[(r + 32) * AST + j];
            const float4* vr = (const float4*)(Vs + j * AST + sub * 8);
            float4 va = vr[0], vb = vr[1];
            float vv[8] = {va.x,va.y,va.z,va.w,vb.x,vb.y,vb.z,vb.w};
            #pragma unroll
            for (int i = 0; i < 8; i++) { acc0[i] += p0*vv[i]; acc1[i] += p1*vv[i]; }
        }
        m0 = nm0; m1 = nm1;
    }

    float inv0 = 1.f / l0, inv1 = 1.f / l1;
    float* o0 = O + base + ((size_t)(qt * 64 + r) << 10) + sub * 8;
    float* o1 = O + base + ((size_t)(qt * 64 + r + 32) << 10) + sub * 8;
    float4 w0, w1;
    w0.x = acc0[0]*inv0; w0.y = acc0[1]*inv0; w0.z = acc0[2]*inv0; w0.w = acc0[3]*inv0;
    w1.x = acc0[4]*inv0; w1.y = acc0[5]*inv0; w1.z = acc0[6]*inv0; w1.w = acc0[7]*inv0;
    ((float4*)o0)[0] = w0; ((float4*)o0)[1] = w1;
    w0.x = acc1[0]*inv1; w0.y = acc1[1]*inv1; w0.z = acc1[2]*inv1; w0.w = acc1[3]*inv1;
    w1.x = acc1[4]*inv1; w1.y = acc1[5]*inv1; w1.z = acc1[6]*inv1; w1.w = acc1[7]*inv1;
    ((float4*)o1)[0] = w0; ((float4*)o1)[1] = w1;
}

// ---------------- launch ------------------------------------------------------
extern "C" void kernel_launch(void* const* d_in, const int* in_sizes, int n_in,
                              void* d_out, int out_size)
{
    const int*   ids   = (const int*)  d_in[0];
    const float* wte   = (const float*)d_in[1];
    const float* wpe   = (const float*)d_in[2];
    const float* wq    = (const float*)d_in[3];
    const float* wk    = (const float*)d_in[4];
    const float* wv    = (const float*)d_in[5];
    const float* bq    = (const float*)d_in[6];
    const float* bk    = (const float*)d_in[7];
    const float* bv    = (const float*)d_in[8];
    const float* wproj = (const float*)d_in[9];
    const float* bproj = (const float*)d_in[10];
    const float* ln1g  = (const float*)d_in[11];
    const float* ln1b  = (const float*)d_in[12];
    const float* ln2g  = (const float*)d_in[13];
    const float* ln2b  = (const float*)d_in[14];
    const float* wfc   = (const float*)d_in[15];
    const float* bfc   = (const float*)d_in[16];
    const float* wout  = (const float*)d_in[17];
    const float* bout  = (const float*)d_in[18];
    float* out = (float*)d_out;

    float *x, *h, *q, *k, *v, *o, *x2, *mb;
    cudaGetSymbolAddress((void**)&x,  g_x);
    cudaGetSymbolAddress((void**)&h,  g_h);
    cudaGetSymbolAddress((void**)&q,  g_q);
    cudaGetSymbolAddress((void**)&k,  g_k);
    cudaGetSymbolAddress((void**)&v,  g_v);
    cudaGetSymbolAddress((void**)&o,  g_o);
    cudaGetSymbolAddress((void**)&x2, g_x2);
    cudaGetSymbolAddress((void**)&mb, g_m);

    const int attn_smem = 4 * 64 * AST * 4;
    cudaFuncSetAttribute(attn_kernel, cudaFuncAttributeMaxDynamicSharedMemorySize, attn_smem);

    // 1. embed
    embed_kernel<<<(MM * EE / 4) / 256, 256>>>(ids, wte, wpe, x);
    // 2. ln1
    ln_kernel<<<MM, 256>>>(x, ln1g, ln1b, h);
    // 3. qkv projections  (W layout (H,E,D))
    dim3 g1(EE / 128, MM / 128);
    gemm_kernel<1, false, false><<<g1, 256>>>(h, wq, bq, nullptr, q, MM, EE, EE);
    gemm_kernel<1, false, false><<<g1, 256>>>(h, wk, bk, nullptr, k, MM, EE, EE);
    gemm_kernel<1, false, false><<<g1, 256>>>(h, wv, bv, nullptr, v, MM, EE, EE);
    // 4. causal flash attention
    attn_kernel<<<dim3(TT / 64, HH, BB), 256, attn_smem>>>(q, k, v, o);
    // 5. proj + residual  -> x2
    gemm_kernel<0, false, true><<<g1, 256>>>(o, wproj, bproj, x, x2, MM, EE, EE);
    // 6. ln2
    ln_kernel<<<MM, 256>>>(x2, ln2g, ln2b, h);
    // 7. fc + gelu -> m
    dim3 g2(FF / 128, MM / 128);
    gemm_kernel<0, true, false><<<g2, 256>>>(h, wfc, bfc, nullptr, mb, MM, FF, EE);
    // 8. out proj + residual -> d_out
    gemm_kernel<0, false, true><<<g1, 256>>>(mb, wout, bout, x2, out, MM, EE, FF);
}

// round 4
// speedup vs baseline: 1.6538x; 1.6538x over previous
#include <cuda_runtime.h>
#include <cuda_bf16.h>
#include <math.h>
#include <stdint.h>

// Problem constants
#define BB 4
#define TT 2048
#define EE 1024
#define HH 16
#define DD 64
#define MM (BB*TT)        // 8192
#define FF (4*EE)         // 4096

// ---------------- scratch (device globals; no allocation allowed) -------------
__device__ float g_x [MM*EE];
__device__ float g_h [MM*EE];
__device__ float g_q [MM*EE];
__device__ float g_k [MM*EE];
__device__ float g_v [MM*EE];
__device__ float g_o [MM*EE];
__device__ float g_x2[MM*EE];
__device__ float g_m [(size_t)MM*FF];
// pre-transposed weights (K-major, [N,K] row-major, tf32-rounded)
__device__ float g_wtq [EE*EE];
__device__ float g_wtk [EE*EE];
__device__ float g_wtv [EE*EE];
__device__ float g_wtp [EE*EE];
__device__ float g_wtfc [(size_t)FF*EE];
__device__ float g_wtout[(size_t)EE*FF];

// ---------------- helpers -----------------------------------------------------
__device__ __forceinline__ uint32_t smem_u32(const void* p) {
    uint32_t a;
    asm("{ .reg .u64 t; cvta.to.shared.u64 t, %1; cvt.u32.u64 %0, t; }" : "=r"(a) : "l"(p));
    return a;
}
__device__ __forceinline__ float tf32r(float x) {
    uint32_t u;
    asm("cvt.rna.tf32.f32 %0, %1;" : "=r"(u) : "f"(x));
    return __uint_as_float(u);
}
__device__ __forceinline__ void cp16(uint32_t dst, const void* src) {
    asm volatile("cp.async.cg.shared.global [%0], [%1], 16;" :: "r"(dst), "l"(src));
}
#define CP_COMMIT() asm volatile("cp.async.commit_group;" ::: "memory")
#define CP_WAIT(n)  asm volatile("cp.async.wait_group %0;" :: "n"(n) : "memory")

// mma.sync m16n8k8 tf32 (sm_80+ base-target instruction; works on sm_103)
__device__ __forceinline__ void mma8(float* d, const uint32_t* a, const uint32_t* b) {
    asm volatile("mma.sync.aligned.m16n8k8.row.col.f32.tf32.tf32.f32 "
        "{%0,%1,%2,%3}, {%4,%5,%6,%7}, {%8,%9}, {%0,%1,%2,%3};"
        : "+f"(d[0]), "+f"(d[1]), "+f"(d[2]), "+f"(d[3])
        : "r"(a[0]), "r"(a[1]), "r"(a[2]), "r"(a[3]), "r"(b[0]), "r"(b[1]));
}

// ---------------- embed: x = wte[ids] + wpe ----------------------------------
__global__ __launch_bounds__(256) void embed_kernel(
    const int* __restrict__ ids, const float* __restrict__ wte,
    const float* __restrict__ wpe, float* __restrict__ X)
{
    int i = blockIdx.x * 256 + threadIdx.x;
    int row = i >> 8;
    int c   = i & 255;
    int t   = row & (TT - 1);
    int id  = ids[row];
    float4 a = ((const float4*)wte)[(size_t)id * 256 + c];
    float4 p = ((const float4*)wpe)[(size_t)t  * 256 + c];
    a.x += p.x; a.y += p.y; a.z += p.z; a.w += p.w;
    ((float4*)X)[i] = a;
}

// ---------------- layernorm (output tf32-rounded: feeds GEMM A only) ----------
__global__ __launch_bounds__(256) void ln_kernel(
    const float* __restrict__ X, const float* __restrict__ G,
    const float* __restrict__ Bt, float* __restrict__ Y)
{
    __shared__ float red[16];
    int row = blockIdx.x, tid = threadIdx.x;
    const float4* x4 = (const float4*)(X + ((size_t)row << 10));
    float4 a = x4[tid];
    float s  = a.x + a.y + a.z + a.w;
    float sq = a.x*a.x + a.y*a.y + a.z*a.z + a.w*a.w;
    #pragma unroll
    for (int o = 16; o; o >>= 1) {
        s  += __shfl_xor_sync(0xffffffffu, s,  o);
        sq += __shfl_xor_sync(0xffffffffu, sq, o);
    }
    if ((tid & 31) == 0) { red[tid >> 5] = s; red[8 + (tid >> 5)] = sq; }
    __syncthreads();
    float ts = 0.f, tq = 0.f;
    #pragma unroll
    for (int i = 0; i < 8; i++) { ts += red[i]; tq += red[8 + i]; }
    float mean = ts * (1.f / 1024.f);
    float var  = tq * (1.f / 1024.f) - mean * mean;
    float inv  = rsqrtf(var + 1e-5f);
    float4 g4 = ((const float4*)G)[tid];
    float4 b4 = ((const float4*)Bt)[tid];
    float4 o;
    o.x = tf32r((a.x - mean) * inv * g4.x + b4.x);
    o.y = tf32r((a.y - mean) * inv * g4.y + b4.y);
    o.z = tf32r((a.z - mean) * inv * g4.z + b4.z);
    o.w = tf32r((a.w - mean) * inv * g4.w + b4.w);
    ((float4*)(Y + ((size_t)row << 10)))[tid] = o;
}

// ---------------- weight transposes (tf32-rounded) -----------------------------
__global__ __launch_bounds__(256) void transpose_kernel(
    const float* __restrict__ W, float* __restrict__ Wt, int K, int N)
{
    __shared__ float t[32][33];
    int tx = threadIdx.x, ty = threadIdx.y;
    int k0 = blockIdx.y * 32, n0 = blockIdx.x * 32;
    #pragma unroll
    for (int i = ty; i < 32; i += 8) t[i][tx] = W[(size_t)(k0 + i) * N + n0 + tx];
    __syncthreads();
    #pragma unroll
    for (int i = ty; i < 32; i += 8)
        Wt[(size_t)(n0 + i) * K + k0 + tx] = tf32r(t[tx][i]);
}
__global__ __launch_bounds__(256) void transpose_qkv_kernel(
    const float* __restrict__ W, float* __restrict__ Wt)
{
    __shared__ float t[32][33];
    int tx = threadIdx.x, ty = threadIdx.y;
    int h = blockIdx.z, k0 = blockIdx.y * 32, d0 = blockIdx.x * 32;
    const float* Wh = W + (size_t)h * EE * DD;
    #pragma unroll
    for (int i = ty; i < 32; i += 8) t[i][tx] = Wh[(size_t)(k0 + i) * DD + d0 + tx];
    __syncthreads();
    #pragma unroll
    for (int i = ty; i < 32; i += 8)
        Wt[(size_t)(h * DD + d0 + i) * EE + k0 + tx] = tf32r(t[tx][i]);
}

// ---------------- mma.sync tf32 GEMM ------------------------------------------
// C[M,N] = act(A[M,K] @ Wt[N,K]^T + bias [+ R])
// CTA 128x128, BK=32, 3-stage cp.async pipeline. 8 warps = 2(m) x 4(n),
// warp tile 64x32 via m16n8k8 (4 m-frags x 4 n-frags).
#define GPAD  36                           // padded row stride (floats)
#define GSTGF (2*128*GPAD)                 // floats per stage (A+B)
#define GSTGB (GSTGF*4)                    // bytes per stage
#define GSMEM (3*GSTGB)

__device__ __forceinline__ void gcp_stage(
    uint32_t sbase, int s, const float* __restrict__ A, const float* __restrict__ Wt,
    int bm, int bn, int K, int k0, int tid)
{
    uint32_t sA = sbase + s * GSTGB;
    uint32_t sB = sA + 128 * GPAD * 4;
    #pragma unroll
    for (int e = 0; e < 4; e++) {
        int lin = tid + 256 * e;           // 0..1023
        int r = lin >> 3, c = lin & 7;     // row, 16B-chunk
        cp16(sA + r * (GPAD*4) + c * 16, A  + (size_t)(bm + r) * K + k0 + c * 4);
        cp16(sB + r * (GPAD*4) + c * 16, Wt + (size_t)(bn + r) * K + k0 + c * 4);
    }
}

template<bool GELU_, bool RES>
__global__ __launch_bounds__(256) void tc_gemm(
    const float* __restrict__ A, const float* __restrict__ Wt,
    const float* __restrict__ bias, const float* __restrict__ Rp,
    float* __restrict__ C, int M, int N, int K)
{
    extern __shared__ __align__(16) float smf[];
    uint32_t sbase = smem_u32(smf);
    const int tid = threadIdx.x, wid = tid >> 5, lid = tid & 31;
    const int g = lid >> 2, t = lid & 3;
    const int bm = blockIdx.y * 128, bn = blockIdx.x * 128;
    const int warp_m = (wid & 1) * 64, warp_n = (wid >> 1) * 32;
    const int NT = K >> 5;

    float d[4][4][4];
    #pragma unroll
    for (int i = 0; i < 4; i++)
        #pragma unroll
        for (int j = 0; j < 4; j++)
            #pragma unroll
            for (int p = 0; p < 4; p++) d[i][j][p] = 0.f;

    gcp_stage(sbase, 0, A, Wt, bm, bn, K, 0,  tid); CP_COMMIT();
    gcp_stage(sbase, 1, A, Wt, bm, bn, K, 32, tid); CP_COMMIT();

    for (int kt = 0; kt < NT; kt++) {
        if (kt == NT - 1) { CP_WAIT(0); } else { CP_WAIT(1); }
        __syncthreads();
        if (kt + 2 < NT) {
            gcp_stage(sbase, (kt + 2) % 3, A, Wt, bm, bn, K, (kt + 2) * 32, tid);
            CP_COMMIT();
        }
        const float* As = smf + (size_t)((kt % 3)) * GSTGF;
        const float* Bs = As + 128 * GPAD;
        #pragma unroll
        for (int k8 = 0; k8 < 4; k8++) {
            int kc = k8 * 8 + t;
            uint32_t af[4][4], bf[4][2];
            #pragma unroll
            for (int mf = 0; mf < 4; mf++) {
                int rm = warp_m + mf * 16 + g;
                af[mf][0] = __float_as_uint(As[rm * GPAD + kc]);
                af[mf][1] = __float_as_uint(As[(rm + 8) * GPAD + kc]);
                af[mf][2] = __float_as_uint(As[rm * GPAD + kc + 4]);
                af[mf][3] = __float_as_uint(As[(rm + 8) * GPAD + kc + 4]);
            }
            #pragma unroll
            for (int nf = 0; nf < 4; nf++) {
                int rn = warp_n + nf * 8 + g;
                bf[nf][0] = __float_as_uint(Bs[rn * GPAD + kc]);
                bf[nf][1] = __float_as_uint(Bs[rn * GPAD + kc + 4]);
            }
            #pragma unroll
            for (int mf = 0; mf < 4; mf++)
                #pragma unroll
                for (int nf = 0; nf < 4; nf++)
                    mma8(d[mf][nf], af[mf], bf[nf]);
        }
        __syncthreads();
    }

    // epilogue
    #pragma unroll
    for (int mf = 0; mf < 4; mf++) {
        int row0 = bm + warp_m + mf * 16 + g;
        #pragma unroll
        for (int nf = 0; nf < 4; nf++) {
            int col = bn + warp_n + nf * 8 + 2 * t;
            float b0 = __ldg(bias + col), b1 = __ldg(bias + col + 1);
            #pragma unroll
            for (int p = 0; p < 2; p++) {
                int m = row0 + p * 8;
                float v0 = d[mf][nf][2 * p + 0] + b0;
                float v1 = d[mf][nf][2 * p + 1] + b1;
                if (GELU_) {
                    v0 = 0.5f * v0 * (1.f + erff(v0 * 0.70710678118654752f));
                    v1 = 0.5f * v1 * (1.f + erff(v1 * 0.70710678118654752f));
                    v0 = tf32r(v0); v1 = tf32r(v1);   // feeds next GEMM's A
                }
                if (RES) {
                    float2 rr = *(const float2*)(Rp + (size_t)m * N + col);
                    v0 += rr.x; v1 += rr.y;
                }
                float2 o; o.x = v0; o.y = v1;
                *(float2*)(C + (size_t)m * N + col) = o;
            }
        }
    }
}

// ---------------- flash attention (causal, fp32) ------------------------------
#define AST 68
__global__ __launch_bounds__(256) void attn_kernel(
    const float* __restrict__ Q, const float* __restrict__ K,
    const float* __restrict__ V, float* __restrict__ O)
{
    extern __shared__ float sm[];
    float* Qs = sm;
    float* Ks = sm + 64 * AST;
    float* Vs = sm + 2 * 64 * AST;
    float* Ps = sm + 3 * 64 * AST;

    int qt = blockIdx.x, h = blockIdx.y, b = blockIdx.z;
    int tid = threadIdx.x;
    int sub = tid & 7;
    int r   = tid >> 3;

    const size_t base = ((size_t)(b * TT) << 10) + ((size_t)h << 6);

    {
        int lr = tid >> 2, lc = (tid & 3) * 16;
        const float4* src = (const float4*)(Q + base + ((size_t)(qt * 64 + lr) << 10) + lc);
        float4* dst = (float4*)(Qs + lr * AST + lc);
        dst[0] = src[0]; dst[1] = src[1]; dst[2] = src[2]; dst[3] = src[3];
    }
    __syncthreads();

    float q0[8], q1[8];
    const float sc_qk = 0.125f;
    #pragma unroll
    for (int i = 0; i < 8; i++) {
        q0[i] = Qs[r * AST + sub * 8 + i] * sc_qk;
        q1[i] = Qs[(r + 32) * AST + sub * 8 + i] * sc_qk;
    }
    float m0 = -INFINITY, m1 = -INFINITY, l0 = 0.f, l1 = 0.f;
    float acc0[8], acc1[8];
    #pragma unroll
    for (int i = 0; i < 8; i++) { acc0[i] = 0.f; acc1[i] = 0.f; }
    int iq0 = qt * 64 + r, iq1 = iq0 + 32;

    for (int kt = 0; kt <= qt; kt++) {
        __syncthreads();
        {
            int lr = tid >> 2, lc = (tid & 3) * 16;
            const float4* sk = (const float4*)(K + base + ((size_t)(kt * 64 + lr) << 10) + lc);
            const float4* sv = (const float4*)(V + base + ((size_t)(kt * 64 + lr) << 10) + lc);
            float4* dk = (float4*)(Ks + lr * AST + lc);
            float4* dv = (float4*)(Vs + lr * AST + lc);
            dk[0]=sk[0]; dk[1]=sk[1]; dk[2]=sk[2]; dk[3]=sk[3];
            dv[0]=sv[0]; dv[1]=sv[1]; dv[2]=sv[2]; dv[3]=sv[3];
        }
        __syncthreads();

        float mx0 = -INFINITY, mx1 = -INFINITY;
        bool diag = (kt == qt);
        #pragma unroll 4
        for (int j = 0; j < 64; j++) {
            const float4* kr = (const float4*)(Ks + j * AST + sub * 8);
            float4 ka = kr[0], kb = kr[1];
            float kk[8] = {ka.x,ka.y,ka.z,ka.w,kb.x,kb.y,kb.z,kb.w};
            float s0 = 0.f, s1 = 0.f;
            #pragma unroll
            for (int i = 0; i < 8; i++) { s0 += q0[i]*kk[i]; s1 += q1[i]*kk[i]; }
            #pragma unroll
            for (int o = 1; o < 8; o <<= 1) {
                s0 += __shfl_xor_sync(0xffffffffu, s0, o);
                s1 += __shfl_xor_sync(0xffffffffu, s1, o);
            }
            if (diag) {
                int jg = kt * 64 + j;
                if (jg > iq0) s0 = -INFINITY;
                if (jg > iq1) s1 = -INFINITY;
            }
            mx0 = fmaxf(mx0, s0); mx1 = fmaxf(mx1, s1);
            if (sub == (j & 7)) { Ps[r * AST + j] = s0; Ps[(r + 32) * AST + j] = s1; }
        }
        float nm0 = fmaxf(m0, mx0), nm1 = fmaxf(m1, mx1);
        float scl0 = expf(m0 - nm0), scl1 = expf(m1 - nm1);
        float ls0 = 0.f, ls1 = 0.f;
        #pragma unroll
        for (int jj = 0; jj < 8; jj++) {
            int j = jj * 8 + sub;
            float e0 = expf(Ps[r * AST + j] - nm0);
            float e1 = expf(Ps[(r + 32) * AST + j] - nm1);
            Ps[r * AST + j] = e0; Ps[(r + 32) * AST + j] = e1;
            ls0 += e0; ls1 += e1;
        }
        #pragma unroll
        for (int o = 1; o < 8; o <<= 1) {
            ls0 += __shfl_xor_sync(0xffffffffu, ls0, o);
            ls1 += __shfl_xor_sync(0xffffffffu, ls1, o);
        }
        l0 = l0 * scl0 + ls0; l1 = l1 * scl1 + ls1;
        #pragma unroll
        for (int i = 0; i < 8; i++) { acc0[i] *= scl0; acc1[i] *= scl1; }
        __syncwarp();
        #pragma unroll 4
        for (int j = 0; j < 64; j++) {
            float p0 = Ps[r * AST + j], p1 = Ps[(r + 32) * AST + j];
            const float4* vr = (const float4*)(Vs + j * AST + sub * 8);
            float4 va = vr[0], vb = vr[1];
            float vv[8] = {va.x,va.y,va.z,va.w,vb.x,vb.y,vb.z,vb.w};
            #pragma unroll
            for (int i = 0; i < 8; i++) { acc0[i] += p0*vv[i]; acc1[i] += p1*vv[i]; }
        }
        m0 = nm0; m1 = nm1;
    }

    float inv0 = 1.f / l0, inv1 = 1.f / l1;
    float* o0 = O + base + ((size_t)(qt * 64 + r) << 10) + sub * 8;
    float* o1 = O + base + ((size_t)(qt * 64 + r + 32) << 10) + sub * 8;
    float4 w0, w1;
    // tf32-round: o feeds the proj GEMM's A operand
    w0.x = tf32r(acc0[0]*inv0); w0.y = tf32r(acc0[1]*inv0);
    w0.z = tf32r(acc0[2]*inv0); w0.w = tf32r(acc0[3]*inv0);
    w1.x = tf32r(acc0[4]*inv0); w1.y = tf32r(acc0[5]*inv0);
    w1.z = tf32r(acc0[6]*inv0); w1.w = tf32r(acc0[7]*inv0);
    ((float4*)o0)[0] = w0; ((float4*)o0)[1] = w1;
    w0.x = tf32r(acc1[0]*inv1); w0.y = tf32r(acc1[1]*inv1);
    w0.z = tf32r(acc1[2]*inv1); w0.w = tf32r(acc1[3]*inv1);
    w1.x = tf32r(acc1[4]*inv1); w1.y = tf32r(acc1[5]*inv1);
    w1.z = tf32r(acc1[6]*inv1); w1.w = tf32r(acc1[7]*inv1);
    ((float4*)o1)[0] = w0; ((float4*)o1)[1] = w1;
}

// ---------------- launch ------------------------------------------------------
extern "C" void kernel_launch(void* const* d_in, const int* in_sizes, int n_in,
                              void* d_out, int out_size)
{
    const int*   ids   = (const int*)  d_in[0];
    const float* wte   = (const float*)d_in[1];
    const float* wpe   = (const float*)d_in[2];
    const float* wq    = (const float*)d_in[3];
    const float* wk    = (const float*)d_in[4];
    const float* wv    = (const float*)d_in[5];
    const float* bq    = (const float*)d_in[6];
    const float* bk    = (const float*)d_in[7];
    const float* bv    = (const float*)d_in[8];
    const float* wproj = (const float*)d_in[9];
    const float* bproj = (const float*)d_in[10];
    const float* ln1g  = (const float*)d_in[11];
    const float* ln1b  = (const float*)d_in[12];
    const float* ln2g  = (const float*)d_in[13];
    const float* ln2b  = (const float*)d_in[14];
    const float* wfc   = (const float*)d_in[15];
    const float* bfc   = (const float*)d_in[16];
    const float* wout  = (const float*)d_in[17];
    const float* bout  = (const float*)d_in[18];
    float* out = (float*)d_out;

    float *x, *h, *q, *k, *v, *o, *x2, *mb;
    float *wtq, *wtk, *wtv, *wtp, *wtfc, *wtout;
    cudaGetSymbolAddress((void**)&x,  g_x);
    cudaGetSymbolAddress((void**)&h,  g_h);
    cudaGetSymbolAddress((void**)&q,  g_q);
    cudaGetSymbolAddress((void**)&k,  g_k);
    cudaGetSymbolAddress((void**)&v,  g_v);
    cudaGetSymbolAddress((void**)&o,  g_o);
    cudaGetSymbolAddress((void**)&x2, g_x2);
    cudaGetSymbolAddress((void**)&mb, g_m);
    cudaGetSymbolAddress((void**)&wtq,  g_wtq);
    cudaGetSymbolAddress((void**)&wtk,  g_wtk);
    cudaGetSymbolAddress((void**)&wtv,  g_wtv);
    cudaGetSymbolAddress((void**)&wtp,  g_wtp);
    cudaGetSymbolAddress((void**)&wtfc, g_wtfc);
    cudaGetSymbolAddress((void**)&wtout,g_wtout);

    const int attn_smem = 4 * 64 * AST * 4;
    cudaFuncSetAttribute(attn_kernel, cudaFuncAttributeMaxDynamicSharedMemorySize, attn_smem);
    cudaFuncSetAttribute(tc_gemm<false,false>, cudaFuncAttributeMaxDynamicSharedMemorySize, GSMEM);
    cudaFuncSetAttribute(tc_gemm<false,true>,  cudaFuncAttributeMaxDynamicSharedMemorySize, GSMEM);
    cudaFuncSetAttribute(tc_gemm<true,false>,  cudaFuncAttributeMaxDynamicSharedMemorySize, GSMEM);

    dim3 tb(32, 8);
    // weight transposes (K-major + tf32 rounding)
    transpose_qkv_kernel<<<dim3(2, 32, 16), tb>>>(wq, wtq);
    transpose_qkv_kernel<<<dim3(2, 32, 16), tb>>>(wk, wtk);
    transpose_qkv_kernel<<<dim3(2, 32, 16), tb>>>(wv, wtv);
    transpose_kernel<<<dim3(32, 32),  tb>>>(wproj, wtp,  EE, EE);
    transpose_kernel<<<dim3(128, 32), tb>>>(wfc,   wtfc, EE, FF);
    transpose_kernel<<<dim3(32, 128), tb>>>(wout,  wtout, FF, EE);

    // 1. embed
    embed_kernel<<<(MM * EE / 4) / 256, 256>>>(ids, wte, wpe, x);
    // 2. ln1
    ln_kernel<<<MM, 256>>>(x, ln1g, ln1b, h);
    // 3. qkv projections (tf32 mma.sync)
    dim3 g1(EE / 128, MM / 128);
    tc_gemm<false,false><<<g1, 256, GSMEM>>>(h, wtq, bq, nullptr, q, MM, EE, EE);
    tc_gemm<false,false><<<g1, 256, GSMEM>>>(h, wtk, bk, nullptr, k, MM, EE, EE);
    tc_gemm<false,false><<<g1, 256, GSMEM>>>(h, wtv, bv, nullptr, v, MM, EE, EE);
    // 4. causal flash attention
    attn_kernel<<<dim3(TT / 64, HH, BB), 256, attn_smem>>>(q, k, v, o);
    // 5. proj + residual -> x2
    tc_gemm<false,true><<<g1, 256, GSMEM>>>(o, wtp, bproj, x, x2, MM, EE, EE);
    // 6. ln2
    ln_kernel<<<MM, 256>>>(x2, ln2g, ln2b, h);
    // 7. fc + gelu -> m
    dim3 g2(FF / 128, MM / 128);
    tc_gemm<true,false><<<g2, 256, GSMEM>>>(h, wtfc, bfc, nullptr, mb, MM, FF, EE);
    // 8. out proj + residual -> d_out
    tc_gemm<false,true><<<g1, 256, GSMEM>>>(mb, wtout, bout, x2, out, MM, EE, FF);
}

// round 5
// speedup vs baseline: 3.6666x; 2.2171x over previous
#include <cuda_runtime.h>
#include <cuda_bf16.h>
#include <math.h>
#include <stdint.h>

// Problem constants
#define BB 4
#define TT 2048
#define EE 1024
#define HH 16
#define DD 64
#define MM (BB*TT)        // 8192
#define FF (4*EE)         // 4096

// ---------------- scratch (device globals; no allocation allowed) -------------
__device__ float g_x [MM*EE];
__device__ float g_h [MM*EE];
__device__ float g_q [MM*EE];
__device__ float g_k [MM*EE];
__device__ float g_v [MM*EE];
__device__ float g_o [MM*EE];
__device__ float g_x2[MM*EE];
__device__ float g_m [(size_t)MM*FF];
// pre-transposed weights (K-major, [N,K] row-major, tf32-rounded)
__device__ float g_wtq [EE*EE];
__device__ float g_wtk [EE*EE];
__device__ float g_wtv [EE*EE];
__device__ float g_wtp [EE*EE];
__device__ float g_wtfc [(size_t)FF*EE];
__device__ float g_wtout[(size_t)EE*FF];

// ---------------- helpers -----------------------------------------------------
__device__ __forceinline__ uint32_t smem_u32(const void* p) {
    uint32_t a;
    asm("{ .reg .u64 t; cvta.to.shared.u64 t, %1; cvt.u32.u64 %0, t; }" : "=r"(a) : "l"(p));
    return a;
}
__device__ __forceinline__ float tf32r(float x) {
    uint32_t u;
    asm("cvt.rna.tf32.f32 %0, %1;" : "=r"(u) : "f"(x));
    return __uint_as_float(u);
}
__device__ __forceinline__ void cp16(uint32_t dst, const void* src) {
    asm volatile("cp.async.cg.shared.global [%0], [%1], 16;" :: "r"(dst), "l"(src));
}
#define CP_COMMIT() asm volatile("cp.async.commit_group;" ::: "memory")
#define CP_WAIT(n)  asm volatile("cp.async.wait_group %0;" :: "n"(n) : "memory")

// mma.sync m16n8k8 tf32 (base-target instruction, works on sm_103)
__device__ __forceinline__ void mma8(float* d, const uint32_t* a, const uint32_t* b) {
    asm volatile("mma.sync.aligned.m16n8k8.row.col.f32.tf32.tf32.f32 "
        "{%0,%1,%2,%3}, {%4,%5,%6,%7}, {%8,%9}, {%0,%1,%2,%3};"
        : "+f"(d[0]), "+f"(d[1]), "+f"(d[2]), "+f"(d[3])
        : "r"(a[0]), "r"(a[1]), "r"(a[2]), "r"(a[3]), "r"(b[0]), "r"(b[1]));
}

// ---------------- embed: x = wte[ids] + wpe ----------------------------------
__global__ __launch_bounds__(256) void embed_kernel(
    const int* __restrict__ ids, const float* __restrict__ wte,
    const float* __restrict__ wpe, float* __restrict__ X)
{
    int i = blockIdx.x * 256 + threadIdx.x;
    int row = i >> 8;
    int c   = i & 255;
    int t   = row & (TT - 1);
    int id  = ids[row];
    float4 a = ((const float4*)wte)[(size_t)id * 256 + c];
    float4 p = ((const float4*)wpe)[(size_t)t  * 256 + c];
    a.x += p.x; a.y += p.y; a.z += p.z; a.w += p.w;
    ((float4*)X)[i] = a;
}

// ---------------- layernorm (output tf32-rounded: feeds GEMM A) ---------------
__global__ __launch_bounds__(256) void ln_kernel(
    const float* __restrict__ X, const float* __restrict__ G,
    const float* __restrict__ Bt, float* __restrict__ Y)
{
    __shared__ float red[16];
    int row = blockIdx.x, tid = threadIdx.x;
    const float4* x4 = (const float4*)(X + ((size_t)row << 10));
    float4 a = x4[tid];
    float s  = a.x + a.y + a.z + a.w;
    float sq = a.x*a.x + a.y*a.y + a.z*a.z + a.w*a.w;
    #pragma unroll
    for (int o = 16; o; o >>= 1) {
        s  += __shfl_xor_sync(0xffffffffu, s,  o);
        sq += __shfl_xor_sync(0xffffffffu, sq, o);
    }
    if ((tid & 31) == 0) { red[tid >> 5] = s; red[8 + (tid >> 5)] = sq; }
    __syncthreads();
    float ts = 0.f, tq = 0.f;
    #pragma unroll
    for (int i = 0; i < 8; i++) { ts += red[i]; tq += red[8 + i]; }
    float mean = ts * (1.f / 1024.f);
    float var  = tq * (1.f / 1024.f) - mean * mean;
    float inv  = rsqrtf(var + 1e-5f);
    float4 g4 = ((const float4*)G)[tid];
    float4 b4 = ((const float4*)Bt)[tid];
    float4 o;
    o.x = tf32r((a.x - mean) * inv * g4.x + b4.x);
    o.y = tf32r((a.y - mean) * inv * g4.y + b4.y);
    o.z = tf32r((a.z - mean) * inv * g4.z + b4.z);
    o.w = tf32r((a.w - mean) * inv * g4.w + b4.w);
    ((float4*)(Y + ((size_t)row << 10)))[tid] = o;
}

// ---------------- weight transposes (tf32-rounded) -----------------------------
__global__ __launch_bounds__(256) void transpose_kernel(
    const float* __restrict__ W, float* __restrict__ Wt, int K, int N)
{
    __shared__ float t[32][33];
    int tx = threadIdx.x, ty = threadIdx.y;
    int k0 = blockIdx.y * 32, n0 = blockIdx.x * 32;
    #pragma unroll
    for (int i = ty; i < 32; i += 8) t[i][tx] = W[(size_t)(k0 + i) * N + n0 + tx];
    __syncthreads();
    #pragma unroll
    for (int i = ty; i < 32; i += 8)
        Wt[(size_t)(n0 + i) * K + k0 + tx] = tf32r(t[tx][i]);
}
__global__ __launch_bounds__(256) void transpose_qkv_kernel(
    const float* __restrict__ W, float* __restrict__ Wt)
{
    __shared__ float t[32][33];
    int tx = threadIdx.x, ty = threadIdx.y;
    int h = blockIdx.z, k0 = blockIdx.y * 32, d0 = blockIdx.x * 32;
    const float* Wh = W + (size_t)h * EE * DD;
    #pragma unroll
    for (int i = ty; i < 32; i += 8) t[i][tx] = Wh[(size_t)(k0 + i) * DD + d0 + tx];
    __syncthreads();
    #pragma unroll
    for (int i = ty; i < 32; i += 8)
        Wt[(size_t)(h * DD + d0 + i) * EE + k0 + tx] = tf32r(t[tx][i]);
}

// ---------------- mma.sync tf32 GEMM ------------------------------------------
#define GPAD  36
#define GSTGF (2*128*GPAD)
#define GSTGB (GSTGF*4)
#define GSMEM (3*GSTGB)

__device__ __forceinline__ void gcp_stage(
    uint32_t sbase, int s, const float* __restrict__ A, const float* __restrict__ Wt,
    int bm, int bn, int K, int k0, int tid)
{
    uint32_t sA = sbase + s * GSTGB;
    uint32_t sB = sA + 128 * GPAD * 4;
    #pragma unroll
    for (int e = 0; e < 4; e++) {
        int lin = tid + 256 * e;
        int r = lin >> 3, c = lin & 7;
        cp16(sA + r * (GPAD*4) + c * 16, A  + (size_t)(bm + r) * K + k0 + c * 4);
        cp16(sB + r * (GPAD*4) + c * 16, Wt + (size_t)(bn + r) * K + k0 + c * 4);
    }
}

template<bool GELU_, bool RES, bool TF32OUT>
__global__ __launch_bounds__(256) void tc_gemm(
    const float* __restrict__ A, const float* __restrict__ Wt,
    const float* __restrict__ bias, const float* __restrict__ Rp,
    float* __restrict__ C, int M, int N, int K)
{
    extern __shared__ __align__(16) float smf[];
    uint32_t sbase = smem_u32(smf);
    const int tid = threadIdx.x, wid = tid >> 5, lid = tid & 31;
    const int g = lid >> 2, t = lid & 3;
    const int bm = blockIdx.y * 128, bn = blockIdx.x * 128;
    const int warp_m = (wid & 1) * 64, warp_n = (wid >> 1) * 32;
    const int NT = K >> 5;

    float d[4][4][4];
    #pragma unroll
    for (int i = 0; i < 4; i++)
        #pragma unroll
        for (int j = 0; j < 4; j++)
            #pragma unroll
            for (int p = 0; p < 4; p++) d[i][j][p] = 0.f;

    gcp_stage(sbase, 0, A, Wt, bm, bn, K, 0,  tid); CP_COMMIT();
    gcp_stage(sbase, 1, A, Wt, bm, bn, K, 32, tid); CP_COMMIT();

    for (int kt = 0; kt < NT; kt++) {
        if (kt == NT - 1) { CP_WAIT(0); } else { CP_WAIT(1); }
        __syncthreads();
        if (kt + 2 < NT) {
            gcp_stage(sbase, (kt + 2) % 3, A, Wt, bm, bn, K, (kt + 2) * 32, tid);
            CP_COMMIT();
        }
        const float* As = smf + (size_t)((kt % 3)) * GSTGF;
        const float* Bs = As + 128 * GPAD;
        #pragma unroll
        for (int k8 = 0; k8 < 4; k8++) {
            int kc = k8 * 8 + t;
            uint32_t af[4][4], bf[4][2];
            #pragma unroll
            for (int mf = 0; mf < 4; mf++) {
                int rm = warp_m + mf * 16 + g;
                af[mf][0] = __float_as_uint(As[rm * GPAD + kc]);
                af[mf][1] = __float_as_uint(As[(rm + 8) * GPAD + kc]);
                af[mf][2] = __float_as_uint(As[rm * GPAD + kc + 4]);
                af[mf][3] = __float_as_uint(As[(rm + 8) * GPAD + kc + 4]);
            }
            #pragma unroll
            for (int nf = 0; nf < 4; nf++) {
                int rn = warp_n + nf * 8 + g;
                bf[nf][0] = __float_as_uint(Bs[rn * GPAD + kc]);
                bf[nf][1] = __float_as_uint(Bs[rn * GPAD + kc + 4]);
            }
            #pragma unroll
            for (int mf = 0; mf < 4; mf++)
                #pragma unroll
                for (int nf = 0; nf < 4; nf++)
                    mma8(d[mf][nf], af[mf], bf[nf]);
        }
        __syncthreads();
    }

    // epilogue
    #pragma unroll
    for (int mf = 0; mf < 4; mf++) {
        int row0 = bm + warp_m + mf * 16 + g;
        #pragma unroll
        for (int nf = 0; nf < 4; nf++) {
            int col = bn + warp_n + nf * 8 + 2 * t;
            float b0 = __ldg(bias + col), b1 = __ldg(bias + col + 1);
            #pragma unroll
            for (int p = 0; p < 2; p++) {
                int m = row0 + p * 8;
                float v0 = d[mf][nf][2 * p + 0] + b0;
                float v1 = d[mf][nf][2 * p + 1] + b1;
                if (GELU_) {
                    v0 = 0.5f * v0 * (1.f + erff(v0 * 0.70710678118654752f));
                    v1 = 0.5f * v1 * (1.f + erff(v1 * 0.70710678118654752f));
                    v0 = tf32r(v0); v1 = tf32r(v1);
                }
                if (TF32OUT) { v0 = tf32r(v0); v1 = tf32r(v1); }
                if (RES) {
                    float2 rr = *(const float2*)(Rp + (size_t)m * N + col);
                    v0 += rr.x; v1 += rr.y;
                }
                float2 o; o.x = v0; o.y = v1;
                *(float2*)(C + (size_t)m * N + col) = o;
            }
        }
    }
}

// ---------------- tensor-core flash attention (causal, tf32) ------------------
// CTA: 128 q-rows x (b,h); 8 warps, warp w owns rows 16w..16w+15.
// Pads: Q/K/P stride 68 (bank 4g+t), V stride 72 (bank 8t+g): conflict-free.
#define QPAD 68
#define KPAD 68
#define VPAD 72
#define A_QS 0
#define A_KS (128*QPAD)
#define A_VS (A_KS + 2*64*KPAD)
#define A_END (A_VS + 2*64*VPAD)
#define ATT_SMEM (A_END*4)

__global__ __launch_bounds__(256) void attn_tc(
    const float* __restrict__ Q, const float* __restrict__ Kp,
    const float* __restrict__ Vp, float* __restrict__ O)
{
    extern __shared__ __align__(16) float sm[];
    uint32_t sb = smem_u32(sm);
    const int qt = (int)gridDim.x - 1 - (int)blockIdx.x;   // big tiles first
    const int h = blockIdx.y, b = blockIdx.z;
    const int tid = threadIdx.x, wid = tid >> 5, lid = tid & 31;
    const int g = lid >> 2, t = lid & 3;
    const int qbase = qt * 128;
    const size_t base = (size_t)(b * TT) * EE + (size_t)h * DD;
    const float alpha = 0.18033688011112042f;   // 0.125 * log2(e)

    // Q tile -> smem (scaled + tf32-rounded)
    #pragma unroll
    for (int i = 0; i < 8; i++) {
        int idx = tid + i * 256;
        int r = idx >> 4, c = (idx & 15) * 4;
        float4 v4 = *(const float4*)(Q + base + (size_t)(qbase + r) * EE + c);
        v4.x = tf32r(v4.x * alpha); v4.y = tf32r(v4.y * alpha);
        v4.z = tf32r(v4.z * alpha); v4.w = tf32r(v4.w * alpha);
        *(float4*)&sm[A_QS + r * QPAD + c] = v4;
    }
    __syncthreads();

    // Q A-fragments -> registers (Qs region then reused as P scratch)
    uint32_t aQ[8][4];
    const int lr0 = wid * 16 + g;
    #pragma unroll
    for (int kk = 0; kk < 8; kk++) {
        aQ[kk][0] = __float_as_uint(sm[A_QS + lr0 * QPAD + kk * 8 + t]);
        aQ[kk][1] = __float_as_uint(sm[A_QS + (lr0 + 8) * QPAD + kk * 8 + t]);
        aQ[kk][2] = __float_as_uint(sm[A_QS + lr0 * QPAD + kk * 8 + t + 4]);
        aQ[kk][3] = __float_as_uint(sm[A_QS + (lr0 + 8) * QPAD + kk * 8 + t + 4]);
    }

    float o[8][4];
    #pragma unroll
    for (int nf = 0; nf < 8; nf++) { o[nf][0]=0.f; o[nf][1]=0.f; o[nf][2]=0.f; o[nf][3]=0.f; }
    float m0 = -INFINITY, m1 = -INFINITY, l0 = 0.f, l1 = 0.f;
    const int nt = 2 * qt + 2;

    // prefetch key tile 0
    #pragma unroll
    for (int i = 0; i < 4; i++) {
        int idx = tid + i * 256;
        int r = idx >> 4, c = idx & 15;
        cp16(sb + (A_KS + r * KPAD) * 4 + c * 16, Kp + base + (size_t)r * EE + c * 4);
        cp16(sb + (A_VS + r * VPAD) * 4 + c * 16, Vp + base + (size_t)r * EE + c * 4);
    }
    CP_COMMIT();

    for (int kt = 0; kt < nt; kt++) {
        if (kt + 1 < nt) {
            int st = (kt + 1) & 1, kb2 = (kt + 1) * 64;
            #pragma unroll
            for (int i = 0; i < 4; i++) {
                int idx = tid + i * 256;
                int r = idx >> 4, c = idx & 15;
                cp16(sb + (A_KS + st * 64 * KPAD + r * KPAD) * 4 + c * 16,
                     Kp + base + (size_t)(kb2 + r) * EE + c * 4);
                cp16(sb + (A_VS + st * 64 * VPAD + r * VPAD) * 4 + c * 16,
                     Vp + base + (size_t)(kb2 + r) * EE + c * 4);
            }
            CP_COMMIT();
            CP_WAIT(1);
        } else { CP_WAIT(0); }
        __syncthreads();

        const int ktb = kt * 64;
        if (ktb <= qbase + wid * 16 + 15) {          // warp has unmasked rows
            const float* Ks = sm + A_KS + (kt & 1) * 64 * KPAD;
            const float* Vs = sm + A_VS + (kt & 1) * 64 * VPAD;

            float s[8][4];
            #pragma unroll
            for (int nf = 0; nf < 8; nf++) { s[nf][0]=0.f; s[nf][1]=0.f; s[nf][2]=0.f; s[nf][3]=0.f; }
            #pragma unroll
            for (int kk = 0; kk < 8; kk++) {
                #pragma unroll
                for (int nf = 0; nf < 8; nf++) {
                    uint32_t bf[2];
                    bf[0] = __float_as_uint(Ks[(nf * 8 + g) * KPAD + kk * 8 + t]);
                    bf[1] = __float_as_uint(Ks[(nf * 8 + g) * KPAD + kk * 8 + t + 4]);
                    mma8(s[nf], aQ[kk], bf);
                }
            }
            const int r0 = qbase + lr0, r1 = r0 + 8;
            if (ktb + 63 > qbase + wid * 16) {       // diagonal tile: mask
                #pragma unroll
                for (int nf = 0; nf < 8; nf++) {
                    int c0 = ktb + nf * 8 + 2 * t;
                    if (c0     > r0) s[nf][0] = -INFINITY;
                    if (c0 + 1 > r0) s[nf][1] = -INFINITY;
                    if (c0     > r1) s[nf][2] = -INFINITY;
                    if (c0 + 1 > r1) s[nf][3] = -INFINITY;
                }
            }
            float mx0 = -INFINITY, mx1 = -INFINITY;
            #pragma unroll
            for (int nf = 0; nf < 8; nf++) {
                mx0 = fmaxf(mx0, fmaxf(s[nf][0], s[nf][1]));
                mx1 = fmaxf(mx1, fmaxf(s[nf][2], s[nf][3]));
            }
            mx0 = fmaxf(mx0, __shfl_xor_sync(0xffffffffu, mx0, 1));
            mx0 = fmaxf(mx0, __shfl_xor_sync(0xffffffffu, mx0, 2));
            mx1 = fmaxf(mx1, __shfl_xor_sync(0xffffffffu, mx1, 1));
            mx1 = fmaxf(mx1, __shfl_xor_sync(0xffffffffu, mx1, 2));
            float nm0 = fmaxf(m0, mx0), nm1 = fmaxf(m1, mx1);
            float scl0 = exp2f(m0 - nm0), scl1 = exp2f(m1 - nm1);

            float* Ps = sm + A_QS;
            float ls0 = 0.f, ls1 = 0.f;
            #pragma unroll
            for (int nf = 0; nf < 8; nf++) {
                float p0 = tf32r(exp2f(s[nf][0] - nm0));
                float p1 = tf32r(exp2f(s[nf][1] - nm0));
                float p2 = tf32r(exp2f(s[nf][2] - nm1));
                float p3 = tf32r(exp2f(s[nf][3] - nm1));
                ls0 += p0 + p1; ls1 += p2 + p3;
                float2 w0; w0.x = p0; w0.y = p1;
                float2 w1; w1.x = p2; w1.y = p3;
                *(float2*)&Ps[lr0 * QPAD + nf * 8 + 2 * t] = w0;
                *(float2*)&Ps[(lr0 + 8) * QPAD + nf * 8 + 2 * t] = w1;
            }
            ls0 += __shfl_xor_sync(0xffffffffu, ls0, 1);
            ls0 += __shfl_xor_sync(0xffffffffu, ls0, 2);
            ls1 += __shfl_xor_sync(0xffffffffu, ls1, 1);
            ls1 += __shfl_xor_sync(0xffffffffu, ls1, 2);
            l0 = l0 * scl0 + ls0; l1 = l1 * scl1 + ls1;
            #pragma unroll
            for (int nf = 0; nf < 8; nf++) {
                o[nf][0] *= scl0; o[nf][1] *= scl0; o[nf][2] *= scl1; o[nf][3] *= scl1;
            }
            __syncwarp();
            #pragma unroll
            for (int kk = 0; kk < 8; kk++) {
                uint32_t ap[4];
                ap[0] = __float_as_uint(Ps[lr0 * QPAD + kk * 8 + t]);
                ap[1] = __float_as_uint(Ps[(lr0 + 8) * QPAD + kk * 8 + t]);
                ap[2] = __float_as_uint(Ps[lr0 * QPAD + kk * 8 + t + 4]);
                ap[3] = __float_as_uint(Ps[(lr0 + 8) * QPAD + kk * 8 + t + 4]);
                #pragma unroll
                for (int nf = 0; nf < 8; nf++) {
                    uint32_t bf[2];
                    bf[0] = __float_as_uint(Vs[(kk * 8 + t) * VPAD + nf * 8 + g]);
                    bf[1] = __float_as_uint(Vs[(kk * 8 + t + 4) * VPAD + nf * 8 + g]);
                    mma8(o[nf], ap, bf);
                }
            }
            m0 = nm0; m1 = nm1;
        }
        __syncthreads();
    }

    float inv0 = 1.f / l0, inv1 = 1.f / l1;
    #pragma unroll
    for (int nf = 0; nf < 8; nf++) {
        int c = nf * 8 + 2 * t;
        float2 w;
        w.x = tf32r(o[nf][0] * inv0); w.y = tf32r(o[nf][1] * inv0);
        *(float2*)(O + base + (size_t)(qbase + lr0) * EE + c) = w;
        w.x = tf32r(o[nf][2] * inv1); w.y = tf32r(o[nf][3] * inv1);
        *(float2*)(O + base + (size_t)(qbase + lr0 + 8) * EE + c) = w;
    }
}

// ---------------- launch ------------------------------------------------------
extern "C" void kernel_launch(void* const* d_in, const int* in_sizes, int n_in,
                              void* d_out, int out_size)
{
    const int*   ids   = (const int*)  d_in[0];
    const float* wte   = (const float*)d_in[1];
    const float* wpe   = (const float*)d_in[2];
    const float* wq    = (const float*)d_in[3];
    const float* wk    = (const float*)d_in[4];
    const float* wv    = (const float*)d_in[5];
    const float* bq    = (const float*)d_in[6];
    const float* bk    = (const float*)d_in[7];
    const float* bv    = (const float*)d_in[8];
    const float* wproj = (const float*)d_in[9];
    const float* bproj = (const float*)d_in[10];
    const float* ln1g  = (const float*)d_in[11];
    const float* ln1b  = (const float*)d_in[12];
    const float* ln2g  = (const float*)d_in[13];
    const float* ln2b  = (const float*)d_in[14];
    const float* wfc   = (const float*)d_in[15];
    const float* bfc   = (const float*)d_in[16];
    const float* wout  = (const float*)d_in[17];
    const float* bout  = (const float*)d_in[18];
    float* out = (float*)d_out;

    float *x, *h, *q, *k, *v, *o, *x2, *mb;
    float *wtq, *wtk, *wtv, *wtp, *wtfc, *wtout;
    cudaGetSymbolAddress((void**)&x,  g_x);
    cudaGetSymbolAddress((void**)&h,  g_h);
    cudaGetSymbolAddress((void**)&q,  g_q);
    cudaGetSymbolAddress((void**)&k,  g_k);
    cudaGetSymbolAddress((void**)&v,  g_v);
    cudaGetSymbolAddress((void**)&o,  g_o);
    cudaGetSymbolAddress((void**)&x2, g_x2);
    cudaGetSymbolAddress((void**)&mb, g_m);
    cudaGetSymbolAddress((void**)&wtq,  g_wtq);
    cudaGetSymbolAddress((void**)&wtk,  g_wtk);
    cudaGetSymbolAddress((void**)&wtv,  g_wtv);
    cudaGetSymbolAddress((void**)&wtp,  g_wtp);
    cudaGetSymbolAddress((void**)&wtfc, g_wtfc);
    cudaGetSymbolAddress((void**)&wtout,g_wtout);

    cudaFuncSetAttribute(attn_tc, cudaFuncAttributeMaxDynamicSharedMemorySize, ATT_SMEM);
    cudaFuncSetAttribute(tc_gemm<false,false,false>, cudaFuncAttributeMaxDynamicSharedMemorySize, GSMEM);
    cudaFuncSetAttribute(tc_gemm<false,false,true>,  cudaFuncAttributeMaxDynamicSharedMemorySize, GSMEM);
    cudaFuncSetAttribute(tc_gemm<false,true,false>,  cudaFuncAttributeMaxDynamicSharedMemorySize, GSMEM);
    cudaFuncSetAttribute(tc_gemm<true,false,false>,  cudaFuncAttributeMaxDynamicSharedMemorySize, GSMEM);

    dim3 tb(32, 8);
    transpose_qkv_kernel<<<dim3(2, 32, 16), tb>>>(wq, wtq);
    transpose_qkv_kernel<<<dim3(2, 32, 16), tb>>>(wk, wtk);
    transpose_qkv_kernel<<<dim3(2, 32, 16), tb>>>(wv, wtv);
    transpose_kernel<<<dim3(32, 32),  tb>>>(wproj, wtp,  EE, EE);
    transpose_kernel<<<dim3(128, 32), tb>>>(wfc,   wtfc, EE, FF);
    transpose_kernel<<<dim3(32, 128), tb>>>(wout,  wtout, FF, EE);

    // 1. embed
    embed_kernel<<<(MM * EE / 4) / 256, 256>>>(ids, wte, wpe, x);
    // 2. ln1
    ln_kernel<<<MM, 256>>>(x, ln1g, ln1b, h);
    // 3. qkv projections (k, v tf32-rounded for attention MMAs)
    dim3 g1(EE / 128, MM / 128);
    tc_gemm<false,false,false><<<g1, 256, GSMEM>>>(h, wtq, bq, nullptr, q, MM, EE, EE);
    tc_gemm<false,false,true ><<<g1, 256, GSMEM>>>(h, wtk, bk, nullptr, k, MM, EE, EE);
    tc_gemm<false,false,true ><<<g1, 256, GSMEM>>>(h, wtv, bv, nullptr, v, MM, EE, EE);
    // 4. causal flash attention (tensor cores)
    attn_tc<<<dim3(TT / 128, HH, BB), 256, ATT_SMEM>>>(q, k, v, o);
    // 5. proj + residual -> x2
    tc_gemm<false,true,false><<<g1, 256, GSMEM>>>(o, wtp, bproj, x, x2, MM, EE, EE);
    // 6. ln2
    ln_kernel<<<MM, 256>>>(x2, ln2g, ln2b, h);
    // 7. fc + gelu -> m
    dim3 g2(FF / 128, MM / 128);
    tc_gemm<true,false,false><<<g2, 256, GSMEM>>>(h, wtfc, bfc, nullptr, mb, MM, FF, EE);
    // 8. out proj + residual -> d_out
    tc_gemm<false,true,false><<<g1, 256, GSMEM>>>(mb, wtout, bout, x2, out, MM, EE, FF);
}

// round 6
// speedup vs baseline: 4.0214x; 1.0968x over previous
#include <cuda_runtime.h>
#include <cuda_bf16.h>
#include <math.h>
#include <stdint.h>

// Problem constants
#define BB 4
#define TT 2048
#define EE 1024
#define HH 16
#define DD 64
#define MM (BB*TT)        // 8192
#define FF (4*EE)         // 4096

// ---------------- scratch (device globals; no allocation allowed) -------------
__device__ float g_x [MM*EE];
__device__ float g_h [MM*EE];
__device__ float g_q [MM*EE];
__device__ float g_k [MM*EE];
__device__ float g_v [MM*EE];
__device__ float g_o [MM*EE];
__device__ float g_x2[MM*EE];
__device__ float g_m [(size_t)MM*FF];
// pre-transposed weights (K-major, [N,K] row-major, tf32-rounded)
__device__ float g_wtq [EE*EE];
__device__ float g_wtk [EE*EE];
__device__ float g_wtv [EE*EE];
__device__ float g_wtp [EE*EE];
__device__ float g_wtfc [(size_t)FF*EE];
__device__ float g_wtout[(size_t)EE*FF];

// ---------------- helpers -----------------------------------------------------
__device__ __forceinline__ uint32_t smem_u32(const void* p) {
    uint32_t a;
    asm("{ .reg .u64 t; cvta.to.shared.u64 t, %1; cvt.u32.u64 %0, t; }" : "=r"(a) : "l"(p));
    return a;
}
__device__ __forceinline__ float tf32r(float x) {
    uint32_t u;
    asm("cvt.rna.tf32.f32 %0, %1;" : "=r"(u) : "f"(x));
    return __uint_as_float(u);
}
__device__ __forceinline__ void cp16(uint32_t dst, const void* src) {
    asm volatile("cp.async.cg.shared.global [%0], [%1], 16;" :: "r"(dst), "l"(src));
}
#define CP_COMMIT() asm volatile("cp.async.commit_group;" ::: "memory")
#define CP_WAIT(n)  asm volatile("cp.async.wait_group %0;" :: "n"(n) : "memory")

// mma.sync m16n8k8 tf32 (base-target instruction, works on sm_103)
__device__ __forceinline__ void mma8(float* d, const uint32_t* a, const uint32_t* b) {
    asm volatile("mma.sync.aligned.m16n8k8.row.col.f32.tf32.tf32.f32 "
        "{%0,%1,%2,%3}, {%4,%5,%6,%7}, {%8,%9}, {%0,%1,%2,%3};"
        : "+f"(d[0]), "+f"(d[1]), "+f"(d[2]), "+f"(d[3])
        : "r"(a[0]), "r"(a[1]), "r"(a[2]), "r"(a[3]), "r"(b[0]), "r"(b[1]));
}

// ---------------- embed: x = wte[ids] + wpe ----------------------------------
__global__ __launch_bounds__(256) void embed_kernel(
    const int* __restrict__ ids, const float* __restrict__ wte,
    const float* __restrict__ wpe, float* __restrict__ X)
{
    int i = blockIdx.x * 256 + threadIdx.x;
    int row = i >> 8;
    int c   = i & 255;
    int t   = row & (TT - 1);
    int id  = ids[row];
    float4 a = ((const float4*)wte)[(size_t)id * 256 + c];
    float4 p = ((const float4*)wpe)[(size_t)t  * 256 + c];
    a.x += p.x; a.y += p.y; a.z += p.z; a.w += p.w;
    ((float4*)X)[i] = a;
}

// ---------------- layernorm (output tf32-rounded: feeds GEMM A) ---------------
__global__ __launch_bounds__(256) void ln_kernel(
    const float* __restrict__ X, const float* __restrict__ G,
    const float* __restrict__ Bt, float* __restrict__ Y)
{
    __shared__ float red[16];
    int row = blockIdx.x, tid = threadIdx.x;
    const float4* x4 = (const float4*)(X + ((size_t)row << 10));
    float4 a = x4[tid];
    float s  = a.x + a.y + a.z + a.w;
    float sq = a.x*a.x + a.y*a.y + a.z*a.z + a.w*a.w;
    #pragma unroll
    for (int o = 16; o; o >>= 1) {
        s  += __shfl_xor_sync(0xffffffffu, s,  o);
        sq += __shfl_xor_sync(0xffffffffu, sq, o);
    }
    if ((tid & 31) == 0) { red[tid >> 5] = s; red[8 + (tid >> 5)] = sq; }
    __syncthreads();
    float ts = 0.f, tq = 0.f;
    #pragma unroll
    for (int i = 0; i < 8; i++) { ts += red[i]; tq += red[8 + i]; }
    float mean = ts * (1.f / 1024.f);
    float var  = tq * (1.f / 1024.f) - mean * mean;
    float inv  = rsqrtf(var + 1e-5f);
    float4 g4 = ((const float4*)G)[tid];
    float4 b4 = ((const float4*)Bt)[tid];
    float4 o;
    o.x = tf32r((a.x - mean) * inv * g4.x + b4.x);
    o.y = tf32r((a.y - mean) * inv * g4.y + b4.y);
    o.z = tf32r((a.z - mean) * inv * g4.z + b4.z);
    o.w = tf32r((a.w - mean) * inv * g4.w + b4.w);
    ((float4*)(Y + ((size_t)row << 10)))[tid] = o;
}

// ---------------- weight transposes (tf32-rounded) -----------------------------
__global__ __launch_bounds__(256) void transpose_kernel(
    const float* __restrict__ W, float* __restrict__ Wt, int K, int N)
{
    __shared__ float t[32][33];
    int tx = threadIdx.x, ty = threadIdx.y;
    int k0 = blockIdx.y * 32, n0 = blockIdx.x * 32;
    #pragma unroll
    for (int i = ty; i < 32; i += 8) t[i][tx] = W[(size_t)(k0 + i) * N + n0 + tx];
    __syncthreads();
    #pragma unroll
    for (int i = ty; i < 32; i += 8)
        Wt[(size_t)(n0 + i) * K + k0 + tx] = tf32r(t[tx][i]);
}
__global__ __launch_bounds__(256) void transpose_qkv_kernel(
    const float* __restrict__ W, float* __restrict__ Wt)
{
    __shared__ float t[32][33];
    int tx = threadIdx.x, ty = threadIdx.y;
    int h = blockIdx.z, k0 = blockIdx.y * 32, d0 = blockIdx.x * 32;
    const float* Wh = W + (size_t)h * EE * DD;
    #pragma unroll
    for (int i = ty; i < 32; i += 8) t[i][tx] = Wh[(size_t)(k0 + i) * DD + d0 + tx];
    __syncthreads();
    #pragma unroll
    for (int i = ty; i < 32; i += 8)
        Wt[(size_t)(h * DD + d0 + i) * EE + k0 + tx] = tf32r(t[tx][i]);
}

// ---------------- mma.sync tf32 GEMM (persistent, warp tile 64x64) ------------
// C[M,N] = act(A[M,K] @ Wt[N,K]^T + bias [+ R])
// CTA 128x128, BK=32, 3-stage cp.async. 128 threads = 4 warps in 2(m)x2(n),
// warp tile 64x64 via m16n8k8 (4 m-frags x 8 n-frags): 1.0 LDS.32 per MMA.
// Persistent grid (2 CTAs/SM) strides over output tiles (no wave tails).
#define GPAD  36
#define GSTGF (2*128*GPAD)
#define GSTGB (GSTGF*4)
#define GSMEM (3*GSTGB)
#define GEMM_GRID 296

__device__ __forceinline__ void gcp_stage(
    uint32_t sbase, int s, const float* __restrict__ A, const float* __restrict__ Wt,
    int bm, int bn, int K, int k0, int tid)
{
    uint32_t sA = sbase + s * GSTGB;
    uint32_t sB = sA + 128 * GPAD * 4;
    #pragma unroll
    for (int e = 0; e < 8; e++) {
        int lin = tid + 128 * e;           // 0..1023
        int r = lin >> 3, c = lin & 7;
        cp16(sA + r * (GPAD*4) + c * 16, A  + (size_t)(bm + r) * K + k0 + c * 4);
        cp16(sB + r * (GPAD*4) + c * 16, Wt + (size_t)(bn + r) * K + k0 + c * 4);
    }
}

template<bool GELU_, bool RES, bool TF32OUT>
__global__ __launch_bounds__(128) void tc_gemm(
    const float* __restrict__ A, const float* __restrict__ Wt,
    const float* __restrict__ bias, const float* __restrict__ Rp,
    float* __restrict__ C, int M, int N, int K)
{
    extern __shared__ __align__(16) float smf[];
    uint32_t sbase = smem_u32(smf);
    const int tid = threadIdx.x, wid = tid >> 5, lid = tid & 31;
    const int g = lid >> 2, t = lid & 3;
    const int warp_m = (wid & 1) * 64, warp_n = (wid >> 1) * 64;
    const int NT = K >> 5;
    const int mtiles = M >> 7;
    const int total = mtiles * (N >> 7);

    for (int tile = blockIdx.x; tile < total; tile += gridDim.x) {
        const int bm = (tile % mtiles) * 128;
        const int bn = (tile / mtiles) * 128;

        float d[4][8][4];
        #pragma unroll
        for (int i = 0; i < 4; i++)
            #pragma unroll
            for (int j = 0; j < 8; j++)
                #pragma unroll
                for (int p = 0; p < 4; p++) d[i][j][p] = 0.f;

        gcp_stage(sbase, 0, A, Wt, bm, bn, K, 0,  tid); CP_COMMIT();
        gcp_stage(sbase, 1, A, Wt, bm, bn, K, 32, tid); CP_COMMIT();

        for (int kt = 0; kt < NT; kt++) {
            if (kt == NT - 1) { CP_WAIT(0); } else { CP_WAIT(1); }
            __syncthreads();
            if (kt + 2 < NT) {
                gcp_stage(sbase, (kt + 2) % 3, A, Wt, bm, bn, K, (kt + 2) * 32, tid);
                CP_COMMIT();
            }
            const float* As = smf + (size_t)((kt % 3)) * GSTGF;
            const float* Bs = As + 128 * GPAD;
            #pragma unroll
            for (int k8 = 0; k8 < 4; k8++) {
                int kc = k8 * 8 + t;
                uint32_t af[4][4], bf[8][2];
                #pragma unroll
                for (int mf = 0; mf < 4; mf++) {
                    int rm = warp_m + mf * 16 + g;
                    af[mf][0] = __float_as_uint(As[rm * GPAD + kc]);
                    af[mf][1] = __float_as_uint(As[(rm + 8) * GPAD + kc]);
                    af[mf][2] = __float_as_uint(As[rm * GPAD + kc + 4]);
                    af[mf][3] = __float_as_uint(As[(rm + 8) * GPAD + kc + 4]);
                }
                #pragma unroll
                for (int nf = 0; nf < 8; nf++) {
                    int rn = warp_n + nf * 8 + g;
                    bf[nf][0] = __float_as_uint(Bs[rn * GPAD + kc]);
                    bf[nf][1] = __float_as_uint(Bs[rn * GPAD + kc + 4]);
                }
                #pragma unroll
                for (int mf = 0; mf < 4; mf++)
                    #pragma unroll
                    for (int nf = 0; nf < 8; nf++)
                        mma8(d[mf][nf], af[mf], bf[nf]);
            }
            __syncthreads();
        }

        // epilogue
        #pragma unroll
        for (int mf = 0; mf < 4; mf++) {
            int row0 = bm + warp_m + mf * 16 + g;
            #pragma unroll
            for (int nf = 0; nf < 8; nf++) {
                int col = bn + warp_n + nf * 8 + 2 * t;
                float b0 = __ldg(bias + col), b1 = __ldg(bias + col + 1);
                #pragma unroll
                for (int p = 0; p < 2; p++) {
                    int m = row0 + p * 8;
                    float v0 = d[mf][nf][2 * p + 0] + b0;
                    float v1 = d[mf][nf][2 * p + 1] + b1;
                    if (GELU_) {
                        v0 = 0.5f * v0 * (1.f + erff(v0 * 0.70710678118654752f));
                        v1 = 0.5f * v1 * (1.f + erff(v1 * 0.70710678118654752f));
                        v0 = tf32r(v0); v1 = tf32r(v1);
                    }
                    if (TF32OUT) { v0 = tf32r(v0); v1 = tf32r(v1); }
                    if (RES) {
                        float2 rr = *(const float2*)(Rp + (size_t)m * N + col);
                        v0 += rr.x; v1 += rr.y;
                    }
                    float2 o; o.x = v0; o.y = v1;
                    *(float2*)(C + (size_t)m * N + col) = o;
                }
            }
        }
        __syncthreads();   // all reads of smem stages done before next tile refills
    }
}

// ---------------- tensor-core flash attention (causal, tf32) ------------------
#define QPAD 68
#define KPAD 68
#define VPAD 72
#define A_QS 0
#define A_KS (128*QPAD)
#define A_VS (A_KS + 2*64*KPAD)
#define A_END (A_VS + 2*64*VPAD)
#define ATT_SMEM (A_END*4)

__global__ __launch_bounds__(256) void attn_tc(
    const float* __restrict__ Q, const float* __restrict__ Kp,
    const float* __restrict__ Vp, float* __restrict__ O)
{
    extern __shared__ __align__(16) float sm[];
    uint32_t sb = smem_u32(sm);
    const int qt = (int)gridDim.x - 1 - (int)blockIdx.x;   // big tiles first
    const int h = blockIdx.y, b = blockIdx.z;
    const int tid = threadIdx.x, wid = tid >> 5, lid = tid & 31;
    const int g = lid >> 2, t = lid & 3;
    const int qbase = qt * 128;
    const size_t base = (size_t)(b * TT) * EE + (size_t)h * DD;
    const float alpha = 0.18033688011112042f;   // 0.125 * log2(e)

    #pragma unroll
    for (int i = 0; i < 8; i++) {
        int idx = tid + i * 256;
        int r = idx >> 4, c = (idx & 15) * 4;
        float4 v4 = *(const float4*)(Q + base + (size_t)(qbase + r) * EE + c);
        v4.x = tf32r(v4.x * alpha); v4.y = tf32r(v4.y * alpha);
        v4.z = tf32r(v4.z * alpha); v4.w = tf32r(v4.w * alpha);
        *(float4*)&sm[A_QS + r * QPAD + c] = v4;
    }
    __syncthreads();

    uint32_t aQ[8][4];
    const int lr0 = wid * 16 + g;
    #pragma unroll
    for (int kk = 0; kk < 8; kk++) {
        aQ[kk][0] = __float_as_uint(sm[A_QS + lr0 * QPAD + kk * 8 + t]);
        aQ[kk][1] = __float_as_uint(sm[A_QS + (lr0 + 8) * QPAD + kk * 8 + t]);
        aQ[kk][2] = __float_as_uint(sm[A_QS + lr0 * QPAD + kk * 8 + t + 4]);
        aQ[kk][3] = __float_as_uint(sm[A_QS + (lr0 + 8) * QPAD + kk * 8 + t + 4]);
    }

    float o[8][4];
    #pragma unroll
    for (int nf = 0; nf < 8; nf++) { o[nf][0]=0.f; o[nf][1]=0.f; o[nf][2]=0.f; o[nf][3]=0.f; }
    float m0 = -INFINITY, m1 = -INFINITY, l0 = 0.f, l1 = 0.f;
    const int nt = 2 * qt + 2;

    #pragma unroll
    for (int i = 0; i < 4; i++) {
        int idx = tid + i * 256;
        int r = idx >> 4, c = idx & 15;
        cp16(sb + (A_KS + r * KPAD) * 4 + c * 16, Kp + base + (size_t)r * EE + c * 4);
        cp16(sb + (A_VS + r * VPAD) * 4 + c * 16, Vp + base + (size_t)r * EE + c * 4);
    }
    CP_COMMIT();

    for (int kt = 0; kt < nt; kt++) {
        if (kt + 1 < nt) {
            int st = (kt + 1) & 1, kb2 = (kt + 1) * 64;
            #pragma unroll
            for (int i = 0; i < 4; i++) {
                int idx = tid + i * 256;
                int r = idx >> 4, c = idx & 15;
                cp16(sb + (A_KS + st * 64 * KPAD + r * KPAD) * 4 + c * 16,
                     Kp + base + (size_t)(kb2 + r) * EE + c * 4);
                cp16(sb + (A_VS + st * 64 * VPAD + r * VPAD) * 4 + c * 16,
                     Vp + base + (size_t)(kb2 + r) * EE + c * 4);
            }
            CP_COMMIT();
            CP_WAIT(1);
        } else { CP_WAIT(0); }
        __syncthreads();

        const int ktb = kt * 64;
        if (ktb <= qbase + wid * 16 + 15) {
            const float* Ks = sm + A_KS + (kt & 1) * 64 * KPAD;
            const float* Vs = sm + A_VS + (kt & 1) * 64 * VPAD;

            float s[8][4];
            #pragma unroll
            for (int nf = 0; nf < 8; nf++) { s[nf][0]=0.f; s[nf][1]=0.f; s[nf][2]=0.f; s[nf][3]=0.f; }
            #pragma unroll
            for (int kk = 0; kk < 8; kk++) {
                #pragma unroll
                for (int nf = 0; nf < 8; nf++) {
                    uint32_t bf[2];
                    bf[0] = __float_as_uint(Ks[(nf * 8 + g) * KPAD + kk * 8 + t]);
                    bf[1] = __float_as_uint(Ks[(nf * 8 + g) * KPAD + kk * 8 + t + 4]);
                    mma8(s[nf], aQ[kk], bf);
                }
            }
            const int r0 = qbase + lr0, r1 = r0 + 8;
            if (ktb + 63 > qbase + wid * 16) {
                #pragma unroll
                for (int nf = 0; nf < 8; nf++) {
                    int c0 = ktb + nf * 8 + 2 * t;
                    if (c0     > r0) s[nf][0] = -INFINITY;
                    if (c0 + 1 > r0) s[nf][1] = -INFINITY;
                    if (c0     > r1) s[nf][2] = -INFINITY;
                    if (c0 + 1 > r1) s[nf][3] = -INFINITY;
                }
            }
            float mx0 = -INFINITY, mx1 = -INFINITY;
            #pragma unroll
            for (int nf = 0; nf < 8; nf++) {
                mx0 = fmaxf(mx0, fmaxf(s[nf][0], s[nf][1]));
                mx1 = fmaxf(mx1, fmaxf(s[nf][2], s[nf][3]));
            }
            mx0 = fmaxf(mx0, __shfl_xor_sync(0xffffffffu, mx0, 1));
            mx0 = fmaxf(mx0, __shfl_xor_sync(0xffffffffu, mx0, 2));
            mx1 = fmaxf(mx1, __shfl_xor_sync(0xffffffffu, mx1, 1));
            mx1 = fmaxf(mx1, __shfl_xor_sync(0xffffffffu, mx1, 2));
            float nm0 = fmaxf(m0, mx0), nm1 = fmaxf(m1, mx1);
            float scl0 = exp2f(m0 - nm0), scl1 = exp2f(m1 - nm1);

            float* Ps = sm + A_QS;
            float ls0 = 0.f, ls1 = 0.f;
            #pragma unroll
            for (int nf = 0; nf < 8; nf++) {
                float p0 = tf32r(exp2f(s[nf][0] - nm0));
                float p1 = tf32r(exp2f(s[nf][1] - nm0));
                float p2 = tf32r(exp2f(s[nf][2] - nm1));
                float p3 = tf32r(exp2f(s[nf][3] - nm1));
                ls0 += p0 + p1; ls1 += p2 + p3;
                float2 w0; w0.x = p0; w0.y = p1;
                float2 w1; w1.x = p2; w1.y = p3;
                *(float2*)&Ps[lr0 * QPAD + nf * 8 + 2 * t] = w0;
                *(float2*)&Ps[(lr0 + 8) * QPAD + nf * 8 + 2 * t] = w1;
            }
            ls0 += __shfl_xor_sync(0xffffffffu, ls0, 1);
            ls0 += __shfl_xor_sync(0xffffffffu, ls0, 2);
            ls1 += __shfl_xor_sync(0xffffffffu, ls1, 1);
            ls1 += __shfl_xor_sync(0xffffffffu, ls1, 2);
            l0 = l0 * scl0 + ls0; l1 = l1 * scl1 + ls1;
            #pragma unroll
            for (int nf = 0; nf < 8; nf++) {
                o[nf][0] *= scl0; o[nf][1] *= scl0; o[nf][2] *= scl1; o[nf][3] *= scl1;
            }
            __syncwarp();
            #pragma unroll
            for (int kk = 0; kk < 8; kk++) {
                uint32_t ap[4];
                ap[0] = __float_as_uint(Ps[lr0 * QPAD + kk * 8 + t]);
                ap[1] = __float_as_uint(Ps[(lr0 + 8) * QPAD + kk * 8 + t]);
                ap[2] = __float_as_uint(Ps[lr0 * QPAD + kk * 8 + t + 4]);
                ap[3] = __float_as_uint(Ps[(lr0 + 8) * QPAD + kk * 8 + t + 4]);
                #pragma unroll
                for (int nf = 0; nf < 8; nf++) {
                    uint32_t bf[2];
                    bf[0] = __float_as_uint(Vs[(kk * 8 + t) * VPAD + nf * 8 + g]);
                    bf[1] = __float_as_uint(Vs[(kk * 8 + t + 4) * VPAD + nf * 8 + g]);
                    mma8(o[nf], ap, bf);
                }
            }
            m0 = nm0; m1 = nm1;
        }
        __syncthreads();
    }

    float inv0 = 1.f / l0, inv1 = 1.f / l1;
    #pragma unroll
    for (int nf = 0; nf < 8; nf++) {
        int c = nf * 8 + 2 * t;
        float2 w;
        w.x = tf32r(o[nf][0] * inv0); w.y = tf32r(o[nf][1] * inv0);
        *(float2*)(O + base + (size_t)(qbase + lr0) * EE + c) = w;
        w.x = tf32r(o[nf][2] * inv1); w.y = tf32r(o[nf][3] * inv1);
        *(float2*)(O + base + (size_t)(qbase + lr0 + 8) * EE + c) = w;
    }
}

// ---------------- launch ------------------------------------------------------
extern "C" void kernel_launch(void* const* d_in, const int* in_sizes, int n_in,
                              void* d_out, int out_size)
{
    const int*   ids   = (const int*)  d_in[0];
    const float* wte   = (const float*)d_in[1];
    const float* wpe   = (const float*)d_in[2];
    const float* wq    = (const float*)d_in[3];
    const float* wk    = (const float*)d_in[4];
    const float* wv    = (const float*)d_in[5];
    const float* bq    = (const float*)d_in[6];
    const float* bk    = (const float*)d_in[7];
    const float* bv    = (const float*)d_in[8];
    const float* wproj = (const float*)d_in[9];
    const float* bproj = (const float*)d_in[10];
    const float* ln1g  = (const float*)d_in[11];
    const float* ln1b  = (const float*)d_in[12];
    const float* ln2g  = (const float*)d_in[13];
    const float* ln2b  = (const float*)d_in[14];
    const float* wfc   = (const float*)d_in[15];
    const float* bfc   = (const float*)d_in[16];
    const float* wout  = (const float*)d_in[17];
    const float* bout  = (const float*)d_in[18];
    float* out = (float*)d_out;

    float *x, *h, *q, *k, *v, *o, *x2, *mb;
    float *wtq, *wtk, *wtv, *wtp, *wtfc, *wtout;
    cudaGetSymbolAddress((void**)&x,  g_x);
    cudaGetSymbolAddress((void**)&h,  g_h);
    cudaGetSymbolAddress((void**)&q,  g_q);
    cudaGetSymbolAddress((void**)&k,  g_k);
    cudaGetSymbolAddress((void**)&v,  g_v);
    cudaGetSymbolAddress((void**)&o,  g_o);
    cudaGetSymbolAddress((void**)&x2, g_x2);
    cudaGetSymbolAddress((void**)&mb, g_m);
    cudaGetSymbolAddress((void**)&wtq,  g_wtq);
    cudaGetSymbolAddress((void**)&wtk,  g_wtk);
    cudaGetSymbolAddress((void**)&wtv,  g_wtv);
    cudaGetSymbolAddress((void**)&wtp,  g_wtp);
    cudaGetSymbolAddress((void**)&wtfc, g_wtfc);
    cudaGetSymbolAddress((void**)&wtout,g_wtout);

    cudaFuncSetAttribute(attn_tc, cudaFuncAttributeMaxDynamicSharedMemorySize, ATT_SMEM);
    cudaFuncSetAttribute(tc_gemm<false,false,false>, cudaFuncAttributeMaxDynamicSharedMemorySize, GSMEM);
    cudaFuncSetAttribute(tc_gemm<false,false,true>,  cudaFuncAttributeMaxDynamicSharedMemorySize, GSMEM);
    cudaFuncSetAttribute(tc_gemm<false,true,false>,  cudaFuncAttributeMaxDynamicSharedMemorySize, GSMEM);
    cudaFuncSetAttribute(tc_gemm<true,false,false>,  cudaFuncAttributeMaxDynamicSharedMemorySize, GSMEM);

    dim3 tb(32, 8);
    transpose_qkv_kernel<<<dim3(2, 32, 16), tb>>>(wq, wtq);
    transpose_qkv_kernel<<<dim3(2, 32, 16), tb>>>(wk, wtk);
    transpose_qkv_kernel<<<dim3(2, 32, 16), tb>>>(wv, wtv);
    transpose_kernel<<<dim3(32, 32),  tb>>>(wproj, wtp,  EE, EE);
    transpose_kernel<<<dim3(128, 32), tb>>>(wfc,   wtfc, EE, FF);
    transpose_kernel<<<dim3(32, 128), tb>>>(wout,  wtout, FF, EE);

    // 1. embed
    embed_kernel<<<(MM * EE / 4) / 256, 256>>>(ids, wte, wpe, x);
    // 2. ln1
    ln_kernel<<<MM, 256>>>(x, ln1g, ln1b, h);
    // 3. qkv projections (k, v tf32-rounded for attention MMAs)
    tc_gemm<false,false,false><<<GEMM_GRID, 128, GSMEM>>>(h, wtq, bq, nullptr, q, MM, EE, EE);
    tc_gemm<false,false,true ><<<GEMM_GRID, 128, GSMEM>>>(h, wtk, bk, nullptr, k, MM, EE, EE);
    tc_gemm<false,false,true ><<<GEMM_GRID, 128, GSMEM>>>(h, wtv, bv, nullptr, v, MM, EE, EE);
    // 4. causal flash attention (tensor cores)
    attn_tc<<<dim3(TT / 128, HH, BB), 256, ATT_SMEM>>>(q, k, v, o);
    // 5. proj + residual -> x2
    tc_gemm<false,true,false><<<GEMM_GRID, 128, GSMEM>>>(o, wtp, bproj, x, x2, MM, EE, EE);
    // 6. ln2
    ln_kernel<<<MM, 256>>>(x2, ln2g, ln2b, h);
    // 7. fc + gelu -> m
    tc_gemm<true,false,false><<<GEMM_GRID, 128, GSMEM>>>(h, wtfc, bfc, nullptr, mb, MM, FF, EE);
    // 8. out proj + residual -> d_out
    tc_gemm<false,true,false><<<GEMM_GRID, 128, GSMEM>>>(mb, wtout, bout, x2, out, MM, EE, FF);
}

// round 7
// speedup vs baseline: 7.4374x; 1.8495x over previous
#include <cuda_runtime.h>
#include <cuda_fp16.h>
#include <math.h>
#include <stdint.h>

// Problem constants
#define BB 4
#define TT 2048
#define EE 1024
#define HH 16
#define DD 64
#define MM (BB*TT)        // 8192
#define FF (4*EE)         // 4096

// ---------------- scratch (device globals; no allocation allowed) -------------
__device__ float  g_x [MM*EE];               // residual stream (fp32)
__device__ float  g_x2[MM*EE];
__device__ __half g_h [MM*EE];               // LN output (GEMM A)
__device__ __half g_q [MM*EE];               // q (pre-scaled by alpha)
__device__ __half g_k [MM*EE];
__device__ __half g_v [MM*EE];
__device__ __half g_o [MM*EE];               // attention output
__device__ __half g_m [(size_t)MM*FF];       // gelu(fc)
// pre-transposed weights (K-major [N,K], fp16)
__device__ __half g_wtq [EE*EE];
__device__ __half g_wtk [EE*EE];
__device__ __half g_wtv [EE*EE];
__device__ __half g_wtp [EE*EE];
__device__ __half g_wtfc [(size_t)FF*EE];
__device__ __half g_wtout[(size_t)EE*FF];

// ---------------- helpers -----------------------------------------------------
__device__ __forceinline__ uint32_t smem_u32(const void* p) {
    uint32_t a;
    asm("{ .reg .u64 t; cvta.to.shared.u64 t, %1; cvt.u32.u64 %0, t; }" : "=r"(a) : "l"(p));
    return a;
}
__device__ __forceinline__ void cp16(uint32_t dst, const void* src) {
    asm volatile("cp.async.cg.shared.global [%0], [%1], 16;" :: "r"(dst), "l"(src));
}
#define CP_COMMIT() asm volatile("cp.async.commit_group;" ::: "memory")
#define CP_WAIT(n)  asm volatile("cp.async.wait_group %0;" :: "n"(n) : "memory")

// mma.sync m16n8k16 fp16 inputs, fp32 accumulate (sm_80+ base-target)
__device__ __forceinline__ void mma16(float* d, const uint32_t* a, const uint32_t* b) {
    asm volatile("mma.sync.aligned.m16n8k16.row.col.f32.f16.f16.f32 "
        "{%0,%1,%2,%3}, {%4,%5,%6,%7}, {%8,%9}, {%0,%1,%2,%3};"
        : "+f"(d[0]), "+f"(d[1]), "+f"(d[2]), "+f"(d[3])
        : "r"(a[0]), "r"(a[1]), "r"(a[2]), "r"(a[3]), "r"(b[0]), "r"(b[1]));
}
__device__ __forceinline__ void ldmx4t(uint32_t& r0, uint32_t& r1, uint32_t& r2,
                                       uint32_t& r3, uint32_t addr) {
    asm volatile("ldmatrix.sync.aligned.m8n8.x4.trans.shared.b16 {%0,%1,%2,%3}, [%4];"
        : "=r"(r0), "=r"(r1), "=r"(r2), "=r"(r3) : "r"(addr));
}

// ---------------- embed: x = wte[ids] + wpe ----------------------------------
__global__ __launch_bounds__(256) void embed_kernel(
    const int* __restrict__ ids, const float* __restrict__ wte,
    const float* __restrict__ wpe, float* __restrict__ X)
{
    int i = blockIdx.x * 256 + threadIdx.x;
    int row = i >> 8;
    int c   = i & 255;
    int t   = row & (TT - 1);
    int id  = ids[row];
    float4 a = ((const float4*)wte)[(size_t)id * 256 + c];
    float4 p = ((const float4*)wpe)[(size_t)t  * 256 + c];
    a.x += p.x; a.y += p.y; a.z += p.z; a.w += p.w;
    ((float4*)X)[i] = a;
}

// ---------------- layernorm (fp32 in, fp16 out) -------------------------------
__global__ __launch_bounds__(256) void ln_kernel(
    const float* __restrict__ X, const float* __restrict__ G,
    const float* __restrict__ Bt, __half* __restrict__ Y)
{
    __shared__ float red[16];
    int row = blockIdx.x, tid = threadIdx.x;
    const float4* x4 = (const float4*)(X + ((size_t)row << 10));
    float4 a = x4[tid];
    float s  = a.x + a.y + a.z + a.w;
    float sq = a.x*a.x + a.y*a.y + a.z*a.z + a.w*a.w;
    #pragma unroll
    for (int o = 16; o; o >>= 1) {
        s  += __shfl_xor_sync(0xffffffffu, s,  o);
        sq += __shfl_xor_sync(0xffffffffu, sq, o);
    }
    if ((tid & 31) == 0) { red[tid >> 5] = s; red[8 + (tid >> 5)] = sq; }
    __syncthreads();
    float ts = 0.f, tq = 0.f;
    #pragma unroll
    for (int i = 0; i < 8; i++) { ts += red[i]; tq += red[8 + i]; }
    float mean = ts * (1.f / 1024.f);
    float var  = tq * (1.f / 1024.f) - mean * mean;
    float inv  = rsqrtf(var + 1e-5f);
    float4 g4 = ((const float4*)G)[tid];
    float4 b4 = ((const float4*)Bt)[tid];
    __half2 h01 = __floats2half2_rn((a.x - mean) * inv * g4.x + b4.x,
                                    (a.y - mean) * inv * g4.y + b4.y);
    __half2 h23 = __floats2half2_rn((a.z - mean) * inv * g4.z + b4.z,
                                    (a.w - mean) * inv * g4.w + b4.w);
    uint2 o; o.x = *(uint32_t*)&h01; o.y = *(uint32_t*)&h23;
    ((uint2*)(Y + ((size_t)row << 10)))[tid] = o;
}

// ---------------- weight transposes (fp32 -> fp16, K-major) -------------------
__global__ __launch_bounds__(256) void transpose_kernel(
    const float* __restrict__ W, __half* __restrict__ Wt, int K, int N)
{
    __shared__ float t[32][33];
    int tx = threadIdx.x, ty = threadIdx.y;
    int k0 = blockIdx.y * 32, n0 = blockIdx.x * 32;
    #pragma unroll
    for (int i = ty; i < 32; i += 8) t[i][tx] = W[(size_t)(k0 + i) * N + n0 + tx];
    __syncthreads();
    #pragma unroll
    for (int i = ty; i < 32; i += 8)
        Wt[(size_t)(n0 + i) * K + k0 + tx] = __float2half_rn(t[tx][i]);
}
__global__ __launch_bounds__(256) void transpose_qkv_kernel(
    const float* __restrict__ W, __half* __restrict__ Wt)
{
    __shared__ float t[32][33];
    int tx = threadIdx.x, ty = threadIdx.y;
    int h = blockIdx.z, k0 = blockIdx.y * 32, d0 = blockIdx.x * 32;
    const float* Wh = W + (size_t)h * EE * DD;
    #pragma unroll
    for (int i = ty; i < 32; i += 8) t[i][tx] = Wh[(size_t)(k0 + i) * DD + d0 + tx];
    __syncthreads();
    #pragma unroll
    for (int i = ty; i < 32; i += 8)
        Wt[(size_t)(h * DD + d0 + i) * EE + k0 + tx] = __float2half_rn(t[tx][i]);
}

// ---------------- mma.sync fp16 GEMM (persistent, warp tile 64x64) ------------
// C[M,N] = act((A[M,K] @ Wt[N,K]^T + bias) * scale [+ R])
// CTA 128x128, BK=32, 3-stage cp.async; 4 warps (2m x 2n), warp tile 64x64
// via m16n8k16. Row pad 72 halfs (144B): bank = 4*row + t, conflict-free.
#define PADH  72
#define PADB  144
#define GSTGB (256*PADB)       // A(128 rows) + B(128 rows) per stage = 36864B
#define GSMEM (3*GSTGB)
#define GEMM_GRID 296

__device__ __forceinline__ void gcp_stage(
    uint32_t sbase, int s, const __half* __restrict__ A, const __half* __restrict__ Wt,
    int bm, int bn, int K, int k0, int tid)
{
    uint32_t sA = sbase + s * GSTGB;
    uint32_t sB = sA + 128 * PADB;
    #pragma unroll
    for (int e = 0; e < 4; e++) {
        int lin = tid + 128 * e;           // 0..511
        int r = lin >> 2, c = lin & 3;
        cp16(sA + r * PADB + c * 16, A  + (size_t)(bm + r) * K + k0 + c * 8);
        cp16(sB + r * PADB + c * 16, Wt + (size_t)(bn + r) * K + k0 + c * 8);
    }
}

template<bool GELU_, bool RES, bool OUTH>
__global__ __launch_bounds__(128) void tc_gemm(
    const __half* __restrict__ A, const __half* __restrict__ Wt,
    const float* __restrict__ bias, const float* __restrict__ Rp,
    void* __restrict__ Cv, int M, int N, int K, float scale)
{
    extern __shared__ __align__(16) char smc[];
    uint32_t sbase = smem_u32(smc);
    const int tid = threadIdx.x, wid = tid >> 5, lid = tid & 31;
    const int g = lid >> 2, t = lid & 3;
    const int warp_m = (wid & 1) * 64, warp_n = (wid >> 1) * 64;
    const int NT = K >> 5;
    const int mtiles = M >> 7;
    const int total = mtiles * (N >> 7);

    for (int tile = blockIdx.x; tile < total; tile += gridDim.x) {
        const int bm = (tile % mtiles) * 128;
        const int bn = (tile / mtiles) * 128;

        float d[4][8][4];
        #pragma unroll
        for (int i = 0; i < 4; i++)
            #pragma unroll
            for (int j = 0; j < 8; j++)
                #pragma unroll
                for (int p = 0; p < 4; p++) d[i][j][p] = 0.f;

        gcp_stage(sbase, 0, A, Wt, bm, bn, K, 0,  tid); CP_COMMIT();
        gcp_stage(sbase, 1, A, Wt, bm, bn, K, 32, tid); CP_COMMIT();

        for (int kt = 0; kt < NT; kt++) {
            if (kt == NT - 1) { CP_WAIT(0); } else { CP_WAIT(1); }
            __syncthreads();
            if (kt + 2 < NT) {
                gcp_stage(sbase, (kt + 2) % 3, A, Wt, bm, bn, K, (kt + 2) * 32, tid);
                CP_COMMIT();
            }
            const char* As = smc + (size_t)(kt % 3) * GSTGB;
            const char* Bs = As + 128 * PADB;
            #pragma unroll
            for (int ks = 0; ks < 2; ks++) {          // two k16 steps per BK=32
                const int kb = ks * 32 + 4 * t;       // byte offset within row
                uint32_t af[4][4], bf[8][2];
                #pragma unroll
                for (int mf = 0; mf < 4; mf++) {
                    int rm = warp_m + mf * 16 + g;
                    af[mf][0] = *(const uint32_t*)(As + rm * PADB + kb);
                    af[mf][1] = *(const uint32_t*)(As + (rm + 8) * PADB + kb);
                    af[mf][2] = *(const uint32_t*)(As + rm * PADB + kb + 16);
                    af[mf][3] = *(const uint32_t*)(As + (rm + 8) * PADB + kb + 16);
                }
                #pragma unroll
                for (int nf = 0; nf < 8; nf++) {
                    int rn = warp_n + nf * 8 + g;
                    bf[nf][0] = *(const uint32_t*)(Bs + rn * PADB + kb);
                    bf[nf][1] = *(const uint32_t*)(Bs + rn * PADB + kb + 16);
                }
                #pragma unroll
                for (int mf = 0; mf < 4; mf++)
                    #pragma unroll
                    for (int nf = 0; nf < 8; nf++)
                        mma16(d[mf][nf], af[mf], bf[nf]);
            }
            __syncthreads();
        }

        // epilogue
        #pragma unroll
        for (int mf = 0; mf < 4; mf++) {
            int row0 = bm + warp_m + mf * 16 + g;
            #pragma unroll
            for (int nf = 0; nf < 8; nf++) {
                int col = bn + warp_n + nf * 8 + 2 * t;
                float b0 = __ldg(bias + col), b1 = __ldg(bias + col + 1);
                #pragma unroll
                for (int p = 0; p < 2; p++) {
                    int m = row0 + p * 8;
                    float v0 = (d[mf][nf][2 * p + 0] + b0) * scale;
                    float v1 = (d[mf][nf][2 * p + 1] + b1) * scale;
                    if (GELU_) {
                        v0 = 0.5f * v0 * (1.f + erff(v0 * 0.70710678118654752f));
                        v1 = 0.5f * v1 * (1.f + erff(v1 * 0.70710678118654752f));
                    }
                    if (OUTH) {
                        __half2 hp = __floats2half2_rn(v0, v1);
                        *(__half2*)((__half*)Cv + (size_t)m * N + col) = hp;
                    } else {
                        if (RES) {
                            float2 rr = *(const float2*)(Rp + (size_t)m * N + col);
                            v0 += rr.x; v1 += rr.y;
                        }
                        float2 o; o.x = v0; o.y = v1;
                        *(float2*)((float*)Cv + (size_t)m * N + col) = o;
                    }
                }
            }
        }
        __syncthreads();
    }
}

// ---------------- tensor-core flash attention (causal, fp16) ------------------
// CTA: 128 q-rows x (b,h); 8 warps, warp w owns rows 16w..16w+15.
// All tiles padded to 72 halfs (144B rows) -> conflict-free frag accesses.
#define A_QS 0                         // Q tile / P scratch: 128 x 72 halfs
#define A_KS (128*PADH)                // K: 2 x 64 x 72
#define A_VS (A_KS + 2*64*PADH)        // V: 2 x 64 x 72
#define A_ENDH (A_VS + 2*64*PADH)
#define ATT_SMEM (A_ENDH*2)

__global__ __launch_bounds__(256) void attn_tc(
    const __half* __restrict__ Q, const __half* __restrict__ Kp,
    const __half* __restrict__ Vp, __half* __restrict__ O)
{
    extern __shared__ __align__(16) char smc[];
    __half* sm = (__half*)smc;
    uint32_t sb = smem_u32(smc);
    const int qt = (int)gridDim.x - 1 - (int)blockIdx.x;   // big tiles first
    const int h = blockIdx.y, b = blockIdx.z;
    const int tid = threadIdx.x, wid = tid >> 5, lid = tid & 31;
    const int g = lid >> 2, t = lid & 3;
    const int qbase = qt * 128;
    const size_t base = (size_t)(b * TT) * EE + (size_t)h * DD;
    const int lr0 = wid * 16 + g;
    const int nt = 2 * qt + 2;

    // group 0: Q tile (128 rows x 64 halfs = 8 cp16/row)
    #pragma unroll
    for (int i = 0; i < 4; i++) {
        int idx = tid + i * 256;                 // 0..1023
        int r = idx >> 3, c = idx & 7;
        cp16(sb + (A_QS + r * PADH) * 2 + c * 16, Q + base + (size_t)(qbase + r) * EE + c * 8);
    }
    CP_COMMIT();
    // group 1: K/V tile 0 (64 rows x 64 halfs = 8 cp16/row each)
    #pragma unroll
    for (int i = 0; i < 4; i++) {
        int idx = tid + i * 256;
        int r = idx >> 4, c = idx & 7, kv = (idx >> 3) & 1;
        uint32_t dst = kv ? (uint32_t)(A_VS + r * PADH) : (uint32_t)(A_KS + r * PADH);
        const __half* src = kv ? Vp : Kp;
        cp16(sb + dst * 2 + c * 16, src + base + (size_t)r * EE + c * 8);
    }
    CP_COMMIT();

    CP_WAIT(1);            // Q tile resident
    __syncthreads();

    // Q A-fragments -> registers (4 k16 steps x 4 regs)
    uint32_t aQ[4][4];
    {
        const char* Qs = smc + A_QS * 2;
        #pragma unroll
        for (int ks = 0; ks < 4; ks++) {
            int kb = ks * 32 + 4 * t;
            aQ[ks][0] = *(const uint32_t*)(Qs + lr0 * PADB + kb);
            aQ[ks][1] = *(const uint32_t*)(Qs + (lr0 + 8) * PADB + kb);
            aQ[ks][2] = *(const uint32_t*)(Qs + lr0 * PADB + kb + 16);
            aQ[ks][3] = *(const uint32_t*)(Qs + (lr0 + 8) * PADB + kb + 16);
        }
    }
    __syncthreads();

    float o[8][4];
    #pragma unroll
    for (int nf = 0; nf < 8; nf++) { o[nf][0]=0.f; o[nf][1]=0.f; o[nf][2]=0.f; o[nf][3]=0.f; }
    float m0 = -INFINITY, m1 = -INFINITY, l0 = 0.f, l1 = 0.f;

    for (int kt = 0; kt < nt; kt++) {
        if (kt + 1 < nt) {
            int st = (kt + 1) & 1, kb2 = (kt + 1) * 64;
            #pragma unroll
            for (int i = 0; i < 4; i++) {
                int idx = tid + i * 256;
                int r = idx >> 4, c = idx & 7, kv = (idx >> 3) & 1;
                uint32_t dst = kv ? (uint32_t)(A_VS + st * 64 * PADH + r * PADH)
                                  : (uint32_t)(A_KS + st * 64 * PADH + r * PADH);
                const __half* src = kv ? Vp : Kp;
                cp16(sb + dst * 2 + c * 16, src + base + (size_t)(kb2 + r) * EE + c * 8);
            }
            CP_COMMIT();
            CP_WAIT(1);
        } else { CP_WAIT(0); }
        __syncthreads();

        const int ktb = kt * 64;
        if (ktb <= qbase + wid * 16 + 15) {
            const char* Ks = smc + (A_KS + (kt & 1) * 64 * PADH) * 2;
            const uint32_t Vsb = sb + (A_VS + (kt & 1) * 64 * PADH) * 2;

            // S = Q K^T  (4 k16 steps over d=64)
            float s[8][4];
            #pragma unroll
            for (int nf = 0; nf < 8; nf++) { s[nf][0]=0.f; s[nf][1]=0.f; s[nf][2]=0.f; s[nf][3]=0.f; }
            #pragma unroll
            for (int ks = 0; ks < 4; ks++) {
                int kb = ks * 32 + 4 * t;
                #pragma unroll
                for (int nf = 0; nf < 8; nf++) {
                    uint32_t bf[2];
                    const char* kr = Ks + (nf * 8 + g) * PADB + kb;
                    bf[0] = *(const uint32_t*)kr;
                    bf[1] = *(const uint32_t*)(kr + 16);
                    mma16(s[nf], aQ[ks], bf);
                }
            }
            const int r0 = qbase + lr0, r1 = r0 + 8;
            if (ktb + 63 > qbase + wid * 16) {       // diagonal: mask
                #pragma unroll
                for (int nf = 0; nf < 8; nf++) {
                    int c0 = ktb + nf * 8 + 2 * t;
                    if (c0     > r0) s[nf][0] = -INFINITY;
                    if (c0 + 1 > r0) s[nf][1] = -INFINITY;
                    if (c0     > r1) s[nf][2] = -INFINITY;
                    if (c0 + 1 > r1) s[nf][3] = -INFINITY;
                }
            }
            float mx0 = -INFINITY, mx1 = -INFINITY;
            #pragma unroll
            for (int nf = 0; nf < 8; nf++) {
                mx0 = fmaxf(mx0, fmaxf(s[nf][0], s[nf][1]));
                mx1 = fmaxf(mx1, fmaxf(s[nf][2], s[nf][3]));
            }
            mx0 = fmaxf(mx0, __shfl_xor_sync(0xffffffffu, mx0, 1));
            mx0 = fmaxf(mx0, __shfl_xor_sync(0xffffffffu, mx0, 2));
            mx1 = fmaxf(mx1, __shfl_xor_sync(0xffffffffu, mx1, 1));
            mx1 = fmaxf(mx1, __shfl_xor_sync(0xffffffffu, mx1, 2));
            float nm0 = fmaxf(m0, mx0), nm1 = fmaxf(m1, mx1);
            float scl0 = exp2f(m0 - nm0), scl1 = exp2f(m1 - nm1);

            __half* Ps = sm + A_QS;
            float ls0 = 0.f, ls1 = 0.f;
            #pragma unroll
            for (int nf = 0; nf < 8; nf++) {
                float p0 = exp2f(s[nf][0] - nm0);
                float p1 = exp2f(s[nf][1] - nm0);
                float p2 = exp2f(s[nf][2] - nm1);
                float p3 = exp2f(s[nf][3] - nm1);
                ls0 += p0 + p1; ls1 += p2 + p3;
                *(__half2*)&Ps[lr0 * PADH + nf * 8 + 2 * t] = __floats2half2_rn(p0, p1);
                *(__half2*)&Ps[(lr0 + 8) * PADH + nf * 8 + 2 * t] = __floats2half2_rn(p2, p3);
            }
            ls0 += __shfl_xor_sync(0xffffffffu, ls0, 1);
            ls0 += __shfl_xor_sync(0xffffffffu, ls0, 2);
            ls1 += __shfl_xor_sync(0xffffffffu, ls1, 1);
            ls1 += __shfl_xor_sync(0xffffffffu, ls1, 2);
            l0 = l0 * scl0 + ls0; l1 = l1 * scl1 + ls1;
            #pragma unroll
            for (int nf = 0; nf < 8; nf++) {
                o[nf][0] *= scl0; o[nf][1] *= scl0; o[nf][2] *= scl1; o[nf][3] *= scl1;
            }
            __syncwarp();
            // O += P V   (4 k16 steps over s=64; V frags via ldmatrix.trans)
            const char* Pc = smc + A_QS * 2;
            const int lmq = lid >> 3, lmr = lid & 7;     // ldmatrix lane mapping
            #pragma unroll
            for (int ks = 0; ks < 4; ks++) {
                int kb = ks * 32 + 4 * t;
                uint32_t ap[4];
                ap[0] = *(const uint32_t*)(Pc + lr0 * PADB + kb);
                ap[1] = *(const uint32_t*)(Pc + (lr0 + 8) * PADB + kb);
                ap[2] = *(const uint32_t*)(Pc + lr0 * PADB + kb + 16);
                ap[3] = *(const uint32_t*)(Pc + (lr0 + 8) * PADB + kb + 16);
                #pragma unroll
                for (int nf2 = 0; nf2 < 4; nf2++) {
                    int s_off = ks * 16 + (lmq & 1) * 8 + lmr;
                    int d_off = nf2 * 16 + (lmq >> 1) * 8;
                    uint32_t r0v, r1v, r2v, r3v;
                    ldmx4t(r0v, r1v, r2v, r3v, Vsb + (s_off * PADH + d_off) * 2);
                    uint32_t bfa[2] = { r0v, r1v };
                    uint32_t bfb[2] = { r2v, r3v };
                    mma16(o[nf2 * 2],     ap, bfa);
                    mma16(o[nf2 * 2 + 1], ap, bfb);
                }
            }
            m0 = nm0; m1 = nm1;
        }
        __syncthreads();
    }

    float inv0 = 1.f / l0, inv1 = 1.f / l1;
    #pragma unroll
    for (int nf = 0; nf < 8; nf++) {
        int c = nf * 8 + 2 * t;
        *(__half2*)(O + base + (size_t)(qbase + lr0) * EE + c) =
            __floats2half2_rn(o[nf][0] * inv0, o[nf][1] * inv0);
        *(__half2*)(O + base + (size_t)(qbase + lr0 + 8) * EE + c) =
            __floats2half2_rn(o[nf][2] * inv1, o[nf][3] * inv1);
    }
}

// ---------------- launch ------------------------------------------------------
extern "C" void kernel_launch(void* const* d_in, const int* in_sizes, int n_in,
                              void* d_out, int out_size)
{
    const int*   ids   = (const int*)  d_in[0];
    const float* wte   = (const float*)d_in[1];
    const float* wpe   = (const float*)d_in[2];
    const float* wq    = (const float*)d_in[3];
    const float* wk    = (const float*)d_in[4];
    const float* wv    = (const float*)d_in[5];
    const float* bq    = (const float*)d_in[6];
    const float* bk    = (const float*)d_in[7];
    const float* bv    = (const float*)d_in[8];
    const float* wproj = (const float*)d_in[9];
    const float* bproj = (const float*)d_in[10];
    const float* ln1g  = (const float*)d_in[11];
    const float* ln1b  = (const float*)d_in[12];
    const float* ln2g  = (const float*)d_in[13];
    const float* ln2b  = (const float*)d_in[14];
    const float* wfc   = (const float*)d_in[15];
    const float* bfc   = (const float*)d_in[16];
    const float* wout  = (const float*)d_in[17];
    const float* bout  = (const float*)d_in[18];
    float* out = (float*)d_out;

    float *x, *x2;
    __half *h, *q, *k, *v, *o, *mb;
    __half *wtq, *wtk, *wtv, *wtp, *wtfc, *wtout;
    cudaGetSymbolAddress((void**)&x,  g_x);
    cudaGetSymbolAddress((void**)&x2, g_x2);
    cudaGetSymbolAddress((void**)&h,  g_h);
    cudaGetSymbolAddress((void**)&q,  g_q);
    cudaGetSymbolAddress((void**)&k,  g_k);
    cudaGetSymbolAddress((void**)&v,  g_v);
    cudaGetSymbolAddress((void**)&o,  g_o);
    cudaGetSymbolAddress((void**)&mb, g_m);
    cudaGetSymbolAddress((void**)&wtq,  g_wtq);
    cudaGetSymbolAddress((void**)&wtk,  g_wtk);
    cudaGetSymbolAddress((void**)&wtv,  g_wtv);
    cudaGetSymbolAddress((void**)&wtp,  g_wtp);
    cudaGetSymbolAddress((void**)&wtfc, g_wtfc);
    cudaGetSymbolAddress((void**)&wtout,g_wtout);

    cudaFuncSetAttribute(attn_tc, cudaFuncAttributeMaxDynamicSharedMemorySize, ATT_SMEM);
    cudaFuncSetAttribute(tc_gemm<false,false,true>,  cudaFuncAttributeMaxDynamicSharedMemorySize, GSMEM);
    cudaFuncSetAttribute(tc_gemm<false,true,false>,  cudaFuncAttributeMaxDynamicSharedMemorySize, GSMEM);
    cudaFuncSetAttribute(tc_gemm<true,false,true>,   cudaFuncAttributeMaxDynamicSharedMemorySize, GSMEM);

    const float alpha = 0.18033688011112042f;   // 0.125 * log2(e)

    dim3 tb(32, 8);
    transpose_qkv_kernel<<<dim3(2, 32, 16), tb>>>(wq, wtq);
    transpose_qkv_kernel<<<dim3(2, 32, 16), tb>>>(wk, wtk);
    transpose_qkv_kernel<<<dim3(2, 32, 16), tb>>>(wv, wtv);
    transpose_kernel<<<dim3(32, 32),  tb>>>(wproj, wtp,  EE, EE);
    transpose_kernel<<<dim3(128, 32), tb>>>(wfc,   wtfc, EE, FF);
    transpose_kernel<<<dim3(32, 128), tb>>>(wout,  wtout, FF, EE);

    // 1. embed
    embed_kernel<<<(MM * EE / 4) / 256, 256>>>(ids, wte, wpe, x);
    // 2. ln1
    ln_kernel<<<MM, 256>>>(x, ln1g, ln1b, h);
    // 3. qkv projections (q pre-scaled by alpha for attention)
    tc_gemm<false,false,true><<<GEMM_GRID, 128, GSMEM>>>(h, wtq, bq, nullptr, q, MM, EE, EE, alpha);
    tc_gemm<false,false,true><<<GEMM_GRID, 128, GSMEM>>>(h, wtk, bk, nullptr, k, MM, EE, EE, 1.f);
    tc_gemm<false,false,true><<<GEMM_GRID, 128, GSMEM>>>(h, wtv, bv, nullptr, v, MM, EE, EE, 1.f);
    // 4. causal flash attention (fp16 tensor cores)
    attn_tc<<<dim3(TT / 128, HH, BB), 256, ATT_SMEM>>>(q, k, v, o);
    // 5. proj + residual -> x2 (fp32)
    tc_gemm<false,true,false><<<GEMM_GRID, 128, GSMEM>>>(o, wtp, bproj, x, x2, MM, EE, EE, 1.f);
    // 6. ln2
    ln_kernel<<<MM, 256>>>(x2, ln2g, ln2b, h);
    // 7. fc + gelu -> m (fp16)
    tc_gemm<true,false,true><<<GEMM_GRID, 128, GSMEM>>>(h, wtfc, bfc, nullptr, mb, MM, FF, EE, 1.f);
    // 8. out proj + residual -> d_out (fp32)
    tc_gemm<false,true,false><<<GEMM_GRID, 128, GSMEM>>>(mb, wtout, bout, x2, out, MM, EE, FF, 1.f);
}

// round 8
// speedup vs baseline: 7.6472x; 1.0282x over previous
#include <cuda_runtime.h>
#include <cuda_fp16.h>
#include <math.h>
#include <stdint.h>

// Problem constants
#define BB 4
#define TT 2048
#define EE 1024
#define HH 16
#define DD 64
#define MM (BB*TT)        // 8192
#define FF (4*EE)         // 4096
#define QKVS 3072         // merged qkv row stride

// ---------------- scratch (device globals; no allocation allowed) -------------
__device__ float  g_x [MM*EE];               // residual stream (fp32)
__device__ float  g_x2[MM*EE];
__device__ __half g_h [MM*EE];               // LN output (GEMM A)
__device__ __half g_qkv[(size_t)MM*QKVS];    // q|k|v merged (q pre-scaled)
__device__ __half g_o [MM*EE];               // attention output
__device__ __half g_m [(size_t)MM*FF];       // gelu(fc)
// pre-transposed weights (K-major [N,K], fp16)
__device__ __half g_wtqkv[(size_t)QKVS*EE];  // [3072,1024] (q rows pre-scaled)
__device__ float  g_bqkv [QKVS];             // merged bias (q pre-scaled)
__device__ __half g_wtp [EE*EE];
__device__ __half g_wtfc [(size_t)FF*EE];
__device__ __half g_wtout[(size_t)EE*FF];

// ---------------- helpers -----------------------------------------------------
__device__ __forceinline__ uint32_t smem_u32(const void* p) {
    uint32_t a;
    asm("{ .reg .u64 t; cvta.to.shared.u64 t, %1; cvt.u32.u64 %0, t; }" : "=r"(a) : "l"(p));
    return a;
}
__device__ __forceinline__ void cp16(uint32_t dst, const void* src) {
    asm volatile("cp.async.cg.shared.global [%0], [%1], 16;" :: "r"(dst), "l"(src));
}
#define CP_COMMIT() asm volatile("cp.async.commit_group;" ::: "memory")
#define CP_WAIT(n)  asm volatile("cp.async.wait_group %0;" :: "n"(n) : "memory")

// mma.sync m16n8k16 fp16 inputs, fp32 accumulate (sm_80+ base-target)
__device__ __forceinline__ void mma16(float* d, const uint32_t* a, const uint32_t* b) {
    asm volatile("mma.sync.aligned.m16n8k16.row.col.f32.f16.f16.f32 "
        "{%0,%1,%2,%3}, {%4,%5,%6,%7}, {%8,%9}, {%0,%1,%2,%3};"
        : "+f"(d[0]), "+f"(d[1]), "+f"(d[2]), "+f"(d[3])
        : "r"(a[0]), "r"(a[1]), "r"(a[2]), "r"(a[3]), "r"(b[0]), "r"(b[1]));
}
__device__ __forceinline__ void ldmx4t(uint32_t& r0, uint32_t& r1, uint32_t& r2,
                                       uint32_t& r3, uint32_t addr) {
    asm volatile("ldmatrix.sync.aligned.m8n8.x4.trans.shared.b16 {%0,%1,%2,%3}, [%4];"
        : "=r"(r0), "=r"(r1), "=r"(r2), "=r"(r3) : "r"(addr));
}

// ---------------- fused embed + ln1: x = wte[ids]+wpe; h = LN(x) --------------
__global__ __launch_bounds__(256) void embed_ln_kernel(
    const int* __restrict__ ids, const float* __restrict__ wte,
    const float* __restrict__ wpe, const float* __restrict__ G,
    const float* __restrict__ Bt, float* __restrict__ X, __half* __restrict__ Y)
{
    __shared__ float red[16];
    int row = blockIdx.x, tid = threadIdx.x;
    int t   = row & (TT - 1);
    int id  = ids[row];
    float4 a = ((const float4*)wte)[(size_t)id * 256 + tid];
    float4 p = ((const float4*)wpe)[(size_t)t  * 256 + tid];
    a.x += p.x; a.y += p.y; a.z += p.z; a.w += p.w;
    ((float4*)(X + ((size_t)row << 10)))[tid] = a;

    float s  = a.x + a.y + a.z + a.w;
    float sq = a.x*a.x + a.y*a.y + a.z*a.z + a.w*a.w;
    #pragma unroll
    for (int o = 16; o; o >>= 1) {
        s  += __shfl_xor_sync(0xffffffffu, s,  o);
        sq += __shfl_xor_sync(0xffffffffu, sq, o);
    }
    if ((tid & 31) == 0) { red[tid >> 5] = s; red[8 + (tid >> 5)] = sq; }
    __syncthreads();
    float ts = 0.f, tq = 0.f;
    #pragma unroll
    for (int i = 0; i < 8; i++) { ts += red[i]; tq += red[8 + i]; }
    float mean = ts * (1.f / 1024.f);
    float var  = tq * (1.f / 1024.f) - mean * mean;
    float inv  = rsqrtf(var + 1e-5f);
    float4 g4 = ((const float4*)G)[tid];
    float4 b4 = ((const float4*)Bt)[tid];
    __half2 h01 = __floats2half2_rn((a.x - mean) * inv * g4.x + b4.x,
                                    (a.y - mean) * inv * g4.y + b4.y);
    __half2 h23 = __floats2half2_rn((a.z - mean) * inv * g4.z + b4.z,
                                    (a.w - mean) * inv * g4.w + b4.w);
    uint2 o; o.x = *(uint32_t*)&h01; o.y = *(uint32_t*)&h23;
    ((uint2*)(Y + ((size_t)row << 10)))[tid] = o;
}

// ---------------- layernorm (fp32 in, fp16 out) -------------------------------
__global__ __launch_bounds__(256) void ln_kernel(
    const float* __restrict__ X, const float* __restrict__ G,
    const float* __restrict__ Bt, __half* __restrict__ Y)
{
    __shared__ float red[16];
    int row = blockIdx.x, tid = threadIdx.x;
    const float4* x4 = (const float4*)(X + ((size_t)row << 10));
    float4 a = x4[tid];
    float s  = a.x + a.y + a.z + a.w;
    float sq = a.x*a.x + a.y*a.y + a.z*a.z + a.w*a.w;
    #pragma unroll
    for (int o = 16; o; o >>= 1) {
        s  += __shfl_xor_sync(0xffffffffu, s,  o);
        sq += __shfl_xor_sync(0xffffffffu, sq, o);
    }
    if ((tid & 31) == 0) { red[tid >> 5] = s; red[8 + (tid >> 5)] = sq; }
    __syncthreads();
    float ts = 0.f, tq = 0.f;
    #pragma unroll
    for (int i = 0; i < 8; i++) { ts += red[i]; tq += red[8 + i]; }
    float mean = ts * (1.f / 1024.f);
    float var  = tq * (1.f / 1024.f) - mean * mean;
    float inv  = rsqrtf(var + 1e-5f);
    float4 g4 = ((const float4*)G)[tid];
    float4 b4 = ((const float4*)Bt)[tid];
    __half2 h01 = __floats2half2_rn((a.x - mean) * inv * g4.x + b4.x,
                                    (a.y - mean) * inv * g4.y + b4.y);
    __half2 h23 = __floats2half2_rn((a.z - mean) * inv * g4.z + b4.z,
                                    (a.w - mean) * inv * g4.w + b4.w);
    uint2 o; o.x = *(uint32_t*)&h01; o.y = *(uint32_t*)&h23;
    ((uint2*)(Y + ((size_t)row << 10)))[tid] = o;
}

// ---------------- merged qkv weight transpose ---------------------------------
// W_sec (H,E,D) -> Wt[sec*1024 + h*64 + d][k];  q section scaled by alpha.
__global__ __launch_bounds__(256) void transpose_qkv_all(
    const float* __restrict__ Wq, const float* __restrict__ Wk,
    const float* __restrict__ Wv, __half* __restrict__ Wt, float alpha)
{
    __shared__ float t[32][33];
    int tx = threadIdx.x, ty = threadIdx.y;
    int z = blockIdx.z, sec = z >> 4, h = z & 15;
    int k0 = blockIdx.y * 32, d0 = blockIdx.x * 32;
    const float* W = (sec == 0) ? Wq : (sec == 1) ? Wk : Wv;
    float sc = (sec == 0) ? alpha : 1.f;
    const float* Wh = W + (size_t)h * EE * DD;
    #pragma unroll
    for (int i = ty; i < 32; i += 8) t[i][tx] = Wh[(size_t)(k0 + i) * DD + d0 + tx];
    __syncthreads();
    #pragma unroll
    for (int i = ty; i < 32; i += 8)
        Wt[(size_t)(sec * 1024 + h * DD + d0 + i) * EE + k0 + tx] = __float2half_rn(t[tx][i] * sc);
}

// merged qkv bias (q section scaled by alpha)
__global__ __launch_bounds__(256) void bias_merge_kernel(
    const float* __restrict__ bq, const float* __restrict__ bk,
    const float* __restrict__ bv, float* __restrict__ bout, float alpha)
{
    int i = blockIdx.x * 256 + threadIdx.x;   // 0..3071
    int sec = i >> 10, j = i & 1023;
    float v = (sec == 0) ? bq[j] * alpha : (sec == 1) ? bk[j] : bv[j];
    bout[i] = v;
}

// ---------------- flattened 3-job weight transpose ----------------------------
// job 0: wproj [1024,1024]; job 1: wfc [1024,4096]; job 2: wout [4096,1024]
__global__ __launch_bounds__(256) void transpose_all(
    const float* __restrict__ Wp, const float* __restrict__ Wf,
    const float* __restrict__ Wo, __half* __restrict__ Tp,
    __half* __restrict__ Tf, __half* __restrict__ To)
{
    __shared__ float t[32][33];
    int bid = blockIdx.x;
    const float* W; __half* Wt; int K, N, n0, k0;
    if (bid < 1024) {                      // proj: 32 n-blocks x 32 k-blocks
        W = Wp; Wt = Tp; K = 1024; N = 1024;
        n0 = (bid & 31) * 32; k0 = (bid >> 5) * 32;
    } else if (bid < 1024 + 4096) {        // fc: 128 n-blocks x 32 k-blocks
        int b = bid - 1024;
        W = Wf; Wt = Tf; K = 1024; N = 4096;
        n0 = (b & 127) * 32; k0 = (b >> 7) * 32;
    } else {                               // out: 32 n-blocks x 128 k-blocks
        int b = bid - 5120;
        W = Wo; Wt = To; K = 4096; N = 1024;
        n0 = (b & 31) * 32; k0 = (b >> 5) * 32;
    }
    int tx = threadIdx.x, ty = threadIdx.y;
    #pragma unroll
    for (int i = ty; i < 32; i += 8) t[i][tx] = W[(size_t)(k0 + i) * N + n0 + tx];
    __syncthreads();
    #pragma unroll
    for (int i = ty; i < 32; i += 8)
        Wt[(size_t)(n0 + i) * K + k0 + tx] = __float2half_rn(t[tx][i]);
}

// ---------------- mma.sync fp16 GEMM (persistent, warp tile 64x64) ------------
#define PADH  72
#define PADB  144
#define GSTGB (256*PADB)
#define GSMEM (3*GSTGB)
#define GEMM_GRID 296

__device__ __forceinline__ void gcp_stage(
    uint32_t sbase, int s, const __half* __restrict__ A, const __half* __restrict__ Wt,
    int bm, int bn, int K, int k0, int tid)
{
    uint32_t sA = sbase + s * GSTGB;
    uint32_t sB = sA + 128 * PADB;
    #pragma unroll
    for (int e = 0; e < 4; e++) {
        int lin = tid + 128 * e;
        int r = lin >> 2, c = lin & 3;
        cp16(sA + r * PADB + c * 16, A  + (size_t)(bm + r) * K + k0 + c * 8);
        cp16(sB + r * PADB + c * 16, Wt + (size_t)(bn + r) * K + k0 + c * 8);
    }
}

template<bool GELU_, bool RES, bool OUTH>
__global__ __launch_bounds__(128) void tc_gemm(
    const __half* __restrict__ A, const __half* __restrict__ Wt,
    const float* __restrict__ bias, const float* __restrict__ Rp,
    void* __restrict__ Cv, int M, int N, int K)
{
    extern __shared__ __align__(16) char smc[];
    uint32_t sbase = smem_u32(smc);
    const int tid = threadIdx.x, wid = tid >> 5, lid = tid & 31;
    const int g = lid >> 2, t = lid & 3;
    const int warp_m = (wid & 1) * 64, warp_n = (wid >> 1) * 64;
    const int NT = K >> 5;
    const int mtiles = M >> 7;
    const int total = mtiles * (N >> 7);

    for (int tile = blockIdx.x; tile < total; tile += gridDim.x) {
        const int bm = (tile % mtiles) * 128;
        const int bn = (tile / mtiles) * 128;

        float d[4][8][4];
        #pragma unroll
        for (int i = 0; i < 4; i++)
            #pragma unroll
            for (int j = 0; j < 8; j++)
                #pragma unroll
                for (int p = 0; p < 4; p++) d[i][j][p] = 0.f;

        gcp_stage(sbase, 0, A, Wt, bm, bn, K, 0,  tid); CP_COMMIT();
        gcp_stage(sbase, 1, A, Wt, bm, bn, K, 32, tid); CP_COMMIT();

        for (int kt = 0; kt < NT; kt++) {
            if (kt == NT - 1) { CP_WAIT(0); } else { CP_WAIT(1); }
            __syncthreads();                       // single barrier per stage
            if (kt + 2 < NT) {
                gcp_stage(sbase, (kt + 2) % 3, A, Wt, bm, bn, K, (kt + 2) * 32, tid);
                CP_COMMIT();
            }
            const char* As = smc + (size_t)(kt % 3) * GSTGB;
            const char* Bs = As + 128 * PADB;
            #pragma unroll
            for (int ks = 0; ks < 2; ks++) {
                const int kb = ks * 32 + 4 * t;
                uint32_t af[4][4], bf[8][2];
                #pragma unroll
                for (int mf = 0; mf < 4; mf++) {
                    int rm = warp_m + mf * 16 + g;
                    af[mf][0] = *(const uint32_t*)(As + rm * PADB + kb);
                    af[mf][1] = *(const uint32_t*)(As + (rm + 8) * PADB + kb);
                    af[mf][2] = *(const uint32_t*)(As + rm * PADB + kb + 16);
                    af[mf][3] = *(const uint32_t*)(As + (rm + 8) * PADB + kb + 16);
                }
                #pragma unroll
                for (int nf = 0; nf < 8; nf++) {
                    int rn = warp_n + nf * 8 + g;
                    bf[nf][0] = *(const uint32_t*)(Bs + rn * PADB + kb);
                    bf[nf][1] = *(const uint32_t*)(Bs + rn * PADB + kb + 16);
                }
                #pragma unroll
                for (int mf = 0; mf < 4; mf++)
                    #pragma unroll
                    for (int nf = 0; nf < 8; nf++)
                        mma16(d[mf][nf], af[mf], bf[nf]);
            }
        }
        __syncthreads();   // mainloop reads done before epilogue/next-tile refill

        // epilogue
        #pragma unroll
        for (int mf = 0; mf < 4; mf++) {
            int row0 = bm + warp_m + mf * 16 + g;
            #pragma unroll
            for (int nf = 0; nf < 8; nf++) {
                int col = bn + warp_n + nf * 8 + 2 * t;
                float b0 = __ldg(bias + col), b1 = __ldg(bias + col + 1);
                #pragma unroll
                for (int p = 0; p < 2; p++) {
                    int m = row0 + p * 8;
                    float v0 = d[mf][nf][2 * p + 0] + b0;
                    float v1 = d[mf][nf][2 * p + 1] + b1;
                    if (GELU_) {
                        v0 = 0.5f * v0 * (1.f + erff(v0 * 0.70710678118654752f));
                        v1 = 0.5f * v1 * (1.f + erff(v1 * 0.70710678118654752f));
                    }
                    if (OUTH) {
                        __half2 hp = __floats2half2_rn(v0, v1);
                        *(__half2*)((__half*)Cv + (size_t)m * N + col) = hp;
                    } else {
                        if (RES) {
                            float2 rr = *(const float2*)(Rp + (size_t)m * N + col);
                            v0 += rr.x; v1 += rr.y;
                        }
                        float2 o; o.x = v0; o.y = v1;
                        *(float2*)((float*)Cv + (size_t)m * N + col) = o;
                    }
                }
            }
        }
    }
}

// ---------------- tensor-core flash attention (causal, fp16) ------------------
#define A_QS 0
#define A_KS (128*PADH)
#define A_VS (A_KS + 2*64*PADH)
#define A_ENDH (A_VS + 2*64*PADH)
#define ATT_SMEM (A_ENDH*2)

__global__ __launch_bounds__(256) void attn_tc(
    const __half* __restrict__ QKV, __half* __restrict__ O)
{
    extern __shared__ __align__(16) char smc[];
    __half* sm = (__half*)smc;
    uint32_t sb = smem_u32(smc);
    const int qt = (int)gridDim.x - 1 - (int)blockIdx.x;
    const int h = blockIdx.y, b = blockIdx.z;
    const int tid = threadIdx.x, wid = tid >> 5, lid = tid & 31;
    const int g = lid >> 2, t = lid & 3;
    const int qbase = qt * 128;
    const size_t qkvbase = (size_t)(b * TT) * QKVS + (size_t)h * DD;
    const __half* Q  = QKV + qkvbase;
    const __half* Kp = QKV + qkvbase + 1024;
    const __half* Vp = QKV + qkvbase + 2048;
    const size_t obase = (size_t)(b * TT) * EE + (size_t)h * DD;
    const int lr0 = wid * 16 + g;
    const int nt = 2 * qt + 2;

    #pragma unroll
    for (int i = 0; i < 4; i++) {
        int idx = tid + i * 256;
        int r = idx >> 3, c = idx & 7;
        cp16(sb + (A_QS + r * PADH) * 2 + c * 16, Q + (size_t)(qbase + r) * QKVS + c * 8);
    }
    CP_COMMIT();
    #pragma unroll
    for (int i = 0; i < 4; i++) {
        int idx = tid + i * 256;
        int r = idx >> 4, c = idx & 7, kv = (idx >> 3) & 1;
        uint32_t dst = kv ? (uint32_t)(A_VS + r * PADH) : (uint32_t)(A_KS + r * PADH);
        const __half* src = kv ? Vp : Kp;
        cp16(sb + dst * 2 + c * 16, src + (size_t)r * QKVS + c * 8);
    }
    CP_COMMIT();

    CP_WAIT(1);
    __syncthreads();

    uint32_t aQ[4][4];
    {
        const char* Qs = smc + A_QS * 2;
        #pragma unroll
        for (int ks = 0; ks < 4; ks++) {
            int kb = ks * 32 + 4 * t;
            aQ[ks][0] = *(const uint32_t*)(Qs + lr0 * PADB + kb);
            aQ[ks][1] = *(const uint32_t*)(Qs + (lr0 + 8) * PADB + kb);
            aQ[ks][2] = *(const uint32_t*)(Qs + lr0 * PADB + kb + 16);
            aQ[ks][3] = *(const uint32_t*)(Qs + (lr0 + 8) * PADB + kb + 16);
        }
    }
    __syncthreads();

    float o[8][4];
    #pragma unroll
    for (int nf = 0; nf < 8; nf++) { o[nf][0]=0.f; o[nf][1]=0.f; o[nf][2]=0.f; o[nf][3]=0.f; }
    float m0 = -INFINITY, m1 = -INFINITY, l0 = 0.f, l1 = 0.f;

    for (int kt = 0; kt < nt; kt++) {
        if (kt + 1 < nt) {
            int st = (kt + 1) & 1, kb2 = (kt + 1) * 64;
            #pragma unroll
            for (int i = 0; i < 4; i++) {
                int idx = tid + i * 256;
                int r = idx >> 4, c = idx & 7, kv = (idx >> 3) & 1;
                uint32_t dst = kv ? (uint32_t)(A_VS + st * 64 * PADH + r * PADH)
                                  : (uint32_t)(A_KS + st * 64 * PADH + r * PADH);
                const __half* src = kv ? Vp : Kp;
                cp16(sb + dst * 2 + c * 16, src + (size_t)(kb2 + r) * QKVS + c * 8);
            }
            CP_COMMIT();
            CP_WAIT(1);
        } else { CP_WAIT(0); }
        __syncthreads();

        const int ktb = kt * 64;
        if (ktb <= qbase + wid * 16 + 15) {
            const char* Ks = smc + (A_KS + (kt & 1) * 64 * PADH) * 2;
            const uint32_t Vsb = sb + (A_VS + (kt & 1) * 64 * PADH) * 2;

            float s[8][4];
            #pragma unroll
            for (int nf = 0; nf < 8; nf++) { s[nf][0]=0.f; s[nf][1]=0.f; s[nf][2]=0.f; s[nf][3]=0.f; }
            #pragma unroll
            for (int ks = 0; ks < 4; ks++) {
                int kb = ks * 32 + 4 * t;
                #pragma unroll
                for (int nf = 0; nf < 8; nf++) {
                    uint32_t bf[2];
                    const char* kr = Ks + (nf * 8 + g) * PADB + kb;
                    bf[0] = *(const uint32_t*)kr;
                    bf[1] = *(const uint32_t*)(kr + 16);
                    mma16(s[nf], aQ[ks], bf);
                }
            }
            const int r0 = qbase + lr0, r1 = r0 + 8;
            if (ktb + 63 > qbase + wid * 16) {
                #pragma unroll
                for (int nf = 0; nf < 8; nf++) {
                    int c0 = ktb + nf * 8 + 2 * t;
                    if (c0     > r0) s[nf][0] = -INFINITY;
                    if (c0 + 1 > r0) s[nf][1] = -INFINITY;
                    if (c0     > r1) s[nf][2] = -INFINITY;
                    if (c0 + 1 > r1) s[nf][3] = -INFINITY;
                }
            }
            float mx0 = -INFINITY, mx1 = -INFINITY;
            #pragma unroll
            for (int nf = 0; nf < 8; nf++) {
                mx0 = fmaxf(mx0, fmaxf(s[nf][0], s[nf][1]));
                mx1 = fmaxf(mx1, fmaxf(s[nf][2], s[nf][3]));
            }
            mx0 = fmaxf(mx0, __shfl_xor_sync(0xffffffffu, mx0, 1));
            mx0 = fmaxf(mx0, __shfl_xor_sync(0xffffffffu, mx0, 2));
            mx1 = fmaxf(mx1, __shfl_xor_sync(0xffffffffu, mx1, 1));
            mx1 = fmaxf(mx1, __shfl_xor_sync(0xffffffffu, mx1, 2));
            float nm0 = fmaxf(m0, mx0), nm1 = fmaxf(m1, mx1);
            float scl0 = exp2f(m0 - nm0), scl1 = exp2f(m1 - nm1);

            __half* Ps = sm + A_QS;
            float ls0 = 0.f, ls1 = 0.f;
            #pragma unroll
            for (int nf = 0; nf < 8; nf++) {
                float p0 = exp2f(s[nf][0] - nm0);
                float p1 = exp2f(s[nf][1] - nm0);
                float p2 = exp2f(s[nf][2] - nm1);
                float p3 = exp2f(s[nf][3] - nm1);
                ls0 += p0 + p1; ls1 += p2 + p3;
                *(__half2*)&Ps[lr0 * PADH + nf * 8 + 2 * t] = __floats2half2_rn(p0, p1);
                *(__half2*)&Ps[(lr0 + 8) * PADH + nf * 8 + 2 * t] = __floats2half2_rn(p2, p3);
            }
            ls0 += __shfl_xor_sync(0xffffffffu, ls0, 1);
            ls0 += __shfl_xor_sync(0xffffffffu, ls0, 2);
            ls1 += __shfl_xor_sync(0xffffffffu, ls1, 1);
            ls1 += __shfl_xor_sync(0xffffffffu, ls1, 2);
            l0 = l0 * scl0 + ls0; l1 = l1 * scl1 + ls1;
            #pragma unroll
            for (int nf = 0; nf < 8; nf++) {
                o[nf][0] *= scl0; o[nf][1] *= scl0; o[nf][2] *= scl1; o[nf][3] *= scl1;
            }
            __syncwarp();
            const char* Pc = smc + A_QS * 2;
            const int lmq = lid >> 3, lmr = lid & 7;
            #pragma unroll
            for (int ks = 0; ks < 4; ks++) {
                int kb = ks * 32 + 4 * t;
                uint32_t ap[4];
                ap[0] = *(const uint32_t*)(Pc + lr0 * PADB + kb);
                ap[1] = *(const uint32_t*)(Pc + (lr0 + 8) * PADB + kb);
                ap[2] = *(const uint32_t*)(Pc + lr0 * PADB + kb + 16);
                ap[3] = *(const uint32_t*)(Pc + (lr0 + 8) * PADB + kb + 16);
                #pragma unroll
                for (int nf2 = 0; nf2 < 4; nf2++) {
                    int s_off = ks * 16 + (lmq & 1) * 8 + lmr;
                    int d_off = nf2 * 16 + (lmq >> 1) * 8;
                    uint32_t r0v, r1v, r2v, r3v;
                    ldmx4t(r0v, r1v, r2v, r3v, Vsb + (s_off * PADH + d_off) * 2);
                    uint32_t bfa[2] = { r0v, r1v };
                    uint32_t bfb[2] = { r2v, r3v };
                    mma16(o[nf2 * 2],     ap, bfa);
                    mma16(o[nf2 * 2 + 1], ap, bfb);
                }
            }
            m0 = nm0; m1 = nm1;
        }
        __syncthreads();
    }

    float inv0 = 1.f / l0, inv1 = 1.f / l1;
    #pragma unroll
    for (int nf = 0; nf < 8; nf++) {
        int c = nf * 8 + 2 * t;
        *(__half2*)(O + obase + (size_t)(qbase + lr0) * EE + c) =
            __floats2half2_rn(o[nf][0] * inv0, o[nf][1] * inv0);
        *(__half2*)(O + obase + (size_t)(qbase + lr0 + 8) * EE + c) =
            __floats2half2_rn(o[nf][2] * inv1, o[nf][3] * inv1);
    }
}

// ---------------- launch ------------------------------------------------------
extern "C" void kernel_launch(void* const* d_in, const int* in_sizes, int n_in,
                              void* d_out, int out_size)
{
    const int*   ids   = (const int*)  d_in[0];
    const float* wte   = (const float*)d_in[1];
    const float* wpe   = (const float*)d_in[2];
    const float* wq    = (const float*)d_in[3];
    const float* wk    = (const float*)d_in[4];
    const float* wv    = (const float*)d_in[5];
    const float* bq    = (const float*)d_in[6];
    const float* bk    = (const float*)d_in[7];
    const float* bv    = (const float*)d_in[8];
    const float* wproj = (const float*)d_in[9];
    const float* bproj = (const float*)d_in[10];
    const float* ln1g  = (const float*)d_in[11];
    const float* ln1b  = (const float*)d_in[12];
    const float* ln2g  = (const float*)d_in[13];
    const float* ln2b  = (const float*)d_in[14];
    const float* wfc   = (const float*)d_in[15];
    const float* bfc   = (const float*)d_in[16];
    const float* wout  = (const float*)d_in[17];
    const float* bout  = (const float*)d_in[18];
    float* out = (float*)d_out;

    float *x, *x2, *bqkv;
    __half *h, *qkv, *o, *mb;
    __half *wtqkv, *wtp, *wtfc, *wtout;
    cudaGetSymbolAddress((void**)&x,  g_x);
    cudaGetSymbolAddress((void**)&x2, g_x2);
    cudaGetSymbolAddress((void**)&h,  g_h);
    cudaGetSymbolAddress((void**)&qkv, g_qkv);
    cudaGetSymbolAddress((void**)&o,  g_o);
    cudaGetSymbolAddress((void**)&mb, g_m);
    cudaGetSymbolAddress((void**)&wtqkv, g_wtqkv);
    cudaGetSymbolAddress((void**)&bqkv,  g_bqkv);
    cudaGetSymbolAddress((void**)&wtp,   g_wtp);
    cudaGetSymbolAddress((void**)&wtfc,  g_wtfc);
    cudaGetSymbolAddress((void**)&wtout, g_wtout);

    cudaFuncSetAttribute(attn_tc, cudaFuncAttributeMaxDynamicSharedMemorySize, ATT_SMEM);
    cudaFuncSetAttribute(tc_gemm<false,false,true>,  cudaFuncAttributeMaxDynamicSharedMemorySize, GSMEM);
    cudaFuncSetAttribute(tc_gemm<false,true,false>,  cudaFuncAttributeMaxDynamicSharedMemorySize, GSMEM);
    cudaFuncSetAttribute(tc_gemm<true,false,true>,   cudaFuncAttributeMaxDynamicSharedMemorySize, GSMEM);

    const float alpha = 0.18033688011112042f;   // 0.125 * log2(e)

    dim3 tb(32, 8);
    // weight prep (q section pre-scaled by alpha)
    transpose_qkv_all<<<dim3(2, 32, 48), tb>>>(wq, wk, wv, wtqkv, alpha);
    bias_merge_kernel<<<12, 256>>>(bq, bk, bv, bqkv, alpha);
    transpose_all<<<9216, tb>>>(wproj, wfc, wout, wtp, wtfc, wtout);

    // 1+2. embed + ln1 (fused)
    embed_ln_kernel<<<MM, 256>>>(ids, wte, wpe, ln1g, ln1b, x, h);
    // 3. merged qkv projection (N=3072)
    tc_gemm<false,false,true><<<GEMM_GRID, 128, GSMEM>>>(h, wtqkv, bqkv, nullptr, qkv, MM, QKVS, EE);
    // 4. causal flash attention
    attn_tc<<<dim3(TT / 128, HH, BB), 256, ATT_SMEM>>>(qkv, o);
    // 5. proj + residual -> x2
    tc_gemm<false,true,false><<<GEMM_GRID, 128, GSMEM>>>(o, wtp, bproj, x, x2, MM, EE, EE);
    // 6. ln2
    ln_kernel<<<MM, 256>>>(x2, ln2g, ln2b, h);
    // 7. fc + gelu -> m
    tc_gemm<true,false,true><<<GEMM_GRID, 128, GSMEM>>>(h, wtfc, bfc, nullptr, mb, MM, FF, EE);
    // 8. out proj + residual -> d_out
    tc_gemm<false,true,false><<<GEMM_GRID, 128, GSMEM>>>(mb, wtout, bout, x2, out, MM, EE, FF);
}

// round 9
// speedup vs baseline: 7.9475x; 1.0393x over previous
#include <cuda_runtime.h>
#include <cuda_fp16.h>
#include <math.h>
#include <stdint.h>

// Problem constants
#define BB 4
#define TT 2048
#define EE 1024
#define HH 16
#define DD 64
#define MM (BB*TT)        // 8192
#define FF (4*EE)         // 4096
#define QKVS 3072         // merged qkv row stride

// ---------------- scratch (device globals; no allocation allowed) -------------
__device__ float  g_x [MM*EE];               // residual stream (fp32)
__device__ float  g_x2[MM*EE];
__device__ __half g_h [MM*EE];               // LN output (GEMM A)
__device__ __half g_qkv[(size_t)MM*QKVS];    // q|k|v merged (q pre-scaled)
__device__ __half g_o [MM*EE];               // attention output
__device__ __half g_m [(size_t)MM*FF];       // gelu(fc)
// pre-transposed weights (K-major [N,K], fp16)
__device__ __half g_wtqkv[(size_t)QKVS*EE];  // [3072,1024] (q rows pre-scaled)
__device__ float  g_bqkv [QKVS];             // merged bias (q pre-scaled)
__device__ __half g_wtp [EE*EE];
__device__ __half g_wtfc [(size_t)FF*EE];
__device__ __half g_wtout[(size_t)EE*FF];

// ---------------- helpers -----------------------------------------------------
__device__ __forceinline__ uint32_t smem_u32(const void* p) {
    uint32_t a;
    asm("{ .reg .u64 t; cvta.to.shared.u64 t, %1; cvt.u32.u64 %0, t; }" : "=r"(a) : "l"(p));
    return a;
}
__device__ __forceinline__ void cp16(uint32_t dst, const void* src) {
    asm volatile("cp.async.cg.shared.global [%0], [%1], 16;" :: "r"(dst), "l"(src));
}
#define CP_COMMIT() asm volatile("cp.async.commit_group;" ::: "memory")
#define CP_WAIT(n)  asm volatile("cp.async.wait_group %0;" :: "n"(n) : "memory")

// mma.sync m16n8k16 fp16 inputs, fp32 accumulate (sm_80+ base-target)
__device__ __forceinline__ void mma16(float* d, const uint32_t* a, const uint32_t* b) {
    asm volatile("mma.sync.aligned.m16n8k16.row.col.f32.f16.f16.f32 "
        "{%0,%1,%2,%3}, {%4,%5,%6,%7}, {%8,%9}, {%0,%1,%2,%3};"
        : "+f"(d[0]), "+f"(d[1]), "+f"(d[2]), "+f"(d[3])
        : "r"(a[0]), "r"(a[1]), "r"(a[2]), "r"(a[3]), "r"(b[0]), "r"(b[1]));
}
__device__ __forceinline__ void ldmx4t(uint32_t& r0, uint32_t& r1, uint32_t& r2,
                                       uint32_t& r3, uint32_t addr) {
    asm volatile("ldmatrix.sync.aligned.m8n8.x4.trans.shared.b16 {%0,%1,%2,%3}, [%4];"
        : "=r"(r0), "=r"(r1), "=r"(r2), "=r"(r3) : "r"(addr));
}

// ---------------- fused prep kernel -------------------------------------------
// blocks [0,8192): embed+ln1     [8192,11264): qkv weight transpose
// [11264,11276): bias merge      [11276,20492): proj/fc/out transposes
__global__ __launch_bounds__(256) void prep_kernel(
    const int* __restrict__ ids, const float* __restrict__ wte,
    const float* __restrict__ wpe, const float* __restrict__ ln1g,
    const float* __restrict__ ln1b,
    const float* __restrict__ Wq, const float* __restrict__ Wk,
    const float* __restrict__ Wv, const float* __restrict__ bq,
    const float* __restrict__ bk, const float* __restrict__ bv,
    const float* __restrict__ Wp, const float* __restrict__ Wf,
    const float* __restrict__ Wo,
    float* __restrict__ X, __half* __restrict__ Y,
    __half* __restrict__ Wtqkv, float* __restrict__ bqkv,
    __half* __restrict__ Tp, __half* __restrict__ Tf, __half* __restrict__ To,
    float alpha)
{
    __shared__ float sh[32 * 33];
    const int bid = blockIdx.x, tid = threadIdx.x;

    if (bid < 8192) {
        // ---- embed + ln1 ----
        int row = bid;
        int t   = row & (TT - 1);
        int id  = ids[row];
        float4 a = ((const float4*)wte)[(size_t)id * 256 + tid];
        float4 p = ((const float4*)wpe)[(size_t)t  * 256 + tid];
        a.x += p.x; a.y += p.y; a.z += p.z; a.w += p.w;
        ((float4*)(X + ((size_t)row << 10)))[tid] = a;

        float s  = a.x + a.y + a.z + a.w;
        float sq = a.x*a.x + a.y*a.y + a.z*a.z + a.w*a.w;
        #pragma unroll
        for (int o = 16; o; o >>= 1) {
            s  += __shfl_xor_sync(0xffffffffu, s,  o);
            sq += __shfl_xor_sync(0xffffffffu, sq, o);
        }
        if ((tid & 31) == 0) { sh[tid >> 5] = s; sh[8 + (tid >> 5)] = sq; }
        __syncthreads();
        float ts = 0.f, tq = 0.f;
        #pragma unroll
        for (int i = 0; i < 8; i++) { ts += sh[i]; tq += sh[8 + i]; }
        float mean = ts * (1.f / 1024.f);
        float var  = tq * (1.f / 1024.f) - mean * mean;
        float inv  = rsqrtf(var + 1e-5f);
        float4 g4 = ((const float4*)ln1g)[tid];
        float4 b4 = ((const float4*)ln1b)[tid];
        __half2 h01 = __floats2half2_rn((a.x - mean) * inv * g4.x + b4.x,
                                        (a.y - mean) * inv * g4.y + b4.y);
        __half2 h23 = __floats2half2_rn((a.z - mean) * inv * g4.z + b4.z,
                                        (a.w - mean) * inv * g4.w + b4.w);
        uint2 o; o.x = *(uint32_t*)&h01; o.y = *(uint32_t*)&h23;
        ((uint2*)(Y + ((size_t)row << 10)))[tid] = o;
    } else if (bid < 11264) {
        // ---- qkv weight transpose (q section scaled by alpha) ----
        int b2 = bid - 8192;
        int bx = b2 & 1, by = (b2 >> 1) & 31, bz = b2 >> 6;
        int sec = bz >> 4, h = bz & 15;
        int k0 = by * 32, d0 = bx * 32;
        const float* W = (sec == 0) ? Wq : (sec == 1) ? Wk : Wv;
        float sc = (sec == 0) ? alpha : 1.f;
        const float* Wh = W + (size_t)h * EE * DD;
        int tx = tid & 31, ty = tid >> 5;
        #pragma unroll
        for (int i = ty; i < 32; i += 8) sh[i * 33 + tx] = Wh[(size_t)(k0 + i) * DD + d0 + tx];
        __syncthreads();
        #pragma unroll
        for (int i = ty; i < 32; i += 8)
            Wtqkv[(size_t)(sec * 1024 + h * DD + d0 + i) * EE + k0 + tx] =
                __float2half_rn(sh[tx * 33 + i] * sc);
    } else if (bid < 11276) {
        // ---- bias merge ----
        int i = (bid - 11264) * 256 + tid;     // 0..3071
        int sec = i >> 10, j = i & 1023;
        float v = (sec == 0) ? bq[j] * alpha : (sec == 1) ? bk[j] : bv[j];
        bqkv[i] = v;
    } else {
        // ---- proj / fc / out transposes ----
        int b3 = bid - 11276;
        const float* W; __half* Wt; int K, N, n0, k0;
        if (b3 < 1024) {
            W = Wp; Wt = Tp; K = 1024; N = 1024;
            n0 = (b3 & 31) * 32; k0 = (b3 >> 5) * 32;
        } else if (b3 < 5120) {
            int b = b3 - 1024;
            W = Wf; Wt = Tf; K = 1024; N = 4096;
            n0 = (b & 127) * 32; k0 = (b >> 7) * 32;
        } else {
            int b = b3 - 5120;
            W = Wo; Wt = To; K = 4096; N = 1024;
            n0 = (b & 31) * 32; k0 = (b >> 5) * 32;
        }
        int tx = tid & 31, ty = tid >> 5;
        #pragma unroll
        for (int i = ty; i < 32; i += 8) sh[i * 33 + tx] = W[(size_t)(k0 + i) * N + n0 + tx];
        __syncthreads();
        #pragma unroll
        for (int i = ty; i < 32; i += 8)
            Wt[(size_t)(n0 + i) * K + k0 + tx] = __float2half_rn(sh[tx * 33 + i]);
    }
}

// ---------------- layernorm (fp32 in, fp16 out) -------------------------------
__global__ __launch_bounds__(256) void ln_kernel(
    const float* __restrict__ X, const float* __restrict__ G,
    const float* __restrict__ Bt, __half* __restrict__ Y)
{
    __shared__ float red[16];
    int row = blockIdx.x, tid = threadIdx.x;
    const float4* x4 = (const float4*)(X + ((size_t)row << 10));
    float4 a = x4[tid];
    float s  = a.x + a.y + a.z + a.w;
    float sq = a.x*a.x + a.y*a.y + a.z*a.z + a.w*a.w;
    #pragma unroll
    for (int o = 16; o; o >>= 1) {
        s  += __shfl_xor_sync(0xffffffffu, s,  o);
        sq += __shfl_xor_sync(0xffffffffu, sq, o);
    }
    if ((tid & 31) == 0) { red[tid >> 5] = s; red[8 + (tid >> 5)] = sq; }
    __syncthreads();
    float ts = 0.f, tq = 0.f;
    #pragma unroll
    for (int i = 0; i < 8; i++) { ts += red[i]; tq += red[8 + i]; }
    float mean = ts * (1.f / 1024.f);
    float var  = tq * (1.f / 1024.f) - mean * mean;
    float inv  = rsqrtf(var + 1e-5f);
    float4 g4 = ((const float4*)G)[tid];
    float4 b4 = ((const float4*)Bt)[tid];
    __half2 h01 = __floats2half2_rn((a.x - mean) * inv * g4.x + b4.x,
                                    (a.y - mean) * inv * g4.y + b4.y);
    __half2 h23 = __floats2half2_rn((a.z - mean) * inv * g4.z + b4.z,
                                    (a.w - mean) * inv * g4.w + b4.w);
    uint2 o; o.x = *(uint32_t*)&h01; o.y = *(uint32_t*)&h23;
    ((uint2*)(Y + ((size_t)row << 10)))[tid] = o;
}

// ---------------- mma.sync fp16 GEMM (persistent, BK=64, warp tile 64x64) -----
#define PADH  72
#define PADB  144
#define GSTGB (256*PADB)       // A(128 rows x 144B) + B(128 rows x 144B) = 36864B
#define GSMEM (3*GSTGB)
#define GEMM_GRID 296

__device__ __forceinline__ void gcp_stage(
    uint32_t sbase, int s, const __half* __restrict__ A, const __half* __restrict__ Wt,
    int bm, int bn, int K, int k0, int tid)
{
    uint32_t sA = sbase + s * GSTGB;
    uint32_t sB = sA + 128 * PADB;
    #pragma unroll
    for (int e = 0; e < 8; e++) {
        int lin = tid + 128 * e;           // 0..1023 (128 rows x 8 chunks)
        int r = lin >> 3, c = lin & 7;
        cp16(sA + r * PADB + c * 16, A  + (size_t)(bm + r) * K + k0 + c * 8);
        cp16(sB + r * PADB + c * 16, Wt + (size_t)(bn + r) * K + k0 + c * 8);
    }
}

template<bool GELU_, bool RES, bool OUTH>
__global__ __launch_bounds__(128) void tc_gemm(
    const __half* __restrict__ A, const __half* __restrict__ Wt,
    const float* __restrict__ bias, const float* __restrict__ Rp,
    void* __restrict__ Cv, int M, int N, int K)
{
    extern __shared__ __align__(16) char smc[];
    uint32_t sbase = smem_u32(smc);
    const int tid = threadIdx.x, wid = tid >> 5, lid = tid & 31;
    const int g = lid >> 2, t = lid & 3;
    const int warp_m = (wid & 1) * 64, warp_n = (wid >> 1) * 64;
    const int NT = K >> 6;                 // BK=64 stages
    const int mtiles = M >> 7;
    const int total = mtiles * (N >> 7);

    for (int tile = blockIdx.x; tile < total; tile += gridDim.x) {
        const int bm = (tile % mtiles) * 128;
        const int bn = (tile / mtiles) * 128;

        float d[4][8][4];
        #pragma unroll
        for (int i = 0; i < 4; i++)
            #pragma unroll
            for (int j = 0; j < 8; j++)
                #pragma unroll
                for (int p = 0; p < 4; p++) d[i][j][p] = 0.f;

        gcp_stage(sbase, 0, A, Wt, bm, bn, K, 0,  tid); CP_COMMIT();
        gcp_stage(sbase, 1, A, Wt, bm, bn, K, 64, tid); CP_COMMIT();

        for (int kt = 0; kt < NT; kt++) {
            if (kt == NT - 1) { CP_WAIT(0); } else { CP_WAIT(1); }
            __syncthreads();
            if (kt + 2 < NT) {
                gcp_stage(sbase, (kt + 2) % 3, A, Wt, bm, bn, K, (kt + 2) * 64, tid);
                CP_COMMIT();
            }
            const char* As = smc + (size_t)(kt % 3) * GSTGB;
            const char* Bs = As + 128 * PADB;
            #pragma unroll
            for (int ks = 0; ks < 4; ks++) {          // four k16 steps per BK=64
                const int kb = ks * 32 + 4 * t;
                uint32_t af[4][4], bf[8][2];
                #pragma unroll
                for (int mf = 0; mf < 4; mf++) {
                    int rm = warp_m + mf * 16 + g;
                    af[mf][0] = *(const uint32_t*)(As + rm * PADB + kb);
                    af[mf][1] = *(const uint32_t*)(As + (rm + 8) * PADB + kb);
                    af[mf][2] = *(const uint32_t*)(As + rm * PADB + kb + 16);
                    af[mf][3] = *(const uint32_t*)(As + (rm + 8) * PADB + kb + 16);
                }
                #pragma unroll
                for (int nf = 0; nf < 8; nf++) {
                    int rn = warp_n + nf * 8 + g;
                    bf[nf][0] = *(const uint32_t*)(Bs + rn * PADB + kb);
                    bf[nf][1] = *(const uint32_t*)(Bs + rn * PADB + kb + 16);
                }
                #pragma unroll
                for (int mf = 0; mf < 4; mf++)
                    #pragma unroll
                    for (int nf = 0; nf < 8; nf++)
                        mma16(d[mf][nf], af[mf], bf[nf]);
            }
        }
        __syncthreads();   // mainloop reads done before next tile refill

        // epilogue
        #pragma unroll
        for (int mf = 0; mf < 4; mf++) {
            int row0 = bm + warp_m + mf * 16 + g;
            #pragma unroll
            for (int nf = 0; nf < 8; nf++) {
                int col = bn + warp_n + nf * 8 + 2 * t;
                float b0 = __ldg(bias + col), b1 = __ldg(bias + col + 1);
                #pragma unroll
                for (int p = 0; p < 2; p++) {
                    int m = row0 + p * 8;
                    float v0 = d[mf][nf][2 * p + 0] + b0;
                    float v1 = d[mf][nf][2 * p + 1] + b1;
                    if (GELU_) {
                        v0 = 0.5f * v0 * (1.f + erff(v0 * 0.70710678118654752f));
                        v1 = 0.5f * v1 * (1.f + erff(v1 * 0.70710678118654752f));
                    }
                    if (OUTH) {
                        __half2 hp = __floats2half2_rn(v0, v1);
                        *(__half2*)((__half*)Cv + (size_t)m * N + col) = hp;
                    } else {
                        if (RES) {
                            float2 rr = *(const float2*)(Rp + (size_t)m * N + col);
                            v0 += rr.x; v1 += rr.y;
                        }
                        float2 o; o.x = v0; o.y = v1;
                        *(float2*)((float*)Cv + (size_t)m * N + col) = o;
                    }
                }
            }
        }
    }
}

// ---------------- tensor-core flash attention (causal, fp16) ------------------
#define A_QS 0
#define A_KS (128*PADH)
#define A_VS (A_KS + 2*64*PADH)
#define A_ENDH (A_VS + 2*64*PADH)
#define ATT_SMEM (A_ENDH*2)

__global__ __launch_bounds__(256) void attn_tc(
    const __half* __restrict__ QKV, __half* __restrict__ O)
{
    extern __shared__ __align__(16) char smc[];
    __half* sm = (__half*)smc;
    uint32_t sb = smem_u32(smc);
    const int qt = (int)gridDim.x - 1 - (int)blockIdx.x;
    const int h = blockIdx.y, b = blockIdx.z;
    const int tid = threadIdx.x, wid = tid >> 5, lid = tid & 31;
    const int g = lid >> 2, t = lid & 3;
    const int qbase = qt * 128;
    const size_t qkvbase = (size_t)(b * TT) * QKVS + (size_t)h * DD;
    const __half* Q  = QKV + qkvbase;
    const __half* Kp = QKV + qkvbase + 1024;
    const __half* Vp = QKV + qkvbase + 2048;
    const size_t obase = (size_t)(b * TT) * EE + (size_t)h * DD;
    const int lr0 = wid * 16 + g;
    const int nt = 2 * qt + 2;

    #pragma unroll
    for (int i = 0; i < 4; i++) {
        int idx = tid + i * 256;
        int r = idx >> 3, c = idx & 7;
        cp16(sb + (A_QS + r * PADH) * 2 + c * 16, Q + (size_t)(qbase + r) * QKVS + c * 8);
    }
    CP_COMMIT();
    #pragma unroll
    for (int i = 0; i < 4; i++) {
        int idx = tid + i * 256;
        int r = idx >> 4, c = idx & 7, kv = (idx >> 3) & 1;
        uint32_t dst = kv ? (uint32_t)(A_VS + r * PADH) : (uint32_t)(A_KS + r * PADH);
        const __half* src = kv ? Vp : Kp;
        cp16(sb + dst * 2 + c * 16, src + (size_t)r * QKVS + c * 8);
    }
    CP_COMMIT();

    CP_WAIT(1);
    __syncthreads();

    uint32_t aQ[4][4];
    {
        const char* Qs = smc + A_QS * 2;
        #pragma unroll
        for (int ks = 0; ks < 4; ks++) {
            int kb = ks * 32 + 4 * t;
            aQ[ks][0] = *(const uint32_t*)(Qs + lr0 * PADB + kb);
            aQ[ks][1] = *(const uint32_t*)(Qs + (lr0 + 8) * PADB + kb);
            aQ[ks][2] = *(const uint32_t*)(Qs + lr0 * PADB + kb + 16);
            aQ[ks][3] = *(const uint32_t*)(Qs + (lr0 + 8) * PADB + kb + 16);
        }
    }
    __syncthreads();

    float o[8][4];
    #pragma unroll
    for (int nf = 0; nf < 8; nf++) { o[nf][0]=0.f; o[nf][1]=0.f; o[nf][2]=0.f; o[nf][3]=0.f; }
    float m0 = -INFINITY, m1 = -INFINITY, l0 = 0.f, l1 = 0.f;

    for (int kt = 0; kt < nt; kt++) {
        if (kt + 1 < nt) {
            int st = (kt + 1) & 1, kb2 = (kt + 1) * 64;
            #pragma unroll
            for (int i = 0; i < 4; i++) {
                int idx = tid + i * 256;
                int r = idx >> 4, c = idx & 7, kv = (idx >> 3) & 1;
                uint32_t dst = kv ? (uint32_t)(A_VS + st * 64 * PADH + r * PADH)
                                  : (uint32_t)(A_KS + st * 64 * PADH + r * PADH);
                const __half* src = kv ? Vp : Kp;
                cp16(sb + dst * 2 + c * 16, src + (size_t)(kb2 + r) * QKVS + c * 8);
            }
            CP_COMMIT();
            CP_WAIT(1);
        } else { CP_WAIT(0); }
        __syncthreads();

        const int ktb = kt * 64;
        if (ktb <= qbase + wid * 16 + 15) {
            const char* Ks = smc + (A_KS + (kt & 1) * 64 * PADH) * 2;
            const uint32_t Vsb = sb + (A_VS + (kt & 1) * 64 * PADH) * 2;

            float s[8][4];
            #pragma unroll
            for (int nf = 0; nf < 8; nf++) { s[nf][0]=0.f; s[nf][1]=0.f; s[nf][2]=0.f; s[nf][3]=0.f; }
            #pragma unroll
            for (int ks = 0; ks < 4; ks++) {
                int kb = ks * 32 + 4 * t;
                #pragma unroll
                for (int nf = 0; nf < 8; nf++) {
                    uint32_t bf[2];
                    const char* kr = Ks + (nf * 8 + g) * PADB + kb;
                    bf[0] = *(const uint32_t*)kr;
                    bf[1] = *(const uint32_t*)(kr + 16);
                    mma16(s[nf], aQ[ks], bf);
                }
            }
            const int r0 = qbase + lr0, r1 = r0 + 8;
            if (ktb + 63 > qbase + wid * 16) {
                #pragma unroll
                for (int nf = 0; nf < 8; nf++) {
                    int c0 = ktb + nf * 8 + 2 * t;
                    if (c0     > r0) s[nf][0] = -INFINITY;
                    if (c0 + 1 > r0) s[nf][1] = -INFINITY;
                    if (c0     > r1) s[nf][2] = -INFINITY;
                    if (c0 + 1 > r1) s[nf][3] = -INFINITY;
                }
            }
            float mx0 = -INFINITY, mx1 = -INFINITY;
            #pragma unroll
            for (int nf = 0; nf < 8; nf++) {
                mx0 = fmaxf(mx0, fmaxf(s[nf][0], s[nf][1]));
                mx1 = fmaxf(mx1, fmaxf(s[nf][2], s[nf][3]));
            }
            mx0 = fmaxf(mx0, __shfl_xor_sync(0xffffffffu, mx0, 1));
            mx0 = fmaxf(mx0, __shfl_xor_sync(0xffffffffu, mx0, 2));
            mx1 = fmaxf(mx1, __shfl_xor_sync(0xffffffffu, mx1, 1));
            mx1 = fmaxf(mx1, __shfl_xor_sync(0xffffffffu, mx1, 2));
            float nm0 = fmaxf(m0, mx0), nm1 = fmaxf(m1, mx1);
            float scl0 = exp2f(m0 - nm0), scl1 = exp2f(m1 - nm1);

            __half* Ps = sm + A_QS;
            float ls0 = 0.f, ls1 = 0.f;
            #pragma unroll
            for (int nf = 0; nf < 8; nf++) {
                float p0 = exp2f(s[nf][0] - nm0);
                float p1 = exp2f(s[nf][1] - nm0);
                float p2 = exp2f(s[nf][2] - nm1);
                float p3 = exp2f(s[nf][3] - nm1);
                ls0 += p0 + p1; ls1 += p2 + p3;
                *(__half2*)&Ps[lr0 * PADH + nf * 8 + 2 * t] = __floats2half2_rn(p0, p1);
                *(__half2*)&Ps[(lr0 + 8) * PADH + nf * 8 + 2 * t] = __floats2half2_rn(p2, p3);
            }
            ls0 += __shfl_xor_sync(0xffffffffu, ls0, 1);
            ls0 += __shfl_xor_sync(0xffffffffu, ls0, 2);
            ls1 += __shfl_xor_sync(0xffffffffu, ls1, 1);
            ls1 += __shfl_xor_sync(0xffffffffu, ls1, 2);
            l0 = l0 * scl0 + ls0; l1 = l1 * scl1 + ls1;
            #pragma unroll
            for (int nf = 0; nf < 8; nf++) {
                o[nf][0] *= scl0; o[nf][1] *= scl0; o[nf][2] *= scl1; o[nf][3] *= scl1;
            }
            __syncwarp();
            const char* Pc = smc + A_QS * 2;
            const int lmq = lid >> 3, lmr = lid & 7;
            #pragma unroll
            for (int ks = 0; ks < 4; ks++) {
                int kb = ks * 32 + 4 * t;
                uint32_t ap[4];
                ap[0] = *(const uint32_t*)(Pc + lr0 * PADB + kb);
                ap[1] = *(const uint32_t*)(Pc + (lr0 + 8) * PADB + kb);
                ap[2] = *(const uint32_t*)(Pc + lr0 * PADB + kb + 16);
                ap[3] = *(const uint32_t*)(Pc + (lr0 + 8) * PADB + kb + 16);
                #pragma unroll
                for (int nf2 = 0; nf2 < 4; nf2++) {
                    int s_off = ks * 16 + (lmq & 1) * 8 + lmr;
                    int d_off = nf2 * 16 + (lmq >> 1) * 8;
                    uint32_t r0v, r1v, r2v, r3v;
                    ldmx4t(r0v, r1v, r2v, r3v, Vsb + (s_off * PADH + d_off) * 2);
                    uint32_t bfa[2] = { r0v, r1v };
                    uint32_t bfb[2] = { r2v, r3v };
                    mma16(o[nf2 * 2],     ap, bfa);
                    mma16(o[nf2 * 2 + 1], ap, bfb);
                }
            }
            m0 = nm0; m1 = nm1;
        }
        __syncthreads();
    }

    float inv0 = 1.f / l0, inv1 = 1.f / l1;
    #pragma unroll
    for (int nf = 0; nf < 8; nf++) {
        int c = nf * 8 + 2 * t;
        *(__half2*)(O + obase + (size_t)(qbase + lr0) * EE + c) =
            __floats2half2_rn(o[nf][0] * inv0, o[nf][1] * inv0);
        *(__half2*)(O + obase + (size_t)(qbase + lr0 + 8) * EE + c) =
            __floats2half2_rn(o[nf][2] * inv1, o[nf][3] * inv1);
    }
}

// ---------------- launch ------------------------------------------------------
extern "C" void kernel_launch(void* const* d_in, const int* in_sizes, int n_in,
                              void* d_out, int out_size)
{
    const int*   ids   = (const int*)  d_in[0];
    const float* wte   = (const float*)d_in[1];
    const float* wpe   = (const float*)d_in[2];
    const float* wq    = (const float*)d_in[3];
    const float* wk    = (const float*)d_in[4];
    const float* wv    = (const float*)d_in[5];
    const float* bq    = (const float*)d_in[6];
    const float* bk    = (const float*)d_in[7];
    const float* bv    = (const float*)d_in[8];
    const float* wproj = (const float*)d_in[9];
    const float* bproj = (const float*)d_in[10];
    const float* ln1g  = (const float*)d_in[11];
    const float* ln1b  = (const float*)d_in[12];
    const float* ln2g  = (const float*)d_in[13];
    const float* ln2b  = (const float*)d_in[14];
    const float* wfc   = (const float*)d_in[15];
    const float* bfc   = (const float*)d_in[16];
    const float* wout  = (const float*)d_in[17];
    const float* bout  = (const float*)d_in[18];
    float* out = (float*)d_out;

    float *x, *x2, *bqkv;
    __half *h, *qkv, *o, *mb;
    __half *wtqkv, *wtp, *wtfc, *wtout;
    cudaGetSymbolAddress((void**)&x,  g_x);
    cudaGetSymbolAddress((void**)&x2, g_x2);
    cudaGetSymbolAddress((void**)&h,  g_h);
    cudaGetSymbolAddress((void**)&qkv, g_qkv);
    cudaGetSymbolAddress((void**)&o,  g_o);
    cudaGetSymbolAddress((void**)&mb, g_m);
    cudaGetSymbolAddress((void**)&wtqkv, g_wtqkv);
    cudaGetSymbolAddress((void**)&bqkv,  g_bqkv);
    cudaGetSymbolAddress((void**)&wtp,   g_wtp);
    cudaGetSymbolAddress((void**)&wtfc,  g_wtfc);
    cudaGetSymbolAddress((void**)&wtout, g_wtout);

    cudaFuncSetAttribute(attn_tc, cudaFuncAttributeMaxDynamicSharedMemorySize, ATT_SMEM);
    cudaFuncSetAttribute(tc_gemm<false,false,true>,  cudaFuncAttributeMaxDynamicSharedMemorySize, GSMEM);
    cudaFuncSetAttribute(tc_gemm<false,true,false>,  cudaFuncAttributeMaxDynamicSharedMemorySize, GSMEM);
    cudaFuncSetAttribute(tc_gemm<true,false,true>,   cudaFuncAttributeMaxDynamicSharedMemorySize, GSMEM);

    const float alpha = 0.18033688011112042f;   // 0.125 * log2(e)

    // 0. fused prep: embed+ln1 + all weight transposes + bias merge
    prep_kernel<<<20492, 256>>>(ids, wte, wpe, ln1g, ln1b,
                                wq, wk, wv, bq, bk, bv,
                                wproj, wfc, wout,
                                x, h, wtqkv, bqkv, wtp, wtfc, wtout, alpha);
    // 1. merged qkv projection (N=3072)
    tc_gemm<false,false,true><<<GEMM_GRID, 128, GSMEM>>>(h, wtqkv, bqkv, nullptr, qkv, MM, QKVS, EE);
    // 2. causal flash attention
    attn_tc<<<dim3(TT / 128, HH, BB), 256, ATT_SMEM>>>(qkv, o);
    // 3. proj + residual -> x2
    tc_gemm<false,true,false><<<GEMM_GRID, 128, GSMEM>>>(o, wtp, bproj, x, x2, MM, EE, EE);
    // 4. ln2
    ln_kernel<<<MM, 256>>>(x2, ln2g, ln2b, h);
    // 5. fc + gelu -> m
    tc_gemm<true,false,true><<<GEMM_GRID, 128, GSMEM>>>(h, wtfc, bfc, nullptr, mb, MM, FF, EE);
    // 6. out proj + residual -> d_out
    tc_gemm<false,true,false><<<GEMM_GRID, 128, GSMEM>>>(mb, wtout, bout, x2, out, MM, EE, FF);
}

// round 10
// speedup vs baseline: 8.6941x; 1.0939x over previous
#include <cuda_runtime.h>
#include <cuda_fp16.h>
#include <math.h>
#include <stdint.h>

// Problem constants
#define BB 4
#define TT 2048
#define EE 1024
#define HH 16
#define DD 64
#define MM (BB*TT)        // 8192
#define FF (4*EE)         // 4096
#define QKVS 3072         // merged qkv row stride

// ---------------- scratch (device globals; no allocation allowed) -------------
__device__ float  g_x [MM*EE];               // residual stream (fp32)
__device__ float  g_x2[MM*EE];
__device__ __half g_h [MM*EE];               // LN output (GEMM A)
__device__ __half g_qkv[(size_t)MM*QKVS];    // q|k|v merged (q pre-scaled)
__device__ __half g_o [MM*EE];               // attention output
__device__ __half g_m [(size_t)MM*FF];       // gelu(fc)
// pre-transposed weights (K-major [N,K], fp16)
__device__ __half g_wtqkv[(size_t)QKVS*EE];  // [3072,1024] (q rows pre-scaled)
__device__ float  g_bqkv [QKVS];             // merged bias (q pre-scaled)
__device__ __half g_wtp [EE*EE];
__device__ __half g_wtfc [(size_t)FF*EE];
__device__ __half g_wtout[(size_t)EE*FF];

// ---------------- helpers -----------------------------------------------------
__device__ __forceinline__ uint32_t smem_u32(const void* p) {
    uint32_t a;
    asm("{ .reg .u64 t; cvta.to.shared.u64 t, %1; cvt.u32.u64 %0, t; }" : "=r"(a) : "l"(p));
    return a;
}
__device__ __forceinline__ void cp16(uint32_t dst, const void* src) {
    asm volatile("cp.async.cg.shared.global [%0], [%1], 16;" :: "r"(dst), "l"(src));
}
#define CP_COMMIT() asm volatile("cp.async.commit_group;" ::: "memory")
#define CP_WAIT(n)  asm volatile("cp.async.wait_group %0;" :: "n"(n) : "memory")

// mma.sync m16n8k16 fp16 inputs, fp32 accumulate (sm_80+ base-target)
__device__ __forceinline__ void mma16(float* d, const uint32_t* a, const uint32_t* b) {
    asm volatile("mma.sync.aligned.m16n8k16.row.col.f32.f16.f16.f32 "
        "{%0,%1,%2,%3}, {%4,%5,%6,%7}, {%8,%9}, {%0,%1,%2,%3};"
        : "+f"(d[0]), "+f"(d[1]), "+f"(d[2]), "+f"(d[3])
        : "r"(a[0]), "r"(a[1]), "r"(a[2]), "r"(a[3]), "r"(b[0]), "r"(b[1]));
}
__device__ __forceinline__ void ldmx4(uint32_t& r0, uint32_t& r1, uint32_t& r2,
                                      uint32_t& r3, uint32_t addr) {
    asm volatile("ldmatrix.sync.aligned.m8n8.x4.shared.b16 {%0,%1,%2,%3}, [%4];"
        : "=r"(r0), "=r"(r1), "=r"(r2), "=r"(r3) : "r"(addr));
}
__device__ __forceinline__ void ldmx4t(uint32_t& r0, uint32_t& r1, uint32_t& r2,
                                       uint32_t& r3, uint32_t addr) {
    asm volatile("ldmatrix.sync.aligned.m8n8.x4.trans.shared.b16 {%0,%1,%2,%3}, [%4];"
        : "=r"(r0), "=r"(r1), "=r"(r2), "=r"(r3) : "r"(addr));
}

// ---------------- fused prep kernel -------------------------------------------
// blocks [0,8192): embed+ln1     [8192,11264): qkv weight transpose
// [11264,11276): bias merge      [11276,20492): proj/fc/out transposes
__global__ __launch_bounds__(256) void prep_kernel(
    const int* __restrict__ ids, const float* __restrict__ wte,
    const float* __restrict__ wpe, const float* __restrict__ ln1g,
    const float* __restrict__ ln1b,
    const float* __restrict__ Wq, const float* __restrict__ Wk,
    const float* __restrict__ Wv, const float* __restrict__ bq,
    const float* __restrict__ bk, const float* __restrict__ bv,
    const float* __restrict__ Wp, const float* __restrict__ Wf,
    const float* __restrict__ Wo,
    float* __restrict__ X, __half* __restrict__ Y,
    __half* __restrict__ Wtqkv, float* __restrict__ bqkv,
    __half* __restrict__ Tp, __half* __restrict__ Tf, __half* __restrict__ To,
    float alpha)
{
    __shared__ float sh[32 * 33];
    const int bid = blockIdx.x, tid = threadIdx.x;

    if (bid < 8192) {
        // ---- embed + ln1 ----
        int row = bid;
        int t   = row & (TT - 1);
        int id  = ids[row];
        float4 a = ((const float4*)wte)[(size_t)id * 256 + tid];
        float4 p = ((const float4*)wpe)[(size_t)t  * 256 + tid];
        a.x += p.x; a.y += p.y; a.z += p.z; a.w += p.w;
        ((float4*)(X + ((size_t)row << 10)))[tid] = a;

        float s  = a.x + a.y + a.z + a.w;
        float sq = a.x*a.x + a.y*a.y + a.z*a.z + a.w*a.w;
        #pragma unroll
        for (int o = 16; o; o >>= 1) {
            s  += __shfl_xor_sync(0xffffffffu, s,  o);
            sq += __shfl_xor_sync(0xffffffffu, sq, o);
        }
        if ((tid & 31) == 0) { sh[tid >> 5] = s; sh[8 + (tid >> 5)] = sq; }
        __syncthreads();
        float ts = 0.f, tq = 0.f;
        #pragma unroll
        for (int i = 0; i < 8; i++) { ts += sh[i]; tq += sh[8 + i]; }
        float mean = ts * (1.f / 1024.f);
        float var  = tq * (1.f / 1024.f) - mean * mean;
        float inv  = rsqrtf(var + 1e-5f);
        float4 g4 = ((const float4*)ln1g)[tid];
        float4 b4 = ((const float4*)ln1b)[tid];
        __half2 h01 = __floats2half2_rn((a.x - mean) * inv * g4.x + b4.x,
                                        (a.y - mean) * inv * g4.y + b4.y);
        __half2 h23 = __floats2half2_rn((a.z - mean) * inv * g4.z + b4.z,
                                        (a.w - mean) * inv * g4.w + b4.w);
        uint2 o; o.x = *(uint32_t*)&h01; o.y = *(uint32_t*)&h23;
        ((uint2*)(Y + ((size_t)row << 10)))[tid] = o;
    } else if (bid < 11264) {
        // ---- qkv weight transpose (q section scaled by alpha) ----
        int b2 = bid - 8192;
        int bx = b2 & 1, by = (b2 >> 1) & 31, bz = b2 >> 6;
        int sec = bz >> 4, h = bz & 15;
        int k0 = by * 32, d0 = bx * 32;
        const float* W = (sec == 0) ? Wq : (sec == 1) ? Wk : Wv;
        float sc = (sec == 0) ? alpha : 1.f;
        const float* Wh = W + (size_t)h * EE * DD;
        int tx = tid & 31, ty = tid >> 5;
        #pragma unroll
        for (int i = ty; i < 32; i += 8) sh[i * 33 + tx] = Wh[(size_t)(k0 + i) * DD + d0 + tx];
        __syncthreads();
        #pragma unroll
        for (int i = ty; i < 32; i += 8)
            Wtqkv[(size_t)(sec * 1024 + h * DD + d0 + i) * EE + k0 + tx] =
                __float2half_rn(sh[tx * 33 + i] * sc);
    } else if (bid < 11276) {
        // ---- bias merge ----
        int i = (bid - 11264) * 256 + tid;     // 0..3071
        int sec = i >> 10, j = i & 1023;
        float v = (sec == 0) ? bq[j] * alpha : (sec == 1) ? bk[j] : bv[j];
        bqkv[i] = v;
    } else {
        // ---- proj / fc / out transposes ----
        int b3 = bid - 11276;
        const float* W; __half* Wt; int K, N, n0, k0;
        if (b3 < 1024) {
            W = Wp; Wt = Tp; K = 1024; N = 1024;
            n0 = (b3 & 31) * 32; k0 = (b3 >> 5) * 32;
        } else if (b3 < 5120) {
            int b = b3 - 1024;
            W = Wf; Wt = Tf; K = 1024; N = 4096;
            n0 = (b & 127) * 32; k0 = (b >> 7) * 32;
        } else {
            int b = b3 - 5120;
            W = Wo; Wt = To; K = 4096; N = 1024;
            n0 = (b & 31) * 32; k0 = (b >> 5) * 32;
        }
        int tx = tid & 31, ty = tid >> 5;
        #pragma unroll
        for (int i = ty; i < 32; i += 8) sh[i * 33 + tx] = W[(size_t)(k0 + i) * N + n0 + tx];
        __syncthreads();
        #pragma unroll
        for (int i = ty; i < 32; i += 8)
            Wt[(size_t)(n0 + i) * K + k0 + tx] = __float2half_rn(sh[tx * 33 + i]);
    }
}

// ---------------- layernorm (fp32 in, fp16 out) -------------------------------
__global__ __launch_bounds__(256) void ln_kernel(
    const float* __restrict__ X, const float* __restrict__ G,
    const float* __restrict__ Bt, __half* __restrict__ Y)
{
    __shared__ float red[16];
    int row = blockIdx.x, tid = threadIdx.x;
    const float4* x4 = (const float4*)(X + ((size_t)row << 10));
    float4 a = x4[tid];
    float s  = a.x + a.y + a.z + a.w;
    float sq = a.x*a.x + a.y*a.y + a.z*a.z + a.w*a.w;
    #pragma unroll
    for (int o = 16; o; o >>= 1) {
        s  += __shfl_xor_sync(0xffffffffu, s,  o);
        sq += __shfl_xor_sync(0xffffffffu, sq, o);
    }
    if ((tid & 31) == 0) { red[tid >> 5] = s; red[8 + (tid >> 5)] = sq; }
    __syncthreads();
    float ts = 0.f, tq = 0.f;
    #pragma unroll
    for (int i = 0; i < 8; i++) { ts += red[i]; tq += red[8 + i]; }
    float mean = ts * (1.f / 1024.f);
    float var  = tq * (1.f / 1024.f) - mean * mean;
    float inv  = rsqrtf(var + 1e-5f);
    float4 g4 = ((const float4*)G)[tid];
    float4 b4 = ((const float4*)Bt)[tid];
    __half2 h01 = __floats2half2_rn((a.x - mean) * inv * g4.x + b4.x,
                                    (a.y - mean) * inv * g4.y + b4.y);
    __half2 h23 = __floats2half2_rn((a.z - mean) * inv * g4.z + b4.z,
                                    (a.w - mean) * inv * g4.w + b4.w);
    uint2 o; o.x = *(uint32_t*)&h01; o.y = *(uint32_t*)&h23;
    ((uint2*)(Y + ((size_t)row << 10)))[tid] = o;
}

// ---------------- mma.sync fp16 GEMM (persistent, BK=64, ldmatrix frags) ------
#define PADH  72
#define PADB  144
#define GSTGB (256*PADB)       // A(128 rows x 144B) + B(128 rows x 144B) = 36864B
#define GSMEM (3*GSTGB)
#define GEMM_GRID 296

__device__ __forceinline__ void gcp_stage(
    uint32_t sbase, int s, const __half* __restrict__ A, const __half* __restrict__ Wt,
    int bm, int bn, int K, int k0, int tid)
{
    uint32_t sA = sbase + s * GSTGB;
    uint32_t sB = sA + 128 * PADB;
    #pragma unroll
    for (int e = 0; e < 8; e++) {
        int lin = tid + 128 * e;           // 0..1023 (128 rows x 8 chunks)
        int r = lin >> 3, c = lin & 7;
        cp16(sA + r * PADB + c * 16, A  + (size_t)(bm + r) * K + k0 + c * 8);
        cp16(sB + r * PADB + c * 16, Wt + (size_t)(bn + r) * K + k0 + c * 8);
    }
}

template<bool GELU_, bool RES, bool OUTH>
__global__ __launch_bounds__(128) void tc_gemm(
    const __half* __restrict__ A, const __half* __restrict__ Wt,
    const float* __restrict__ bias, const float* __restrict__ Rp,
    void* __restrict__ Cv, int M, int N, int K)
{
    extern __shared__ __align__(16) char smc[];
    uint32_t sbase = smem_u32(smc);
    const int tid = threadIdx.x, wid = tid >> 5, lid = tid & 31;
    const int g = lid >> 2, t = lid & 3;
    const int warp_m = (wid & 1) * 64, warp_n = (wid >> 1) * 64;
    const int NT = K >> 6;                 // BK=64 stages
    const int mtiles = M >> 7;
    const int total = mtiles * (N >> 7);

    // per-lane ldmatrix base offsets (within a stage)
    const uint32_t aOff = (uint32_t)((warp_m + (lid & 15)) * PADB + (lid >> 4) * 16);
    const uint32_t bOff = (uint32_t)(128 * PADB +
        (warp_n + (lid & 7) + ((lid & 16) ? 8 : 0)) * PADB + ((lid >> 3) & 1) * 16);

    for (int tile = blockIdx.x; tile < total; tile += gridDim.x) {
        const int bm = (tile % mtiles) * 128;
        const int bn = (tile / mtiles) * 128;

        float d[4][8][4];
        #pragma unroll
        for (int i = 0; i < 4; i++)
            #pragma unroll
            for (int j = 0; j < 8; j++)
                #pragma unroll
                for (int p = 0; p < 4; p++) d[i][j][p] = 0.f;

        gcp_stage(sbase, 0, A, Wt, bm, bn, K, 0,  tid); CP_COMMIT();
        gcp_stage(sbase, 1, A, Wt, bm, bn, K, 64, tid); CP_COMMIT();

        for (int kt = 0; kt < NT; kt++) {
            if (kt == NT - 1) { CP_WAIT(0); } else { CP_WAIT(1); }
            __syncthreads();
            if (kt + 2 < NT) {
                gcp_stage(sbase, (kt + 2) % 3, A, Wt, bm, bn, K, (kt + 2) * 64, tid);
                CP_COMMIT();
            }
            const uint32_t stg = sbase + (uint32_t)((kt % 3) * GSTGB);
            #pragma unroll
            for (int ks = 0; ks < 4; ks++) {          // four k16 steps per BK=64
                const uint32_t kb = ks * 32;
                uint32_t af[4][4], bf[8][2];
                #pragma unroll
                for (int mf = 0; mf < 4; mf++)
                    ldmx4(af[mf][0], af[mf][1], af[mf][2], af[mf][3],
                          stg + aOff + mf * 16 * PADB + kb);
                #pragma unroll
                for (int np = 0; np < 4; np++)
                    ldmx4(bf[2*np][0], bf[2*np][1], bf[2*np+1][0], bf[2*np+1][1],
                          stg + bOff + np * 16 * PADB + kb);
                #pragma unroll
                for (int mf = 0; mf < 4; mf++)
                    #pragma unroll
                    for (int nf = 0; nf < 8; nf++)
                        mma16(d[mf][nf], af[mf], bf[nf]);
            }
        }
        __syncthreads();   // mainloop reads done before next tile refill

        // epilogue
        #pragma unroll
        for (int mf = 0; mf < 4; mf++) {
            int row0 = bm + warp_m + mf * 16 + g;
            #pragma unroll
            for (int nf = 0; nf < 8; nf++) {
                int col = bn + warp_n + nf * 8 + 2 * t;
                float b0 = __ldg(bias + col), b1 = __ldg(bias + col + 1);
                #pragma unroll
                for (int p = 0; p < 2; p++) {
                    int m = row0 + p * 8;
                    float v0 = d[mf][nf][2 * p + 0] + b0;
                    float v1 = d[mf][nf][2 * p + 1] + b1;
                    if (GELU_) {
                        v0 = 0.5f * v0 * (1.f + erff(v0 * 0.70710678118654752f));
                        v1 = 0.5f * v1 * (1.f + erff(v1 * 0.70710678118654752f));
                    }
                    if (OUTH) {
                        __half2 hp = __floats2half2_rn(v0, v1);
                        *(__half2*)((__half*)Cv + (size_t)m * N + col) = hp;
                    } else {
                        if (RES) {
                            float2 rr = *(const float2*)(Rp + (size_t)m * N + col);
                            v0 += rr.x; v1 += rr.y;
                        }
                        float2 o; o.x = v0; o.y = v1;
                        *(float2*)((float*)Cv + (size_t)m * N + col) = o;
                    }
                }
            }
        }
    }
}

// ---------------- tensor-core flash attention (causal, fp16) ------------------
#define A_QS 0
#define A_KS (128*PADH)
#define A_VS (A_KS + 2*64*PADH)
#define A_ENDH (A_VS + 2*64*PADH)
#define ATT_SMEM (A_ENDH*2)

__global__ __launch_bounds__(256) void attn_tc(
    const __half* __restrict__ QKV, __half* __restrict__ O)
{
    extern __shared__ __align__(16) char smc[];
    __half* sm = (__half*)smc;
    uint32_t sb = smem_u32(smc);
    const int qt = (int)gridDim.x - 1 - (int)blockIdx.x;
    const int h = blockIdx.y, b = blockIdx.z;
    const int tid = threadIdx.x, wid = tid >> 5, lid = tid & 31;
    const int g = lid >> 2, t = lid & 3;
    const int qbase = qt * 128;
    const size_t qkvbase = (size_t)(b * TT) * QKVS + (size_t)h * DD;
    const __half* Q  = QKV + qkvbase;
    const __half* Kp = QKV + qkvbase + 1024;
    const __half* Vp = QKV + qkvbase + 2048;
    const size_t obase = (size_t)(b * TT) * EE + (size_t)h * DD;
    const int lr0 = wid * 16 + g;
    const int nt = 2 * qt + 2;

    // A-pattern ldmatrix per-lane offset (for Q and P tiles; row = wid*16 + (lid&15))
    const uint32_t apOff = (uint32_t)((wid * 16 + (lid & 15)) * PADB + (lid >> 4) * 16);
    // B-pattern ldmatrix per-lane offset (for K tiles)
    const uint32_t bkOff = (uint32_t)(((lid & 7) + ((lid & 16) ? 8 : 0)) * PADB
                                      + ((lid >> 3) & 1) * 16);

    #pragma unroll
    for (int i = 0; i < 4; i++) {
        int idx = tid + i * 256;
        int r = idx >> 3, c = idx & 7;
        cp16(sb + (A_QS + r * PADH) * 2 + c * 16, Q + (size_t)(qbase + r) * QKVS + c * 8);
    }
    CP_COMMIT();
    #pragma unroll
    for (int i = 0; i < 4; i++) {
        int idx = tid + i * 256;
        int r = idx >> 4, c = idx & 7, kv = (idx >> 3) & 1;
        uint32_t dst = kv ? (uint32_t)(A_VS + r * PADH) : (uint32_t)(A_KS + r * PADH);
        const __half* src = kv ? Vp : Kp;
        cp16(sb + dst * 2 + c * 16, src + (size_t)r * QKVS + c * 8);
    }
    CP_COMMIT();

    CP_WAIT(1);
    __syncthreads();

    uint32_t aQ[4][4];
    #pragma unroll
    for (int ks = 0; ks < 4; ks++)
        ldmx4(aQ[ks][0], aQ[ks][1], aQ[ks][2], aQ[ks][3],
              sb + A_QS * 2 + apOff + ks * 32);
    __syncthreads();

    float o[8][4];
    #pragma unroll
    for (int nf = 0; nf < 8; nf++) { o[nf][0]=0.f; o[nf][1]=0.f; o[nf][2]=0.f; o[nf][3]=0.f; }
    float m0 = -INFINITY, m1 = -INFINITY, l0 = 0.f, l1 = 0.f;

    for (int kt = 0; kt < nt; kt++) {
        if (kt + 1 < nt) {
            int st = (kt + 1) & 1, kb2 = (kt + 1) * 64;
            #pragma unroll
            for (int i = 0; i < 4; i++) {
                int idx = tid + i * 256;
                int r = idx >> 4, c = idx & 7, kv = (idx >> 3) & 1;
                uint32_t dst = kv ? (uint32_t)(A_VS + st * 64 * PADH + r * PADH)
                                  : (uint32_t)(A_KS + st * 64 * PADH + r * PADH);
                const __half* src = kv ? Vp : Kp;
                cp16(sb + dst * 2 + c * 16, src + (size_t)(kb2 + r) * QKVS + c * 8);
            }
            CP_COMMIT();
            CP_WAIT(1);
        } else { CP_WAIT(0); }
        __syncthreads();

        const int ktb = kt * 64;
        if (ktb <= qbase + wid * 16 + 15) {
            const uint32_t Ksb = sb + (A_KS + (kt & 1) * 64 * PADH) * 2;
            const uint32_t Vsb = sb + (A_VS + (kt & 1) * 64 * PADH) * 2;

            float s[8][4];
            #pragma unroll
            for (int nf = 0; nf < 8; nf++) { s[nf][0]=0.f; s[nf][1]=0.f; s[nf][2]=0.f; s[nf][3]=0.f; }
            #pragma unroll
            for (int ks = 0; ks < 4; ks++) {
                #pragma unroll
                for (int np = 0; np < 4; np++) {
                    uint32_t bf0[2], bf1[2];
                    ldmx4(bf0[0], bf0[1], bf1[0], bf1[1],
                          Ksb + bkOff + np * 16 * PADB + ks * 32);
                    mma16(s[2*np],   aQ[ks], bf0);
                    mma16(s[2*np+1], aQ[ks], bf1);
                }
            }
            const int r0 = qbase + lr0, r1 = r0 + 8;
            if (ktb + 63 > qbase + wid * 16) {
                #pragma unroll
                for (int nf = 0; nf < 8; nf++) {
                    int c0 = ktb + nf * 8 + 2 * t;
                    if (c0     > r0) s[nf][0] = -INFINITY;
                    if (c0 + 1 > r0) s[nf][1] = -INFINITY;
                    if (c0     > r1) s[nf][2] = -INFINITY;
                    if (c0 + 1 > r1) s[nf][3] = -INFINITY;
                }
            }
            float mx0 = -INFINITY, mx1 = -INFINITY;
            #pragma unroll
            for (int nf = 0; nf < 8; nf++) {
                mx0 = fmaxf(mx0, fmaxf(s[nf][0], s[nf][1]));
                mx1 = fmaxf(mx1, fmaxf(s[nf][2], s[nf][3]));
            }
            mx0 = fmaxf(mx0, __shfl_xor_sync(0xffffffffu, mx0, 1));
            mx0 = fmaxf(mx0, __shfl_xor_sync(0xffffffffu, mx0, 2));
            mx1 = fmaxf(mx1, __shfl_xor_sync(0xffffffffu, mx1, 1));
            mx1 = fmaxf(mx1, __shfl_xor_sync(0xffffffffu, mx1, 2));
            float nm0 = fmaxf(m0, mx0), nm1 = fmaxf(m1, mx1);
            float scl0 = exp2f(m0 - nm0), scl1 = exp2f(m1 - nm1);

            __half* Ps = sm + A_QS;
            float ls0 = 0.f, ls1 = 0.f;
            #pragma unroll
            for (int nf = 0; nf < 8; nf++) {
                float p0 = exp2f(s[nf][0] - nm0);
                float p1 = exp2f(s[nf][1] - nm0);
                float p2 = exp2f(s[nf][2] - nm1);
                float p3 = exp2f(s[nf][3] - nm1);
                ls0 += p0 + p1; ls1 += p2 + p3;
                *(__half2*)&Ps[lr0 * PADH + nf * 8 + 2 * t] = __floats2half2_rn(p0, p1);
                *(__half2*)&Ps[(lr0 + 8) * PADH + nf * 8 + 2 * t] = __floats2half2_rn(p2, p3);
            }
            ls0 += __shfl_xor_sync(0xffffffffu, ls0, 1);
            ls0 += __shfl_xor_sync(0xffffffffu, ls0, 2);
            ls1 += __shfl_xor_sync(0xffffffffu, ls1, 1);
            ls1 += __shfl_xor_sync(0xffffffffu, ls1, 2);
            l0 = l0 * scl0 + ls0; l1 = l1 * scl1 + ls1;
            #pragma unroll
            for (int nf = 0; nf < 8; nf++) {
                o[nf][0] *= scl0; o[nf][1] *= scl0; o[nf][2] *= scl1; o[nf][3] *= scl1;
            }
            __syncwarp();
            const int lmq = lid >> 3, lmr = lid & 7;
            #pragma unroll
            for (int ks = 0; ks < 4; ks++) {
                uint32_t ap[4];
                ldmx4(ap[0], ap[1], ap[2], ap[3],
                      sb + A_QS * 2 + apOff + ks * 32);
                #pragma unroll
                for (int nf2 = 0; nf2 < 4; nf2++) {
                    int s_off = ks * 16 + (lmq & 1) * 8 + lmr;
                    int d_off = nf2 * 16 + (lmq >> 1) * 8;
                    uint32_t r0v, r1v, r2v, r3v;
                    ldmx4t(r0v, r1v, r2v, r3v, Vsb + (s_off * PADH + d_off) * 2);
                    uint32_t bfa[2] = { r0v, r1v };
                    uint32_t bfb[2] = { r2v, r3v };
                    mma16(o[nf2 * 2],     ap, bfa);
                    mma16(o[nf2 * 2 + 1], ap, bfb);
                }
            }
            m0 = nm0; m1 = nm1;
        }
        __syncthreads();
    }

    float inv0 = 1.f / l0, inv1 = 1.f / l1;
    #pragma unroll
    for (int nf = 0; nf < 8; nf++) {
        int c = nf * 8 + 2 * t;
        *(__half2*)(O + obase + (size_t)(qbase + lr0) * EE + c) =
            __floats2half2_rn(o[nf][0] * inv0, o[nf][1] * inv0);
        *(__half2*)(O + obase + (size_t)(qbase + lr0 + 8) * EE + c) =
            __floats2half2_rn(o[nf][2] * inv1, o[nf][3] * inv1);
    }
}

// ---------------- launch ------------------------------------------------------
extern "C" void kernel_launch(void* const* d_in, const int* in_sizes, int n_in,
                              void* d_out, int out_size)
{
    const int*   ids   = (const int*)  d_in[0];
    const float* wte   = (const float*)d_in[1];
    const float* wpe   = (const float*)d_in[2];
    const float* wq    = (const float*)d_in[3];
    const float* wk    = (const float*)d_in[4];
    const float* wv    = (const float*)d_in[5];
    const float* bq    = (const float*)d_in[6];
    const float* bk    = (const float*)d_in[7];
    const float* bv    = (const float*)d_in[8];
    const float* wproj = (const float*)d_in[9];
    const float* bproj = (const float*)d_in[10];
    const float* ln1g  = (const float*)d_in[11];
    const float* ln1b  = (const float*)d_in[12];
    const float* ln2g  = (const float*)d_in[13];
    const float* ln2b  = (const float*)d_in[14];
    const float* wfc   = (const float*)d_in[15];
    const float* bfc   = (const float*)d_in[16];
    const float* wout  = (const float*)d_in[17];
    const float* bout  = (const float*)d_in[18];
    float* out = (float*)d_out;

    float *x, *x2, *bqkv;
    __half *h, *qkv, *o, *mb;
    __half *wtqkv, *wtp, *wtfc, *wtout;
    cudaGetSymbolAddress((void**)&x,  g_x);
    cudaGetSymbolAddress((void**)&x2, g_x2);
    cudaGetSymbolAddress((void**)&h,  g_h);
    cudaGetSymbolAddress((void**)&qkv, g_qkv);
    cudaGetSymbolAddress((void**)&o,  g_o);
    cudaGetSymbolAddress((void**)&mb, g_m);
    cudaGetSymbolAddress((void**)&wtqkv, g_wtqkv);
    cudaGetSymbolAddress((void**)&bqkv,  g_bqkv);
    cudaGetSymbolAddress((void**)&wtp,   g_wtp);
    cudaGetSymbolAddress((void**)&wtfc,  g_wtfc);
    cudaGetSymbolAddress((void**)&wtout, g_wtout);

    cudaFuncSetAttribute(attn_tc, cudaFuncAttributeMaxDynamicSharedMemorySize, ATT_SMEM);
    cudaFuncSetAttribute(tc_gemm<false,false,true>,  cudaFuncAttributeMaxDynamicSharedMemorySize, GSMEM);
    cudaFuncSetAttribute(tc_gemm<false,true,false>,  cudaFuncAttributeMaxDynamicSharedMemorySize, GSMEM);
    cudaFuncSetAttribute(tc_gemm<true,false,true>,   cudaFuncAttributeMaxDynamicSharedMemorySize, GSMEM);

    const float alpha = 0.18033688011112042f;   // 0.125 * log2(e)

    // 0. fused prep: embed+ln1 + all weight transposes + bias merge
    prep_kernel<<<20492, 256>>>(ids, wte, wpe, ln1g, ln1b,
                                wq, wk, wv, bq, bk, bv,
                                wproj, wfc, wout,
                                x, h, wtqkv, bqkv, wtp, wtfc, wtout, alpha);
    // 1. merged qkv projection (N=3072)
    tc_gemm<false,false,true><<<GEMM_GRID, 128, GSMEM>>>(h, wtqkv, bqkv, nullptr, qkv, MM, QKVS, EE);
    // 2. causal flash attention
    attn_tc<<<dim3(TT / 128, HH, BB), 256, ATT_SMEM>>>(qkv, o);
    // 3. proj + residual -> x2
    tc_gemm<false,true,false><<<GEMM_GRID, 128, GSMEM>>>(o, wtp, bproj, x, x2, MM, EE, EE);
    // 4. ln2
    ln_kernel<<<MM, 256>>>(x2, ln2g, ln2b, h);
    // 5. fc + gelu -> m
    tc_gemm<true,false,true><<<GEMM_GRID, 128, GSMEM>>>(h, wtfc, bfc, nullptr, mb, MM, FF, EE);
    // 6. out proj + residual -> d_out
    tc_gemm<false,true,false><<<GEMM_GRID, 128, GSMEM>>>(mb, wtout, bout, x2, out, MM, EE, FF);
}